// round 2
// baseline (speedup 1.0000x reference)
#include <cuda_runtime.h>

#define CL 512
#define CE 512
#define NPAIR 128
#define NB 32
#define ATTN_ELEMS (NPAIR * CL * CL)
#define OUT_ELEMS (NB * 1024)
#define SCALE_F 0.044194173824159216f
#define NEG_INF_F (-1e9f)

// Scratch (alloc-free rule: device globals only)
__device__ float g_x2T[NPAIR * CL * CE];      // x2 transposed per pair: [p][e][k]
__device__ float g_x1att[NPAIR * CL * CE];    // attn @ V
__device__ float g_pooled[NB * 4096];         // [b][mean(2048) | max(2048)]
__device__ float g_attn_scratch[ATTN_ELEMS];  // fallback if attn not in d_out
__device__ float g_out_dummy[OUT_ELEMS];      // fallback if out not in d_out
__device__ int g_qlen[32];
__device__ int g_klen[128];

// ---------------- length normalization: auto-detect int32 vs int64 ----------------
// If the arrays are int64 (little-endian, values in [0,512)), every odd 32-bit
// word of the first 128 words of x2_len is zero. For genuine int32 data the
// odd words are uniform in [0,512): P(all 64 zero) = (1/512)^64 ~ 0.
__global__ void k_lens(const unsigned int* __restrict__ x1l,
                       const unsigned int* __restrict__ x2l) {
    __shared__ int is64;
    int t = threadIdx.x;
    if (t == 0) {
        int all0 = 1;
        for (int i = 1; i < 128; i += 2)
            if (x2l[i] != 0u) { all0 = 0; break; }
        is64 = all0;
    }
    __syncthreads();
    if (t < 32)  g_qlen[t] = (int)(is64 ? x1l[2 * t] : x1l[t]);
    if (t < 128) g_klen[t] = (int)(is64 ? x2l[2 * t] : x2l[t]);
}

// ---------------- x2 transpose: g_x2T[p][e][k] = x2[p][k][e] ----------------
__global__ void k_transpose(const float* __restrict__ x2) {
    __shared__ float tile[32][33];
    int p = blockIdx.z;
    int k0 = blockIdx.x * 32, e0 = blockIdx.y * 32;
    const float* src = x2 + (size_t)p * CL * CE;
    float* dst = g_x2T + (size_t)p * CL * CE;
    int tx = threadIdx.x, ty = threadIdx.y;
#pragma unroll
    for (int i = 0; i < 4; i++)
        tile[ty + 8 * i][tx] = src[(k0 + ty + 8 * i) * CE + e0 + tx];
    __syncthreads();
#pragma unroll
    for (int i = 0; i < 4; i++)
        dst[(e0 + ty + 8 * i) * CL + k0 + tx] = tile[tx][ty + 8 * i];
}

// ---------------- attention: scores (Q @ x2T) + mask + softmax -> attn ----------------
// block = (pair p, 32-query tile). tile: 32 q x 512 k, micro 8x8 (split 4+4).
__global__ __launch_bounds__(256) void k_attn(const float* __restrict__ x1,
                                              float* __restrict__ attn_out) {
    extern __shared__ float sm[];
    float* sc = sm;                   // 32 * 516
    float* As = sc + 32 * 516;        // 16 * 36
    float* Bs = As + 16 * 36;         // 16 * 516
    float* rinv = Bs + 16 * 516;      // 32

    int t = threadIdx.x;
    int p = blockIdx.y;
    int q0 = blockIdx.x * 32;
    int x1i = p & 31;
    int qlen = g_qlen[x1i];
    int klen = g_klen[p];
    const float* Q = x1 + (size_t)x1i * CL * CE + (size_t)q0 * CE;
    const float* BT = g_x2T + (size_t)p * CL * CE;

    int trow = t >> 6;   // 0..3  -> q rows trow*4+{0..3} and +16
    int tcol = t & 63;   // 0..63 -> k cols tcol*4+{0..3} and +256

    float acc[2][4][2][4];
#pragma unroll
    for (int a = 0; a < 2; a++)
#pragma unroll
        for (int b = 0; b < 4; b++)
#pragma unroll
            for (int c = 0; c < 2; c++)
#pragma unroll
                for (int d = 0; d < 4; d++) acc[a][b][c][d] = 0.f;

    for (int ec = 0; ec < CE / 16; ec++) {
        if (t < 128) {  // 32 q x 16 e, transposed store
            int q = t >> 2, e4 = (t & 3) << 2;
            float4 v = *(const float4*)(Q + q * CE + ec * 16 + e4);
            As[(e4 + 0) * 36 + q] = v.x;
            As[(e4 + 1) * 36 + q] = v.y;
            As[(e4 + 2) * 36 + q] = v.z;
            As[(e4 + 3) * 36 + q] = v.w;
        }
#pragma unroll
        for (int i = 0; i < 8; i++) {  // 16 e x 512 k direct copy
            int lin = i * 256 + t;
            int ee = lin >> 7, k4 = (lin & 127) << 2;
            *(float4*)&Bs[ee * 516 + k4] = *(const float4*)(BT + (size_t)(ec * 16 + ee) * CL + k4);
        }
        __syncthreads();
#pragma unroll
        for (int ee = 0; ee < 16; ee++) {
            float4 a0 = *(float4*)&As[ee * 36 + trow * 4];
            float4 a1 = *(float4*)&As[ee * 36 + trow * 4 + 16];
            float4 b0 = *(float4*)&Bs[ee * 516 + tcol * 4];
            float4 b1 = *(float4*)&Bs[ee * 516 + tcol * 4 + 256];
            float av[2][4] = {{a0.x, a0.y, a0.z, a0.w}, {a1.x, a1.y, a1.z, a1.w}};
            float bv[2][4] = {{b0.x, b0.y, b0.z, b0.w}, {b1.x, b1.y, b1.z, b1.w}};
#pragma unroll
            for (int ri = 0; ri < 2; ri++)
#pragma unroll
                for (int i = 0; i < 4; i++)
#pragma unroll
                    for (int ci = 0; ci < 2; ci++)
#pragma unroll
                        for (int j = 0; j < 4; j++)
                            acc[ri][i][ci][j] += av[ri][i] * bv[ci][j];
        }
        __syncthreads();
    }

    // scale + mask -> scores in smem
#pragma unroll
    for (int ri = 0; ri < 2; ri++)
#pragma unroll
        for (int i = 0; i < 4; i++) {
            int r = trow * 4 + ri * 16 + i;
            bool qv = (q0 + r) < qlen;
#pragma unroll
            for (int ci = 0; ci < 2; ci++)
#pragma unroll
                for (int j = 0; j < 4; j++) {
                    int c = tcol * 4 + ci * 256 + j;
                    sc[r * 516 + c] = (qv && c < klen) ? acc[ri][i][ci][j] * SCALE_F : NEG_INF_F;
                }
        }
    __syncthreads();

    // softmax: 8 threads per row
    {
        int row = t >> 3, g = t & 7;
        float* rp = sc + row * 516 + g * 64;
        float m = -3.0e38f;
#pragma unroll 8
        for (int k = 0; k < 64; k++) m = fmaxf(m, rp[k]);
        m = fmaxf(m, __shfl_xor_sync(0xffffffffu, m, 4));
        m = fmaxf(m, __shfl_xor_sync(0xffffffffu, m, 2));
        m = fmaxf(m, __shfl_xor_sync(0xffffffffu, m, 1));
        float s = 0.f;
#pragma unroll 8
        for (int k = 0; k < 64; k++) {
            float e = __expf(rp[k] - m);
            rp[k] = e;
            s += e;
        }
        s += __shfl_xor_sync(0xffffffffu, s, 4);
        s += __shfl_xor_sync(0xffffffffu, s, 2);
        s += __shfl_xor_sync(0xffffffffu, s, 1);
        if (g == 0) rinv[row] = 1.0f / s;
    }
    __syncthreads();

    float* ao = attn_out + (size_t)p * CL * CL + (size_t)q0 * CL;
    for (int idx = t; idx < 32 * 512; idx += 256) {
        int r = idx >> 9, c = idx & 511;
        ao[r * CL + c] = sc[r * 516 + c] * rinv[r];
    }
}

// ---------------- x1_att = attn @ V : 128x128 tile, 8x8 micro, K=512 ----------------
__global__ __launch_bounds__(256) void k_av(const float* __restrict__ attn,
                                            const float* __restrict__ x2) {
    __shared__ float As[8 * 132];
    __shared__ float Bs[8 * 132];
    int t = threadIdx.x;
    int p = blockIdx.z, q0 = blockIdx.y * 128, e0 = blockIdx.x * 128;
    const float* Ap = attn + (size_t)p * CL * CL + (size_t)q0 * CL;
    const float* Bp = x2 + (size_t)p * CL * CE + e0;
    int trow = t >> 4, tcol = t & 15;
    int qa = t >> 1, ja = t & 1;
    int kb = t >> 5, e4 = (t & 31) << 2;

    float acc[2][4][2][4];
#pragma unroll
    for (int a = 0; a < 2; a++)
#pragma unroll
        for (int b = 0; b < 4; b++)
#pragma unroll
            for (int c = 0; c < 2; c++)
#pragma unroll
                for (int d = 0; d < 4; d++) acc[a][b][c][d] = 0.f;

    for (int kc = 0; kc < 64; kc++) {
        float4 va = *(const float4*)(Ap + qa * CL + kc * 8 + ja * 4);
        As[(ja * 4 + 0) * 132 + qa] = va.x;
        As[(ja * 4 + 1) * 132 + qa] = va.y;
        As[(ja * 4 + 2) * 132 + qa] = va.z;
        As[(ja * 4 + 3) * 132 + qa] = va.w;
        *(float4*)&Bs[kb * 132 + e4] = *(const float4*)(Bp + (size_t)(kc * 8 + kb) * CE + e4);
        __syncthreads();
#pragma unroll
        for (int kk = 0; kk < 8; kk++) {
            float4 a0 = *(float4*)&As[kk * 132 + trow * 4];
            float4 a1 = *(float4*)&As[kk * 132 + trow * 4 + 64];
            float4 b0 = *(float4*)&Bs[kk * 132 + tcol * 4];
            float4 b1 = *(float4*)&Bs[kk * 132 + tcol * 4 + 64];
            float av[2][4] = {{a0.x, a0.y, a0.z, a0.w}, {a1.x, a1.y, a1.z, a1.w}};
            float bv[2][4] = {{b0.x, b0.y, b0.z, b0.w}, {b1.x, b1.y, b1.z, b1.w}};
#pragma unroll
            for (int ri = 0; ri < 2; ri++)
#pragma unroll
                for (int i = 0; i < 4; i++)
#pragma unroll
                    for (int ci = 0; ci < 2; ci++)
#pragma unroll
                        for (int j = 0; j < 4; j++)
                            acc[ri][i][ci][j] += av[ri][i] * bv[ci][j];
        }
        __syncthreads();
    }

    float* Cp = g_x1att + (size_t)p * CL * CE + (size_t)q0 * CE + e0;
#pragma unroll
    for (int ri = 0; ri < 2; ri++)
#pragma unroll
        for (int i = 0; i < 4; i++) {
            int r = trow * 4 + ri * 64 + i;
#pragma unroll
            for (int ci = 0; ci < 2; ci++) {
                float4 v = make_float4(acc[ri][i][ci][0], acc[ri][i][ci][1],
                                       acc[ri][i][ci][2], acc[ri][i][ci][3]);
                *(float4*)(Cp + (size_t)r * CE + tcol * 4 + ci * 64) = v;
            }
        }
}

// ---------------- fusion GEMM + fused mean/max pooling ----------------
// block = (pair p, 128 e-cols); loops 4 q-tiles of 128, K = 1024 (cat dim)
__global__ __launch_bounds__(256) void k_fusion(const float* __restrict__ x1,
                                                const float* __restrict__ fw,
                                                const float* __restrict__ fb) {
    __shared__ float As[8 * 132];
    __shared__ float Bs[8 * 132];
    __shared__ float redS[16 * 128];
    __shared__ float redM[16 * 128];
    int t = threadIdx.x;
    int p = blockIdx.y, e0 = blockIdx.x * 128;
    int x1i = p & 31;
    const float* X1 = x1 + (size_t)x1i * CL * CE;
    const float* XA = g_x1att + (size_t)p * CL * CE;
    int trow = t >> 4, tcol = t & 15;
    int qa = t >> 1, ja = t & 1;
    int kb = t >> 5, e4 = (t & 31) << 2;

    float bias[2][4];
#pragma unroll
    for (int ci = 0; ci < 2; ci++)
#pragma unroll
        for (int j = 0; j < 4; j++) bias[ci][j] = fb[e0 + tcol * 4 + ci * 64 + j];

    float csum[2][4] = {{0.f, 0.f, 0.f, 0.f}, {0.f, 0.f, 0.f, 0.f}};
    float cmax[2][4] = {{0.f, 0.f, 0.f, 0.f}, {0.f, 0.f, 0.f, 0.f}};

    for (int qt = 0; qt < 4; qt++) {
        int q0 = qt * 128;
        const float* X1q = X1 + (size_t)(q0 + qa) * CE;
        const float* XAq = XA + (size_t)(q0 + qa) * CE;
        float acc[2][4][2][4];
#pragma unroll
        for (int a = 0; a < 2; a++)
#pragma unroll
            for (int b = 0; b < 4; b++)
#pragma unroll
                for (int c = 0; c < 2; c++)
#pragma unroll
                    for (int d = 0; d < 4; d++) acc[a][b][c][d] = 0.f;

        for (int kc = 0; kc < 128; kc++) {
            int cidx = kc * 8 + ja * 4;
            float4 w;
            if (kc < 64) {
                float4 u = *(const float4*)(X1q + cidx);
                float4 v = *(const float4*)(XAq + cidx);
                w = make_float4(u.x - v.x, u.y - v.y, u.z - v.z, u.w - v.w);
            } else {
                int c2 = cidx - 512;
                float4 u = *(const float4*)(X1q + c2);
                float4 v = *(const float4*)(XAq + c2);
                w = make_float4(u.x * v.x, u.y * v.y, u.z * v.z, u.w * v.w);
            }
            As[(ja * 4 + 0) * 132 + qa] = w.x;
            As[(ja * 4 + 1) * 132 + qa] = w.y;
            As[(ja * 4 + 2) * 132 + qa] = w.z;
            As[(ja * 4 + 3) * 132 + qa] = w.w;
            *(float4*)&Bs[kb * 132 + e4] =
                *(const float4*)(fw + (size_t)(kc * 8 + kb) * CE + e0 + e4);
            __syncthreads();
#pragma unroll
            for (int kk = 0; kk < 8; kk++) {
                float4 a0 = *(float4*)&As[kk * 132 + trow * 4];
                float4 a1 = *(float4*)&As[kk * 132 + trow * 4 + 64];
                float4 b0 = *(float4*)&Bs[kk * 132 + tcol * 4];
                float4 b1 = *(float4*)&Bs[kk * 132 + tcol * 4 + 64];
                float av[2][4] = {{a0.x, a0.y, a0.z, a0.w}, {a1.x, a1.y, a1.z, a1.w}};
                float bv[2][4] = {{b0.x, b0.y, b0.z, b0.w}, {b1.x, b1.y, b1.z, b1.w}};
#pragma unroll
                for (int ri = 0; ri < 2; ri++)
#pragma unroll
                    for (int i = 0; i < 4; i++)
#pragma unroll
                        for (int ci = 0; ci < 2; ci++)
#pragma unroll
                            for (int j = 0; j < 4; j++)
                                acc[ri][i][ci][j] += av[ri][i] * bv[ci][j];
            }
            __syncthreads();
        }
        // relu(acc + bias) -> pool over the 8 rows this thread owns
#pragma unroll
        for (int ri = 0; ri < 2; ri++)
#pragma unroll
            for (int i = 0; i < 4; i++)
#pragma unroll
                for (int ci = 0; ci < 2; ci++)
#pragma unroll
                    for (int j = 0; j < 4; j++) {
                        float v = fmaxf(acc[ri][i][ci][j] + bias[ci][j], 0.f);
                        csum[ci][j] += v;
                        cmax[ci][j] = fmaxf(cmax[ci][j], v);
                    }
    }
    // reduce across the 16 row-thread-groups (deterministic, no atomics)
#pragma unroll
    for (int ci = 0; ci < 2; ci++)
#pragma unroll
        for (int j = 0; j < 4; j++) {
            int col = tcol * 4 + ci * 64 + j;
            redS[trow * 128 + col] = csum[ci][j];
            redM[trow * 128 + col] = cmax[ci][j];
        }
    __syncthreads();
    if (t < 128) {
        float s = 0.f, m = 0.f;
#pragma unroll
        for (int r = 0; r < 16; r++) {
            s += redS[r * 128 + t];
            m = fmaxf(m, redM[r * 128 + t]);
        }
        int base = (p >> 2) * 4096 + (p & 3) * 512 + e0 + t;
        g_pooled[base] = s * (1.0f / 512.0f);
        g_pooled[base + 2048] = m;
    }
}

// ---------------- out = relu(pooled @ out_w + out_b) ----------------
__global__ __launch_bounds__(256) void k_out(const float* __restrict__ ow,
                                             const float* __restrict__ ob,
                                             float* __restrict__ outp) {
    __shared__ float sp[4096];
    int b = blockIdx.x, t = threadIdx.x;
    for (int i = t; i < 4096; i += 256) sp[i] = g_pooled[b * 4096 + i];
    __syncthreads();
    int col = t * 4;
    float4 acc = *(const float4*)(ob + col);
#pragma unroll 8
    for (int c = 0; c < 4096; c++) {
        float pv = sp[c];
        float4 w = *(const float4*)(ow + (size_t)c * 1024 + col);
        acc.x += pv * w.x;
        acc.y += pv * w.y;
        acc.z += pv * w.z;
        acc.w += pv * w.w;
    }
    acc.x = fmaxf(acc.x, 0.f);
    acc.y = fmaxf(acc.y, 0.f);
    acc.z = fmaxf(acc.z, 0.f);
    acc.w = fmaxf(acc.w, 0.f);
    *(float4*)(outp + b * 1024 + col) = acc;
}

extern "C" void kernel_launch(void* const* d_in, const int* in_sizes, int n_in,
                              void* d_out, int out_size) {
    const float* x1 = (const float*)d_in[0];
    const float* x2 = (const float*)d_in[1];
    const unsigned int* x1_len = (const unsigned int*)d_in[2];
    const unsigned int* x2_len = (const unsigned int*)d_in[3];
    const float* fw = (const float*)d_in[4];
    const float* fb = (const float*)d_in[5];
    const float* ow = (const float*)d_in[6];
    const float* ob = (const float*)d_in[7];

    float* outp = (float*)d_out;
    float* attn;
    if (out_size >= OUT_ELEMS + ATTN_ELEMS) {
        attn = outp + OUT_ELEMS;                     // [out | attn] (tuple order)
    } else if (out_size >= ATTN_ELEMS) {
        attn = outp;                                 // attn only
        void* dp = nullptr;
        cudaGetSymbolAddress(&dp, g_out_dummy);
        outp = (float*)dp;
    } else {
        void* dp = nullptr;                          // out only; attn internal
        cudaGetSymbolAddress(&dp, g_attn_scratch);
        attn = (float*)dp;
    }

    const int smemA = (32 * 516 + 16 * 36 + 16 * 516 + 32) * (int)sizeof(float);
    cudaFuncSetAttribute(k_attn, cudaFuncAttributeMaxDynamicSharedMemorySize, smemA);

    k_lens<<<1, 128>>>(x1_len, x2_len);
    k_transpose<<<dim3(16, 16, NPAIR), dim3(32, 8)>>>(x2);
    k_attn<<<dim3(16, NPAIR), 256, smemA>>>(x1, attn);
    k_av<<<dim3(4, 4, NPAIR), 256>>>(attn, x2);
    k_fusion<<<dim3(4, NPAIR), 256>>>(x1, fw, fb);
    k_out<<<NB, 256>>>(ow, ob, outp);
}

// round 4
// speedup vs baseline: 1.1268x; 1.1268x over previous
#include <cuda_runtime.h>
#include <cuda_bf16.h>
#include <cstdint>

#define CL 512
#define CE 512
#define NPAIR 128
#define NB 32
#define ATTN_ELEMS (NPAIR * CL * CL)
#define OUT_ELEMS (NB * 1024)
#define SCALE_F 0.044194173824159216f

// ---------------- scratch (device globals; alloc-free rule) ----------------
__device__ float g_x1att[NPAIR * CL * CE];    // attn @ V
__device__ float g_pooled[NB * 4096];         // [b][mean(2048) | max(2048)]
__device__ float g_attn_scratch[ATTN_ELEMS];  // fallback if attn not in d_out
__device__ float g_out_dummy[OUT_ELEMS];      // fallback if out not in d_out
__device__ float g_rowsum[NPAIR * CL];
__device__ int g_qlen[32];
__device__ int g_klen[128];
__device__ __nv_bfloat16 g_qh[NB * CL * CE];     // x1 hi
__device__ __nv_bfloat16 g_ql[NB * CL * CE];     // x1 lo
__device__ __nv_bfloat16 g_kh[NPAIR * CL * CE];  // x2 hi
__device__ __nv_bfloat16 g_kl[NPAIR * CL * CE];  // x2 lo

// ---------------- PTX helpers (baseline sm_80+ ISA, works on sm_103) ----------------
__device__ __forceinline__ uint32_t smem_u32(const void* p) {
    uint32_t a;
    asm("{ .reg .u64 t; cvta.to.shared.u64 t, %1; cvt.u32.u64 %0, t; }" : "=r"(a) : "l"(p));
    return a;
}
__device__ __forceinline__ void cp_async16(uint32_t dst, const void* src) {
    asm volatile("cp.async.ca.shared.global [%0], [%1], 16;" :: "r"(dst), "l"(src));
}
#define CP_COMMIT() asm volatile("cp.async.commit_group;" ::: "memory")
#define CP_WAIT(n)  asm volatile("cp.async.wait_group %0;" :: "n"(n) : "memory")

__device__ __forceinline__ void ldm_x4(uint32_t* r, uint32_t addr) {
    asm volatile("ldmatrix.sync.aligned.m8n8.x4.shared.b16 {%0,%1,%2,%3}, [%4];"
                 : "=r"(r[0]), "=r"(r[1]), "=r"(r[2]), "=r"(r[3]) : "r"(addr));
}
__device__ __forceinline__ void ldm_x2(uint32_t* r, uint32_t addr) {
    asm volatile("ldmatrix.sync.aligned.m8n8.x2.shared.b16 {%0,%1}, [%2];"
                 : "=r"(r[0]), "=r"(r[1]) : "r"(addr));
}
__device__ __forceinline__ void mma_bf16(float* c, const uint32_t* a, const uint32_t* b) {
    asm volatile(
        "mma.sync.aligned.m16n8k16.row.col.f32.bf16.bf16.f32 "
        "{%0,%1,%2,%3}, {%4,%5,%6,%7}, {%8,%9}, {%0,%1,%2,%3};"
        : "+f"(c[0]), "+f"(c[1]), "+f"(c[2]), "+f"(c[3])
        : "r"(a[0]), "r"(a[1]), "r"(a[2]), "r"(a[3]), "r"(b[0]), "r"(b[1]));
}

// smem staging: 4 tiles per stage (Ahi, Alo, Bhi, Blo), each 128 rows x 80B pitch
#define PITCHB 80
#define TILE_B (128 * PITCHB)     // 10240
#define STAGE_B (4 * TILE_B)      // 40960
#define RS_OFF (2 * STAGE_B)      // 81920
#define SC_SMEM (RS_OFF + 128 * 4 * 4)

// ---------------- length normalization: auto-detect int32 vs int64 ----------------
__global__ void k_lens(const unsigned int* __restrict__ x1l,
                       const unsigned int* __restrict__ x2l) {
    __shared__ int is64;
    int t = threadIdx.x;
    if (t == 0) {
        int all0 = 1;
        for (int i = 1; i < 128; i += 2)
            if (x2l[i] != 0u) { all0 = 0; break; }
        is64 = all0;
    }
    __syncthreads();
    if (t < 32)  g_qlen[t] = (int)(is64 ? x1l[2 * t] : x1l[t]);
    if (t < 128) g_klen[t] = (int)(is64 ? x2l[2 * t] : x2l[t]);
}

// ---------------- fp32 -> bf16 hi/lo split ----------------
__global__ void k_cvt(const float* __restrict__ src, __nv_bfloat16* __restrict__ hi,
                      __nv_bfloat16* __restrict__ lo, int n4) {
    int i = blockIdx.x * blockDim.x + threadIdx.x;
    if (i >= n4) return;
    float4 v = ((const float4*)src)[i];
    __nv_bfloat16 h0 = __float2bfloat16(v.x), h1 = __float2bfloat16(v.y);
    __nv_bfloat16 h2 = __float2bfloat16(v.z), h3 = __float2bfloat16(v.w);
    __nv_bfloat16 l0 = __float2bfloat16(v.x - __bfloat162float(h0));
    __nv_bfloat16 l1 = __float2bfloat16(v.y - __bfloat162float(h1));
    __nv_bfloat16 l2 = __float2bfloat16(v.z - __bfloat162float(h2));
    __nv_bfloat16 l3 = __float2bfloat16(v.w - __bfloat162float(h3));
    __nv_bfloat162 a, b;
    a.x = h0; a.y = h1; b.x = h2; b.y = h3;
    ((__nv_bfloat162*)hi)[2 * i] = a;
    ((__nv_bfloat162*)hi)[2 * i + 1] = b;
    a.x = l0; a.y = l1; b.x = l2; b.y = l3;
    ((__nv_bfloat162*)lo)[2 * i] = a;
    ((__nv_bfloat162*)lo)[2 * i + 1] = b;
}

// ---------------- scores via mma.sync bf16 3x-split + masked exp epilogue ----------
// grid (4 qtiles, 128 pairs), 256 thr = 8 warps (2x4). Block tile 128q x 128k,
// e staged in chunks of 32, cp.async double-buffered. Writes UNNORMALIZED exp
// and per-row sums; k_norm finishes softmax.
__global__ __launch_bounds__(256, 1) void k_scores_mma(float* __restrict__ attn_out) {
    extern __shared__ char smem[];
    uint32_t sb = smem_u32(smem);
    int t = threadIdx.x, lane = t & 31, wid = t >> 5;
    int wm = wid >> 2, wn = wid & 3;  // 2x4 warp grid
    int p = blockIdx.y, x1i = p & 31;
    int qt = blockIdx.x, q0 = qt * 128;
    int qlen = g_qlen[x1i], klen = g_klen[p];

    const char* Qh = (const char*)(g_qh + (size_t)x1i * 262144);
    const char* Ql = (const char*)(g_ql + (size_t)x1i * 262144);
    const char* Kh = (const char*)(g_kh + (size_t)p * 262144);
    const char* Kl = (const char*)(g_kl + (size_t)p * 262144);

    float acc[4][4][4];
#pragma unroll
    for (int a = 0; a < 4; a++)
#pragma unroll
        for (int b = 0; b < 4; b++)
#pragma unroll
            for (int c = 0; c < 4; c++) acc[a][b][c] = 0.f;
    float rsum[4][2];
#pragma unroll
    for (int a = 0; a < 4; a++) rsum[a][0] = rsum[a][1] = 0.f;

    // stage loader: stage s = nt*16 + ec
    auto load_stage = [&](int s) {
        int nt = s >> 4, ec = s & 15;
        uint32_t bb = sb + (s & 1) * STAGE_B;
#pragma unroll
        for (int h = 0; h < 2; h++) {
            int idx = h * 256 + t;
            int row = idx >> 2, q = (idx & 3) * 16;
            uint32_t dst = row * PITCHB + q;
            size_t asrc = (size_t)(q0 + row) * 1024 + ec * 64 + q;
            size_t bsrc = (size_t)(nt * 128 + row) * 1024 + ec * 64 + q;
            cp_async16(bb + dst, Qh + asrc);
            cp_async16(bb + TILE_B + dst, Ql + asrc);
            cp_async16(bb + 2 * TILE_B + dst, Kh + bsrc);
            cp_async16(bb + 3 * TILE_B + dst, Kl + bsrc);
        }
    };

    load_stage(0);
    CP_COMMIT();

    for (int nt = 0; nt < 4; nt++) {
        for (int ec = 0; ec < 16; ec++) {
            int s = nt * 16 + ec;
            if (s + 1 < 64) {
                load_stage(s + 1);
                CP_COMMIT();
                CP_WAIT(1);
            } else {
                CP_WAIT(0);
            }
            __syncthreads();
            uint32_t bb = sb + (s & 1) * STAGE_B;
            uint32_t aBase = bb + (wm * 64 + (lane & 15)) * PITCHB + (lane >> 4) * 16;
            uint32_t bBase = bb + 2 * TILE_B + (wn * 32 + (lane & 7)) * PITCHB +
                             ((lane >> 3) & 1) * 16;
#pragma unroll
            for (int kk = 0; kk < 2; kk++) {
                uint32_t aHi[4][4], aLo[4][4], bHi[4][2], bLo[4][2];
#pragma unroll
                for (int mt = 0; mt < 4; mt++) {
                    uint32_t ad = aBase + mt * 16 * PITCHB + kk * 32;
                    ldm_x4(aHi[mt], ad);
                    ldm_x4(aLo[mt], ad + TILE_B);
                }
#pragma unroll
                for (int ntl = 0; ntl < 4; ntl++) {
                    uint32_t bd = bBase + ntl * 8 * PITCHB + kk * 32;
                    ldm_x2(bHi[ntl], bd);
                    ldm_x2(bLo[ntl], bd + TILE_B);
                }
#pragma unroll
                for (int mt = 0; mt < 4; mt++)
#pragma unroll
                    for (int ntl = 0; ntl < 4; ntl++) {
                        mma_bf16(acc[mt][ntl], aHi[mt], bHi[ntl]);
                        mma_bf16(acc[mt][ntl], aLo[mt], bHi[ntl]);
                        mma_bf16(acc[mt][ntl], aHi[mt], bLo[ntl]);
                    }
            }
            __syncthreads();
        }
        // ---- epilogue for this 128-col block: masked exp, rowsum, store, re-zero
        int nb = nt * 128 + wn * 32;
#pragma unroll
        for (int mt = 0; mt < 4; mt++) {
            int r0 = q0 + wm * 64 + mt * 16 + (lane >> 2);
            bool v0 = r0 < qlen;
            bool v1 = (r0 + 8) < qlen;
#pragma unroll
            for (int ntl = 0; ntl < 4; ntl++) {
                int col = nb + ntl * 8 + (lane & 3) * 2;
                float* cc = acc[mt][ntl];
                float e0 = (v0 && col < klen) ? __expf(cc[0] * SCALE_F) : 0.f;
                float e1 = (v0 && col + 1 < klen) ? __expf(cc[1] * SCALE_F) : 0.f;
                float e2 = (v1 && col < klen) ? __expf(cc[2] * SCALE_F) : 0.f;
                float e3 = (v1 && col + 1 < klen) ? __expf(cc[3] * SCALE_F) : 0.f;
                rsum[mt][0] += e0 + e1;
                rsum[mt][1] += e2 + e3;
                float2 w0 = {e0, e1}, w1 = {e2, e3};
                *(float2*)(attn_out + (size_t)p * 262144 + (size_t)r0 * 512 + col) = w0;
                *(float2*)(attn_out + (size_t)p * 262144 + (size_t)(r0 + 8) * 512 + col) = w1;
                cc[0] = cc[1] = cc[2] = cc[3] = 0.f;
            }
        }
    }
    // ---- deterministic rowsum reduction
    __syncthreads();
    float* rs = (float*)(smem + RS_OFF);
#pragma unroll
    for (int mt = 0; mt < 4; mt++)
#pragma unroll
        for (int ri = 0; ri < 2; ri++) {
            float v = rsum[mt][ri];
            v += __shfl_xor_sync(0xffffffffu, v, 1);
            v += __shfl_xor_sync(0xffffffffu, v, 2);
            if ((lane & 3) == 0)
                rs[(wm * 64 + mt * 16 + ri * 8 + (lane >> 2)) * 4 + wn] = v;
        }
    __syncthreads();
    if (t < 128) {
        float s = rs[t * 4] + rs[t * 4 + 1] + rs[t * 4 + 2] + rs[t * 4 + 3];
        g_rowsum[p * 512 + q0 + t] = s;
    }
}

// ---------------- softmax normalize (handles fully-masked rows -> uniform) --------
__global__ void k_norm(float* __restrict__ attn) {
    int row = blockIdx.x;
    float s = g_rowsum[row];
    float inv = s > 0.f ? 1.f / s : 0.f;
    float add = s > 0.f ? 0.f : (1.f / 512.f);
    float4* a = (float4*)(attn + (size_t)row * 512);
    float4 v = a[threadIdx.x];
    v.x = v.x * inv + add;
    v.y = v.y * inv + add;
    v.z = v.z * inv + add;
    v.w = v.w * inv + add;
    a[threadIdx.x] = v;
}

// ---------------- x1_att = attn @ V : 128x128 tile, 8x8 micro, K=512 ----------------
__global__ __launch_bounds__(256) void k_av(const float* __restrict__ attn,
                                            const float* __restrict__ x2) {
    __shared__ float As[8 * 132];
    __shared__ float Bs[8 * 132];
    int t = threadIdx.x;
    int p = blockIdx.z, q0 = blockIdx.y * 128, e0 = blockIdx.x * 128;
    const float* Ap = attn + (size_t)p * CL * CL + (size_t)q0 * CL;
    const float* Bp = x2 + (size_t)p * CL * CE + e0;
    int trow = t >> 4, tcol = t & 15;
    int qa = t >> 1, ja = t & 1;
    int kb = t >> 5, e4 = (t & 31) << 2;

    float acc[2][4][2][4];
#pragma unroll
    for (int a = 0; a < 2; a++)
#pragma unroll
        for (int b = 0; b < 4; b++)
#pragma unroll
            for (int c = 0; c < 2; c++)
#pragma unroll
                for (int d = 0; d < 4; d++) acc[a][b][c][d] = 0.f;

    for (int kc = 0; kc < 64; kc++) {
        float4 va = *(const float4*)(Ap + qa * CL + kc * 8 + ja * 4);
        As[(ja * 4 + 0) * 132 + qa] = va.x;
        As[(ja * 4 + 1) * 132 + qa] = va.y;
        As[(ja * 4 + 2) * 132 + qa] = va.z;
        As[(ja * 4 + 3) * 132 + qa] = va.w;
        *(float4*)&Bs[kb * 132 + e4] = *(const float4*)(Bp + (size_t)(kc * 8 + kb) * CE + e4);
        __syncthreads();
#pragma unroll
        for (int kk = 0; kk < 8; kk++) {
            float4 a0 = *(float4*)&As[kk * 132 + trow * 4];
            float4 a1 = *(float4*)&As[kk * 132 + trow * 4 + 64];
            float4 b0 = *(float4*)&Bs[kk * 132 + tcol * 4];
            float4 b1 = *(float4*)&Bs[kk * 132 + tcol * 4 + 64];
            float av[2][4] = {{a0.x, a0.y, a0.z, a0.w}, {a1.x, a1.y, a1.z, a1.w}};
            float bv[2][4] = {{b0.x, b0.y, b0.z, b0.w}, {b1.x, b1.y, b1.z, b1.w}};
#pragma unroll
            for (int ri = 0; ri < 2; ri++)
#pragma unroll
                for (int i = 0; i < 4; i++)
#pragma unroll
                    for (int ci = 0; ci < 2; ci++)
#pragma unroll
                        for (int j = 0; j < 4; j++)
                            acc[ri][i][ci][j] += av[ri][i] * bv[ci][j];
        }
        __syncthreads();
    }

    float* Cp = g_x1att + (size_t)p * CL * CE + (size_t)q0 * CE + e0;
#pragma unroll
    for (int ri = 0; ri < 2; ri++)
#pragma unroll
        for (int i = 0; i < 4; i++) {
            int r = trow * 4 + ri * 64 + i;
#pragma unroll
            for (int ci = 0; ci < 2; ci++) {
                float4 v = make_float4(acc[ri][i][ci][0], acc[ri][i][ci][1],
                                       acc[ri][i][ci][2], acc[ri][i][ci][3]);
                *(float4*)(Cp + (size_t)r * CE + tcol * 4 + ci * 64) = v;
            }
        }
}

// ---------------- fusion GEMM + fused mean/max pooling ----------------
__global__ __launch_bounds__(256) void k_fusion(const float* __restrict__ x1,
                                                const float* __restrict__ fw,
                                                const float* __restrict__ fb) {
    __shared__ float As[8 * 132];
    __shared__ float Bs[8 * 132];
    __shared__ float redS[16 * 128];
    __shared__ float redM[16 * 128];
    int t = threadIdx.x;
    int p = blockIdx.y, e0 = blockIdx.x * 128;
    int x1i = p & 31;
    const float* X1 = x1 + (size_t)x1i * CL * CE;
    const float* XA = g_x1att + (size_t)p * CL * CE;
    int trow = t >> 4, tcol = t & 15;
    int qa = t >> 1, ja = t & 1;
    int kb = t >> 5, e4 = (t & 31) << 2;

    float bias[2][4];
#pragma unroll
    for (int ci = 0; ci < 2; ci++)
#pragma unroll
        for (int j = 0; j < 4; j++) bias[ci][j] = fb[e0 + tcol * 4 + ci * 64 + j];

    float csum[2][4] = {{0.f, 0.f, 0.f, 0.f}, {0.f, 0.f, 0.f, 0.f}};
    float cmax[2][4] = {{0.f, 0.f, 0.f, 0.f}, {0.f, 0.f, 0.f, 0.f}};

    for (int qt = 0; qt < 4; qt++) {
        int q0 = qt * 128;
        const float* X1q = X1 + (size_t)(q0 + qa) * CE;
        const float* XAq = XA + (size_t)(q0 + qa) * CE;
        float acc[2][4][2][4];
#pragma unroll
        for (int a = 0; a < 2; a++)
#pragma unroll
            for (int b = 0; b < 4; b++)
#pragma unroll
                for (int c = 0; c < 2; c++)
#pragma unroll
                    for (int d = 0; d < 4; d++) acc[a][b][c][d] = 0.f;

        for (int kc = 0; kc < 128; kc++) {
            int cidx = kc * 8 + ja * 4;
            float4 w;
            if (kc < 64) {
                float4 u = *(const float4*)(X1q + cidx);
                float4 v = *(const float4*)(XAq + cidx);
                w = make_float4(u.x - v.x, u.y - v.y, u.z - v.z, u.w - v.w);
            } else {
                int c2 = cidx - 512;
                float4 u = *(const float4*)(X1q + c2);
                float4 v = *(const float4*)(XAq + c2);
                w = make_float4(u.x * v.x, u.y * v.y, u.z * v.z, u.w * v.w);
            }
            As[(ja * 4 + 0) * 132 + qa] = w.x;
            As[(ja * 4 + 1) * 132 + qa] = w.y;
            As[(ja * 4 + 2) * 132 + qa] = w.z;
            As[(ja * 4 + 3) * 132 + qa] = w.w;
            *(float4*)&Bs[kb * 132 + e4] =
                *(const float4*)(fw + (size_t)(kc * 8 + kb) * CE + e0 + e4);
            __syncthreads();
#pragma unroll
            for (int kk = 0; kk < 8; kk++) {
                float4 a0 = *(float4*)&As[kk * 132 + trow * 4];
                float4 a1 = *(float4*)&As[kk * 132 + trow * 4 + 64];
                float4 b0 = *(float4*)&Bs[kk * 132 + tcol * 4];
                float4 b1 = *(float4*)&Bs[kk * 132 + tcol * 4 + 64];
                float av[2][4] = {{a0.x, a0.y, a0.z, a0.w}, {a1.x, a1.y, a1.z, a1.w}};
                float bv[2][4] = {{b0.x, b0.y, b0.z, b0.w}, {b1.x, b1.y, b1.z, b1.w}};
#pragma unroll
                for (int ri = 0; ri < 2; ri++)
#pragma unroll
                    for (int i = 0; i < 4; i++)
#pragma unroll
                        for (int ci = 0; ci < 2; ci++)
#pragma unroll
                            for (int j = 0; j < 4; j++)
                                acc[ri][i][ci][j] += av[ri][i] * bv[ci][j];
            }
            __syncthreads();
        }
#pragma unroll
        for (int ri = 0; ri < 2; ri++)
#pragma unroll
            for (int i = 0; i < 4; i++)
#pragma unroll
                for (int ci = 0; ci < 2; ci++)
#pragma unroll
                    for (int j = 0; j < 4; j++) {
                        float v = fmaxf(acc[ri][i][ci][j] + bias[ci][j], 0.f);
                        csum[ci][j] += v;
                        cmax[ci][j] = fmaxf(cmax[ci][j], v);
                    }
    }
#pragma unroll
    for (int ci = 0; ci < 2; ci++)
#pragma unroll
        for (int j = 0; j < 4; j++) {
            int col = tcol * 4 + ci * 64 + j;
            redS[trow * 128 + col] = csum[ci][j];
            redM[trow * 128 + col] = cmax[ci][j];
        }
    __syncthreads();
    if (t < 128) {
        float s = 0.f, m = 0.f;
#pragma unroll
        for (int r = 0; r < 16; r++) {
            s += redS[r * 128 + t];
            m = fmaxf(m, redM[r * 128 + t]);
        }
        int base = (p >> 2) * 4096 + (p & 3) * 512 + e0 + t;
        g_pooled[base] = s * (1.0f / 512.0f);
        g_pooled[base + 2048] = m;
    }
}

// ---------------- out = relu(pooled @ out_w + out_b) ----------------
__global__ __launch_bounds__(256) void k_out(const float* __restrict__ ow,
                                             const float* __restrict__ ob,
                                             float* __restrict__ outp) {
    __shared__ float sp[4096];
    int b = blockIdx.x, t = threadIdx.x;
    for (int i = t; i < 4096; i += 256) sp[i] = g_pooled[b * 4096 + i];
    __syncthreads();
    int col = t * 4;
    float4 acc = *(const float4*)(ob + col);
#pragma unroll 8
    for (int c = 0; c < 4096; c++) {
        float pv = sp[c];
        float4 w = *(const float4*)(ow + (size_t)c * 1024 + col);
        acc.x += pv * w.x;
        acc.y += pv * w.y;
        acc.z += pv * w.z;
        acc.w += pv * w.w;
    }
    acc.x = fmaxf(acc.x, 0.f);
    acc.y = fmaxf(acc.y, 0.f);
    acc.z = fmaxf(acc.z, 0.f);
    acc.w = fmaxf(acc.w, 0.f);
    *(float4*)(outp + b * 1024 + col) = acc;
}

extern "C" void kernel_launch(void* const* d_in, const int* in_sizes, int n_in,
                              void* d_out, int out_size) {
    const float* x1 = (const float*)d_in[0];
    const float* x2 = (const float*)d_in[1];
    const unsigned int* x1_len = (const unsigned int*)d_in[2];
    const unsigned int* x2_len = (const unsigned int*)d_in[3];
    const float* fw = (const float*)d_in[4];
    const float* fb = (const float*)d_in[5];
    const float* ow = (const float*)d_in[6];
    const float* ob = (const float*)d_in[7];

    float* outp = (float*)d_out;
    float* attn;
    if (out_size >= OUT_ELEMS + ATTN_ELEMS) {
        attn = outp + OUT_ELEMS;  // [out | attn] tuple order
    } else if (out_size >= ATTN_ELEMS) {
        attn = outp;
        void* dp = nullptr;
        cudaGetSymbolAddress(&dp, g_out_dummy);
        outp = (float*)dp;
    } else {
        void* dp = nullptr;
        cudaGetSymbolAddress(&dp, g_attn_scratch);
        attn = (float*)dp;
    }

    void *qh, *ql, *kh, *kl;
    cudaGetSymbolAddress(&qh, g_qh);
    cudaGetSymbolAddress(&ql, g_ql);
    cudaGetSymbolAddress(&kh, g_kh);
    cudaGetSymbolAddress(&kl, g_kl);

    cudaFuncSetAttribute(k_scores_mma, cudaFuncAttributeMaxDynamicSharedMemorySize, SC_SMEM);

    k_lens<<<1, 128>>>(x1_len, x2_len);
    k_cvt<<<8192, 256>>>(x1, (__nv_bfloat16*)qh, (__nv_bfloat16*)ql, 2097152);
    k_cvt<<<32768, 256>>>(x2, (__nv_bfloat16*)kh, (__nv_bfloat16*)kl, 8388608);
    k_scores_mma<<<dim3(4, NPAIR), 256, SC_SMEM>>>(attn);
    k_norm<<<NPAIR * CL, 128>>>(attn);
    k_av<<<dim3(4, 4, NPAIR), 256>>>(attn, x2);
    k_fusion<<<dim3(4, NPAIR), 256>>>(x1, fw, fb);
    k_out<<<NB, 256>>>(ow, ob, outp);
}

// round 5
// speedup vs baseline: 1.9955x; 1.7709x over previous
#include <cuda_runtime.h>
#include <cuda_bf16.h>
#include <cstdint>

#define CL 512
#define CE 512
#define NPAIR 128
#define NB 32
#define ATTN_ELEMS (NPAIR * CL * CL)
#define OUT_ELEMS (NB * 1024)
#define SCALE_F 0.044194173824159216f

// ---------------- scratch (device globals; alloc-free rule) ----------------
__device__ float g_pooled[NB * 4096];
__device__ float g_attn_scratch[ATTN_ELEMS];
__device__ float g_out_dummy[OUT_ELEMS];
__device__ float g_rowsum[NPAIR * CL];
__device__ float g_psum[4 * NPAIR * CL];
__device__ float g_pmax[4 * NPAIR * CL];
__device__ int g_qlen[32];
__device__ int g_klen[128];
__device__ __nv_bfloat16 g_qh[NB * CL * CE];
__device__ __nv_bfloat16 g_ql[NB * CL * CE];
__device__ __nv_bfloat16 g_kh[NPAIR * CL * CE];
__device__ __nv_bfloat16 g_kl[NPAIR * CL * CE];
__device__ __nv_bfloat16 g_ah[NPAIR * CL * CL];  // normalized attn hi
__device__ __nv_bfloat16 g_al[NPAIR * CL * CL];  // normalized attn lo
__device__ __nv_bfloat16 g_sh[NPAIR * CL * CE];  // x1 - xa hi
__device__ __nv_bfloat16 g_sl[NPAIR * CL * CE];
__device__ __nv_bfloat16 g_mh[NPAIR * CL * CE];  // x1 * xa hi
__device__ __nv_bfloat16 g_ml[NPAIR * CL * CE];
__device__ __nv_bfloat16 g_fwh[1024 * 512];
__device__ __nv_bfloat16 g_fwl[1024 * 512];

// ---------------- PTX helpers ----------------
__device__ __forceinline__ uint32_t smem_u32(const void* p) {
    uint32_t a;
    asm("{ .reg .u64 t; cvta.to.shared.u64 t, %1; cvt.u32.u64 %0, t; }" : "=r"(a) : "l"(p));
    return a;
}
__device__ __forceinline__ void cp_async16(uint32_t dst, const void* src) {
    asm volatile("cp.async.ca.shared.global [%0], [%1], 16;" :: "r"(dst), "l"(src));
}
#define CP_COMMIT() asm volatile("cp.async.commit_group;" ::: "memory")
#define CP_WAIT(n)  asm volatile("cp.async.wait_group %0;" :: "n"(n) : "memory")

__device__ __forceinline__ void ldm_x4(uint32_t* r, uint32_t addr) {
    asm volatile("ldmatrix.sync.aligned.m8n8.x4.shared.b16 {%0,%1,%2,%3}, [%4];"
                 : "=r"(r[0]), "=r"(r[1]), "=r"(r[2]), "=r"(r[3]) : "r"(addr));
}
__device__ __forceinline__ void ldm_x2(uint32_t* r, uint32_t addr) {
    asm volatile("ldmatrix.sync.aligned.m8n8.x2.shared.b16 {%0,%1}, [%2];"
                 : "=r"(r[0]), "=r"(r[1]) : "r"(addr));
}
__device__ __forceinline__ void ldm_x2t(uint32_t* r, uint32_t addr) {
    asm volatile("ldmatrix.sync.aligned.m8n8.x2.trans.shared.b16 {%0,%1}, [%2];"
                 : "=r"(r[0]), "=r"(r[1]) : "r"(addr));
}
__device__ __forceinline__ void mma_bf16(float* c, const uint32_t* a, const uint32_t* b) {
    asm volatile(
        "mma.sync.aligned.m16n8k16.row.col.f32.bf16.bf16.f32 "
        "{%0,%1,%2,%3}, {%4,%5,%6,%7}, {%8,%9}, {%0,%1,%2,%3};"
        : "+f"(c[0]), "+f"(c[1]), "+f"(c[2]), "+f"(c[3])
        : "r"(a[0]), "r"(a[1]), "r"(a[2]), "r"(a[3]), "r"(b[0]), "r"(b[1]));
}

// ---------------- k_scores smem geometry (unchanged from R4) ----------------
#define PITCHB 80
#define TILE_B (128 * PITCHB)
#define STAGE_B (4 * TILE_B)
#define RS_OFF (2 * STAGE_B)
#define SC_SMEM (RS_OFF + 128 * 4 * 4)

// ---------------- AV / fusion smem geometry ----------------
// A tile: 128 rows x 32 bf16 (64B), pitch 80.  B tile: 32 rows x 128 bf16 (256B), pitch 272.
#define AV_A_SZ (128 * 80)                    // 10240
#define AV_V_SZ (32 * 272)                    // 8704
#define AV_VH_OFF (2 * AV_A_SZ)
#define AV_STAGE (2 * AV_A_SZ + 2 * AV_V_SZ)  // 37888
#define AV_SMEM (2 * AV_STAGE)                // 75776
#define FU_RED_OFF AV_SMEM
#define FU_SMEM (AV_SMEM + 2048)

// ---------------- length normalization ----------------
__global__ void k_lens(const unsigned int* __restrict__ x1l,
                       const unsigned int* __restrict__ x2l) {
    __shared__ int is64;
    int t = threadIdx.x;
    if (t == 0) {
        int all0 = 1;
        for (int i = 1; i < 128; i += 2)
            if (x2l[i] != 0u) { all0 = 0; break; }
        is64 = all0;
    }
    __syncthreads();
    if (t < 32)  g_qlen[t] = (int)(is64 ? x1l[2 * t] : x1l[t]);
    if (t < 128) g_klen[t] = (int)(is64 ? x2l[2 * t] : x2l[t]);
}

// ---------------- fp32 -> bf16 hi/lo split ----------------
__global__ void k_cvt(const float* __restrict__ src, __nv_bfloat16* __restrict__ hi,
                      __nv_bfloat16* __restrict__ lo, int n4) {
    int i = blockIdx.x * blockDim.x + threadIdx.x;
    if (i >= n4) return;
    float4 v = ((const float4*)src)[i];
    __nv_bfloat16 h0 = __float2bfloat16(v.x), h1 = __float2bfloat16(v.y);
    __nv_bfloat16 h2 = __float2bfloat16(v.z), h3 = __float2bfloat16(v.w);
    __nv_bfloat16 l0 = __float2bfloat16(v.x - __bfloat162float(h0));
    __nv_bfloat16 l1 = __float2bfloat16(v.y - __bfloat162float(h1));
    __nv_bfloat16 l2 = __float2bfloat16(v.z - __bfloat162float(h2));
    __nv_bfloat16 l3 = __float2bfloat16(v.w - __bfloat162float(h3));
    __nv_bfloat162 a, b;
    a.x = h0; a.y = h1; b.x = h2; b.y = h3;
    ((__nv_bfloat162*)hi)[2 * i] = a;
    ((__nv_bfloat162*)hi)[2 * i + 1] = b;
    a.x = l0; a.y = l1; b.x = l2; b.y = l3;
    ((__nv_bfloat162*)lo)[2 * i] = a;
    ((__nv_bfloat162*)lo)[2 * i + 1] = b;
}

// ---------------- scores via mma.sync (unchanged from R4) ----------------
__global__ __launch_bounds__(256, 1) void k_scores_mma(float* __restrict__ attn_out) {
    extern __shared__ char smem[];
    uint32_t sb = smem_u32(smem);
    int t = threadIdx.x, lane = t & 31, wid = t >> 5;
    int wm = wid >> 2, wn = wid & 3;
    int p = blockIdx.y, x1i = p & 31;
    int qt = blockIdx.x, q0 = qt * 128;
    int qlen = g_qlen[x1i], klen = g_klen[p];

    const char* Qh = (const char*)(g_qh + (size_t)x1i * 262144);
    const char* Ql = (const char*)(g_ql + (size_t)x1i * 262144);
    const char* Kh = (const char*)(g_kh + (size_t)p * 262144);
    const char* Kl = (const char*)(g_kl + (size_t)p * 262144);

    float acc[4][4][4];
#pragma unroll
    for (int a = 0; a < 4; a++)
#pragma unroll
        for (int b = 0; b < 4; b++)
#pragma unroll
            for (int c = 0; c < 4; c++) acc[a][b][c] = 0.f;
    float rsum[4][2];
#pragma unroll
    for (int a = 0; a < 4; a++) rsum[a][0] = rsum[a][1] = 0.f;

    auto load_stage = [&](int s) {
        int nt = s >> 4, ec = s & 15;
        uint32_t bb = sb + (s & 1) * STAGE_B;
#pragma unroll
        for (int h = 0; h < 2; h++) {
            int idx = h * 256 + t;
            int row = idx >> 2, q = (idx & 3) * 16;
            uint32_t dst = row * PITCHB + q;
            size_t asrc = (size_t)(q0 + row) * 1024 + ec * 64 + q;
            size_t bsrc = (size_t)(nt * 128 + row) * 1024 + ec * 64 + q;
            cp_async16(bb + dst, Qh + asrc);
            cp_async16(bb + TILE_B + dst, Ql + asrc);
            cp_async16(bb + 2 * TILE_B + dst, Kh + bsrc);
            cp_async16(bb + 3 * TILE_B + dst, Kl + bsrc);
        }
    };

    load_stage(0);
    CP_COMMIT();

    for (int nt = 0; nt < 4; nt++) {
        for (int ec = 0; ec < 16; ec++) {
            int s = nt * 16 + ec;
            if (s + 1 < 64) {
                load_stage(s + 1);
                CP_COMMIT();
                CP_WAIT(1);
            } else {
                CP_WAIT(0);
            }
            __syncthreads();
            uint32_t bb = sb + (s & 1) * STAGE_B;
            uint32_t aBase = bb + (wm * 64 + (lane & 15)) * PITCHB + (lane >> 4) * 16;
            uint32_t bBase = bb + 2 * TILE_B + (wn * 32 + (lane & 7)) * PITCHB +
                             ((lane >> 3) & 1) * 16;
#pragma unroll
            for (int kk = 0; kk < 2; kk++) {
                uint32_t aHi[4][4], aLo[4][4], bHi[4][2], bLo[4][2];
#pragma unroll
                for (int mt = 0; mt < 4; mt++) {
                    uint32_t ad = aBase + mt * 16 * PITCHB + kk * 32;
                    ldm_x4(aHi[mt], ad);
                    ldm_x4(aLo[mt], ad + TILE_B);
                }
#pragma unroll
                for (int ntl = 0; ntl < 4; ntl++) {
                    uint32_t bd = bBase + ntl * 8 * PITCHB + kk * 32;
                    ldm_x2(bHi[ntl], bd);
                    ldm_x2(bLo[ntl], bd + TILE_B);
                }
#pragma unroll
                for (int mt = 0; mt < 4; mt++)
#pragma unroll
                    for (int ntl = 0; ntl < 4; ntl++) {
                        mma_bf16(acc[mt][ntl], aHi[mt], bHi[ntl]);
                        mma_bf16(acc[mt][ntl], aLo[mt], bHi[ntl]);
                        mma_bf16(acc[mt][ntl], aHi[mt], bLo[ntl]);
                    }
            }
            __syncthreads();
        }
        int nb = nt * 128 + wn * 32;
#pragma unroll
        for (int mt = 0; mt < 4; mt++) {
            int r0 = q0 + wm * 64 + mt * 16 + (lane >> 2);
            bool v0 = r0 < qlen;
            bool v1 = (r0 + 8) < qlen;
#pragma unroll
            for (int ntl = 0; ntl < 4; ntl++) {
                int col = nb + ntl * 8 + (lane & 3) * 2;
                float* cc = acc[mt][ntl];
                float e0 = (v0 && col < klen) ? __expf(cc[0] * SCALE_F) : 0.f;
                float e1 = (v0 && col + 1 < klen) ? __expf(cc[1] * SCALE_F) : 0.f;
                float e2 = (v1 && col < klen) ? __expf(cc[2] * SCALE_F) : 0.f;
                float e3 = (v1 && col + 1 < klen) ? __expf(cc[3] * SCALE_F) : 0.f;
                rsum[mt][0] += e0 + e1;
                rsum[mt][1] += e2 + e3;
                float2 w0 = {e0, e1}, w1 = {e2, e3};
                *(float2*)(attn_out + (size_t)p * 262144 + (size_t)r0 * 512 + col) = w0;
                *(float2*)(attn_out + (size_t)p * 262144 + (size_t)(r0 + 8) * 512 + col) = w1;
                cc[0] = cc[1] = cc[2] = cc[3] = 0.f;
            }
        }
    }
    __syncthreads();
    float* rs = (float*)(smem + RS_OFF);
#pragma unroll
    for (int mt = 0; mt < 4; mt++)
#pragma unroll
        for (int ri = 0; ri < 2; ri++) {
            float v = rsum[mt][ri];
            v += __shfl_xor_sync(0xffffffffu, v, 1);
            v += __shfl_xor_sync(0xffffffffu, v, 2);
            if ((lane & 3) == 0)
                rs[(wm * 64 + mt * 16 + ri * 8 + (lane >> 2)) * 4 + wn] = v;
        }
    __syncthreads();
    if (t < 128) {
        float s = rs[t * 4] + rs[t * 4 + 1] + rs[t * 4 + 2] + rs[t * 4 + 3];
        g_rowsum[p * 512 + q0 + t] = s;
    }
}

// ---------------- normalize + emit bf16 hi/lo of attn ----------------
__global__ void k_norm(float* __restrict__ attn) {
    int row = blockIdx.x;
    int t = threadIdx.x;
    float s = g_rowsum[row];
    float inv = s > 0.f ? 1.f / s : 0.f;
    float add = s > 0.f ? 0.f : (1.f / 512.f);
    float4* a = (float4*)(attn + (size_t)row * 512);
    float4 v = a[t];
    v.x = v.x * inv + add;
    v.y = v.y * inv + add;
    v.z = v.z * inv + add;
    v.w = v.w * inv + add;
    a[t] = v;
    __nv_bfloat16 h0 = __float2bfloat16(v.x), h1 = __float2bfloat16(v.y);
    __nv_bfloat16 h2 = __float2bfloat16(v.z), h3 = __float2bfloat16(v.w);
    __nv_bfloat16 l0 = __float2bfloat16(v.x - __bfloat162float(h0));
    __nv_bfloat16 l1 = __float2bfloat16(v.y - __bfloat162float(h1));
    __nv_bfloat16 l2 = __float2bfloat16(v.z - __bfloat162float(h2));
    __nv_bfloat16 l3 = __float2bfloat16(v.w - __bfloat162float(h3));
    __nv_bfloat162* hp = (__nv_bfloat162*)(g_ah + (size_t)row * 512);
    __nv_bfloat162* lp = (__nv_bfloat162*)(g_al + (size_t)row * 512);
    __nv_bfloat162 x;
    x.x = h0; x.y = h1; hp[2 * t] = x;
    x.x = h2; x.y = h3; hp[2 * t + 1] = x;
    x.x = l0; x.y = l1; lp[2 * t] = x;
    x.x = l2; x.y = l3; lp[2 * t + 1] = x;
}

// ---------------- x1_att = attn @ V via mma.sync; epilogue emits cat bf16 ----------
__global__ __launch_bounds__(256, 1) void k_av_mma(const float* __restrict__ x1) {
    extern __shared__ char smem[];
    uint32_t sb = smem_u32(smem);
    int t = threadIdx.x, lane = t & 31, wid = t >> 5;
    int wm = wid >> 2, wn = wid & 3;
    int p = blockIdx.z, x1i = p & 31;
    int q0 = blockIdx.y * 128, e0 = blockIdx.x * 128;

    const char* Ah = (const char*)(g_ah + (size_t)p * 262144);
    const char* Al = (const char*)(g_al + (size_t)p * 262144);
    const char* Vh = (const char*)(g_kh + (size_t)p * 262144);
    const char* Vl = (const char*)(g_kl + (size_t)p * 262144);

    float acc[4][4][4];
#pragma unroll
    for (int a = 0; a < 4; a++)
#pragma unroll
        for (int b = 0; b < 4; b++)
#pragma unroll
            for (int c = 0; c < 4; c++) acc[a][b][c] = 0.f;

    auto load_stage = [&](int s) {
        uint32_t bb = sb + (s & 1) * AV_STAGE;
#pragma unroll
        for (int h = 0; h < 2; h++) {
            int idx = h * 256 + t;
            int row = idx >> 2, ch = idx & 3;
            uint32_t d = bb + row * 80 + ch * 16;
            size_t off = (size_t)(q0 + row) * 1024 + s * 64 + ch * 16;
            cp_async16(d, Ah + off);
            cp_async16(d + AV_A_SZ, Al + off);
        }
#pragma unroll
        for (int h = 0; h < 2; h++) {
            int idx = h * 256 + t;
            int row = idx >> 4, ch = idx & 15;
            uint32_t d = bb + AV_VH_OFF + row * 272 + ch * 16;
            size_t off = (size_t)(s * 32 + row) * 1024 + e0 * 2 + ch * 16;
            cp_async16(d, Vh + off);
            cp_async16(d + AV_V_SZ, Vl + off);
        }
    };

    load_stage(0);
    CP_COMMIT();

    for (int s = 0; s < 16; s++) {
        if (s + 1 < 16) {
            load_stage(s + 1);
            CP_COMMIT();
            CP_WAIT(1);
        } else {
            CP_WAIT(0);
        }
        __syncthreads();
        uint32_t bb = sb + (s & 1) * AV_STAGE;
#pragma unroll
        for (int kk = 0; kk < 2; kk++) {
            uint32_t aBase = bb + (wm * 64 + (lane & 15)) * 80 + (lane >> 4) * 16 + kk * 32;
            uint32_t bBase = bb + AV_VH_OFF + (kk * 16 + (lane & 15)) * 272 + wn * 64;
            uint32_t aHi[4][4], aLo[4][4], bHi[4][2], bLo[4][2];
#pragma unroll
            for (int mt = 0; mt < 4; mt++) {
                uint32_t ad = aBase + mt * 16 * 80;
                ldm_x4(aHi[mt], ad);
                ldm_x4(aLo[mt], ad + AV_A_SZ);
            }
#pragma unroll
            for (int ntl = 0; ntl < 4; ntl++) {
                uint32_t bd = bBase + ntl * 16;
                ldm_x2t(bHi[ntl], bd);
                ldm_x2t(bLo[ntl], bd + AV_V_SZ);
            }
#pragma unroll
            for (int mt = 0; mt < 4; mt++)
#pragma unroll
                for (int ntl = 0; ntl < 4; ntl++) {
                    mma_bf16(acc[mt][ntl], aHi[mt], bHi[ntl]);
                    mma_bf16(acc[mt][ntl], aLo[mt], bHi[ntl]);
                    mma_bf16(acc[mt][ntl], aHi[mt], bLo[ntl]);
                }
        }
        __syncthreads();
    }

    // epilogue: xa -> (x1 - xa, x1 * xa) bf16 hi/lo
    const float* X1 = x1 + (size_t)x1i * 262144;
    __nv_bfloat162* Sh = (__nv_bfloat162*)(g_sh + (size_t)p * 262144);
    __nv_bfloat162* Sl = (__nv_bfloat162*)(g_sl + (size_t)p * 262144);
    __nv_bfloat162* Mh = (__nv_bfloat162*)(g_mh + (size_t)p * 262144);
    __nv_bfloat162* Ml = (__nv_bfloat162*)(g_ml + (size_t)p * 262144);
#pragma unroll
    for (int mt = 0; mt < 4; mt++) {
#pragma unroll
        for (int ntl = 0; ntl < 4; ntl++) {
            float* cc = acc[mt][ntl];
            int c = e0 + wn * 32 + ntl * 8 + (lane & 3) * 2;
#pragma unroll
            for (int hh = 0; hh < 2; hh++) {
                int r = q0 + wm * 64 + mt * 16 + (lane >> 2) + hh * 8;
                float2 u = *(const float2*)(X1 + (size_t)r * 512 + c);
                float xa0 = cc[hh * 2], xa1 = cc[hh * 2 + 1];
                float s0 = u.x - xa0, s1 = u.y - xa1;
                float m0 = u.x * xa0, m1 = u.y * xa1;
                size_t o = ((size_t)r * 512 + c) >> 1;
                __nv_bfloat162 w;
                __nv_bfloat16 h0 = __float2bfloat16(s0), h1 = __float2bfloat16(s1);
                w.x = h0; w.y = h1; Sh[o] = w;
                w.x = __float2bfloat16(s0 - __bfloat162float(h0));
                w.y = __float2bfloat16(s1 - __bfloat162float(h1));
                Sl[o] = w;
                h0 = __float2bfloat16(m0); h1 = __float2bfloat16(m1);
                w.x = h0; w.y = h1; Mh[o] = w;
                w.x = __float2bfloat16(m0 - __bfloat162float(h0));
                w.y = __float2bfloat16(m1 - __bfloat162float(h1));
                Ml[o] = w;
            }
        }
    }
}

// ---------------- fusion GEMM via mma.sync + bias/relu + partial pooling ----------
__global__ __launch_bounds__(256, 1) void k_fusion_mma(const float* __restrict__ fb) {
    extern __shared__ char smem[];
    uint32_t sb = smem_u32(smem);
    int t = threadIdx.x, lane = t & 31, wid = t >> 5;
    int wm = wid >> 2, wn = wid & 3;
    int p = blockIdx.z;
    int qt = blockIdx.y, q0 = qt * 128, e0 = blockIdx.x * 128;

    const char* Sh = (const char*)(g_sh + (size_t)p * 262144);
    const char* Sl = (const char*)(g_sl + (size_t)p * 262144);
    const char* Mh = (const char*)(g_mh + (size_t)p * 262144);
    const char* Ml = (const char*)(g_ml + (size_t)p * 262144);
    const char* Wh = (const char*)g_fwh;
    const char* Wl = (const char*)g_fwl;

    float acc[4][4][4];
#pragma unroll
    for (int a = 0; a < 4; a++)
#pragma unroll
        for (int b = 0; b < 4; b++)
#pragma unroll
            for (int c = 0; c < 4; c++) acc[a][b][c] = 0.f;

    auto load_stage = [&](int s) {
        uint32_t bb = sb + (s & 1) * AV_STAGE;
        const char* ah = (s < 16) ? Sh : Mh;
        const char* al = (s < 16) ? Sl : Ml;
        int kc = (s & 15) * 64;
#pragma unroll
        for (int h = 0; h < 2; h++) {
            int idx = h * 256 + t;
            int row = idx >> 2, ch = idx & 3;
            uint32_t d = bb + row * 80 + ch * 16;
            size_t off = (size_t)(q0 + row) * 1024 + kc + ch * 16;
            cp_async16(d, ah + off);
            cp_async16(d + AV_A_SZ, al + off);
        }
#pragma unroll
        for (int h = 0; h < 2; h++) {
            int idx = h * 256 + t;
            int row = idx >> 4, ch = idx & 15;
            uint32_t d = bb + AV_VH_OFF + row * 272 + ch * 16;
            size_t off = (size_t)(s * 32 + row) * 1024 + e0 * 2 + ch * 16;
            cp_async16(d, Wh + off);
            cp_async16(d + AV_V_SZ, Wl + off);
        }
    };

    load_stage(0);
    CP_COMMIT();

    for (int s = 0; s < 32; s++) {
        if (s + 1 < 32) {
            load_stage(s + 1);
            CP_COMMIT();
            CP_WAIT(1);
        } else {
            CP_WAIT(0);
        }
        __syncthreads();
        uint32_t bb = sb + (s & 1) * AV_STAGE;
#pragma unroll
        for (int kk = 0; kk < 2; kk++) {
            uint32_t aBase = bb + (wm * 64 + (lane & 15)) * 80 + (lane >> 4) * 16 + kk * 32;
            uint32_t bBase = bb + AV_VH_OFF + (kk * 16 + (lane & 15)) * 272 + wn * 64;
            uint32_t aHi[4][4], aLo[4][4], bHi[4][2], bLo[4][2];
#pragma unroll
            for (int mt = 0; mt < 4; mt++) {
                uint32_t ad = aBase + mt * 16 * 80;
                ldm_x4(aHi[mt], ad);
                ldm_x4(aLo[mt], ad + AV_A_SZ);
            }
#pragma unroll
            for (int ntl = 0; ntl < 4; ntl++) {
                uint32_t bd = bBase + ntl * 16;
                ldm_x2t(bHi[ntl], bd);
                ldm_x2t(bLo[ntl], bd + AV_V_SZ);
            }
#pragma unroll
            for (int mt = 0; mt < 4; mt++)
#pragma unroll
                for (int ntl = 0; ntl < 4; ntl++) {
                    mma_bf16(acc[mt][ntl], aHi[mt], bHi[ntl]);
                    mma_bf16(acc[mt][ntl], aLo[mt], bHi[ntl]);
                    mma_bf16(acc[mt][ntl], aHi[mt], bLo[ntl]);
                }
        }
        __syncthreads();
    }

    // bias + relu + pool over this block's 128 rows
    float psum[4][2], pmax[4][2];
#pragma unroll
    for (int ntl = 0; ntl < 4; ntl++) {
        psum[ntl][0] = psum[ntl][1] = 0.f;
        pmax[ntl][0] = pmax[ntl][1] = 0.f;
    }
#pragma unroll
    for (int ntl = 0; ntl < 4; ntl++) {
        int c = e0 + wn * 32 + ntl * 8 + (lane & 3) * 2;
        float b0 = fb[c], b1 = fb[c + 1];
#pragma unroll
        for (int mt = 0; mt < 4; mt++) {
            float* cc = acc[mt][ntl];
            float v0 = fmaxf(cc[0] + b0, 0.f);
            float v1 = fmaxf(cc[1] + b1, 0.f);
            float v2 = fmaxf(cc[2] + b0, 0.f);
            float v3 = fmaxf(cc[3] + b1, 0.f);
            psum[ntl][0] += v0 + v2;
            psum[ntl][1] += v1 + v3;
            pmax[ntl][0] = fmaxf(pmax[ntl][0], fmaxf(v0, v2));
            pmax[ntl][1] = fmaxf(pmax[ntl][1], fmaxf(v1, v3));
        }
    }
    float* redS = (float*)(smem + FU_RED_OFF);
    float* redM = redS + 256;
#pragma unroll
    for (int ntl = 0; ntl < 4; ntl++)
#pragma unroll
        for (int j = 0; j < 2; j++) {
            float s = psum[ntl][j], m = pmax[ntl][j];
            s += __shfl_xor_sync(0xffffffffu, s, 4);
            s += __shfl_xor_sync(0xffffffffu, s, 8);
            s += __shfl_xor_sync(0xffffffffu, s, 16);
            m = fmaxf(m, __shfl_xor_sync(0xffffffffu, m, 4));
            m = fmaxf(m, __shfl_xor_sync(0xffffffffu, m, 8));
            m = fmaxf(m, __shfl_xor_sync(0xffffffffu, m, 16));
            if (lane < 4) {
                int col = wn * 32 + ntl * 8 + lane * 2 + j;
                redS[wm * 128 + col] = s;
                redM[wm * 128 + col] = m;
            }
        }
    __syncthreads();
    if (t < 128) {
        float s = redS[t] + redS[128 + t];
        float m = fmaxf(redM[t], redM[128 + t]);
        int idx = (p * 4 + qt) * 512 + e0 + t;
        g_psum[idx] = s;
        g_pmax[idx] = m;
    }
}

// ---------------- pool finalize ----------------
__global__ void k_pool(void) {
    int p = blockIdx.x, e = threadIdx.x;
    float s = 0.f, m = 0.f;
#pragma unroll
    for (int qt = 0; qt < 4; qt++) {
        int idx = (p * 4 + qt) * 512 + e;
        s += g_psum[idx];
        m = fmaxf(m, g_pmax[idx]);
    }
    int base = (p >> 2) * 4096 + (p & 3) * 512 + e;
    g_pooled[base] = s * (1.0f / 512.0f);
    g_pooled[base + 2048] = m;
}

// ---------------- out = relu(pooled @ out_w + out_b) ----------------
__global__ __launch_bounds__(256) void k_out(const float* __restrict__ ow,
                                             const float* __restrict__ ob,
                                             float* __restrict__ outp) {
    __shared__ float sp[4096];
    int b = blockIdx.x, t = threadIdx.x;
    for (int i = t; i < 4096; i += 256) sp[i] = g_pooled[b * 4096 + i];
    __syncthreads();
    int col = t * 4;
    float4 acc = *(const float4*)(ob + col);
#pragma unroll 8
    for (int c = 0; c < 4096; c++) {
        float pv = sp[c];
        float4 w = *(const float4*)(ow + (size_t)c * 1024 + col);
        acc.x += pv * w.x;
        acc.y += pv * w.y;
        acc.z += pv * w.z;
        acc.w += pv * w.w;
    }
    acc.x = fmaxf(acc.x, 0.f);
    acc.y = fmaxf(acc.y, 0.f);
    acc.z = fmaxf(acc.z, 0.f);
    acc.w = fmaxf(acc.w, 0.f);
    *(float4*)(outp + b * 1024 + col) = acc;
}

extern "C" void kernel_launch(void* const* d_in, const int* in_sizes, int n_in,
                              void* d_out, int out_size) {
    const float* x1 = (const float*)d_in[0];
    const float* x2 = (const float*)d_in[1];
    const unsigned int* x1_len = (const unsigned int*)d_in[2];
    const unsigned int* x2_len = (const unsigned int*)d_in[3];
    const float* fw = (const float*)d_in[4];
    const float* fb = (const float*)d_in[5];
    const float* ow = (const float*)d_in[6];
    const float* ob = (const float*)d_in[7];

    float* outp = (float*)d_out;
    float* attn;
    if (out_size >= OUT_ELEMS + ATTN_ELEMS) {
        attn = outp + OUT_ELEMS;
    } else if (out_size >= ATTN_ELEMS) {
        attn = outp;
        void* dp = nullptr;
        cudaGetSymbolAddress(&dp, g_out_dummy);
        outp = (float*)dp;
    } else {
        void* dp = nullptr;
        cudaGetSymbolAddress(&dp, g_attn_scratch);
        attn = (float*)dp;
    }

    void *qh, *ql, *kh, *kl, *fwh, *fwl;
    cudaGetSymbolAddress(&qh, g_qh);
    cudaGetSymbolAddress(&ql, g_ql);
    cudaGetSymbolAddress(&kh, g_kh);
    cudaGetSymbolAddress(&kl, g_kl);
    cudaGetSymbolAddress(&fwh, g_fwh);
    cudaGetSymbolAddress(&fwl, g_fwl);

    cudaFuncSetAttribute(k_scores_mma, cudaFuncAttributeMaxDynamicSharedMemorySize, SC_SMEM);
    cudaFuncSetAttribute(k_av_mma, cudaFuncAttributeMaxDynamicSharedMemorySize, AV_SMEM);
    cudaFuncSetAttribute(k_fusion_mma, cudaFuncAttributeMaxDynamicSharedMemorySize, FU_SMEM);

    k_lens<<<1, 128>>>(x1_len, x2_len);
    k_cvt<<<8192, 256>>>(x1, (__nv_bfloat16*)qh, (__nv_bfloat16*)ql, 2097152);
    k_cvt<<<32768, 256>>>(x2, (__nv_bfloat16*)kh, (__nv_bfloat16*)kl, 8388608);
    k_cvt<<<512, 256>>>(fw, (__nv_bfloat16*)fwh, (__nv_bfloat16*)fwl, 131072);
    k_scores_mma<<<dim3(4, NPAIR), 256, SC_SMEM>>>(attn);
    k_norm<<<NPAIR * CL, 128>>>(attn);
    k_av_mma<<<dim3(4, 4, NPAIR), 256, AV_SMEM>>>(x1);
    k_fusion_mma<<<dim3(4, 4, NPAIR), 256, FU_SMEM>>>(fb);
    k_pool<<<NPAIR, 512>>>();
    k_out<<<NB, 256>>>(ow, ob, outp);
}

// round 6
// speedup vs baseline: 2.1123x; 1.0585x over previous
#include <cuda_runtime.h>
#include <cuda_bf16.h>
#include <cstdint>

#define CL 512
#define CE 512
#define NPAIR 128
#define NB 32
#define ATTN_ELEMS (NPAIR * CL * CL)
#define OUT_ELEMS (NB * 1024)
#define SCALE_F 0.044194173824159216f

// ---------------- scratch (device globals; alloc-free rule) ----------------
__device__ float g_pooled[NB * 4096];
__device__ float g_attn_scratch[ATTN_ELEMS];
__device__ float g_out_dummy[OUT_ELEMS];
__device__ float g_rowsum[NPAIR * CL];
__device__ float g_psum[4 * NPAIR * CL];
__device__ float g_pmax[4 * NPAIR * CL];
__device__ int g_qlen[32];
__device__ int g_klen[128];
__device__ __nv_bfloat16 g_qh[NB * CL * CE];
__device__ __nv_bfloat16 g_ql[NB * CL * CE];
__device__ __nv_bfloat16 g_kh[NPAIR * CL * CE];
__device__ __nv_bfloat16 g_kl[NPAIR * CL * CE];
__device__ __nv_bfloat16 g_ah[NPAIR * CL * CL];  // UNNORMALIZED exp hi
__device__ __nv_bfloat16 g_al[NPAIR * CL * CL];  // UNNORMALIZED exp lo
__device__ __nv_bfloat16 g_sh[NPAIR * CL * CE];  // x1 - xa hi
__device__ __nv_bfloat16 g_sl[NPAIR * CL * CE];
__device__ __nv_bfloat16 g_mh[NPAIR * CL * CE];  // x1 * xa hi
__device__ __nv_bfloat16 g_ml[NPAIR * CL * CE];
__device__ __nv_bfloat16 g_fwh[1024 * 512];
__device__ __nv_bfloat16 g_fwl[1024 * 512];

// ---------------- PTX helpers ----------------
__device__ __forceinline__ uint32_t smem_u32(const void* p) {
    uint32_t a;
    asm("{ .reg .u64 t; cvta.to.shared.u64 t, %1; cvt.u32.u64 %0, t; }" : "=r"(a) : "l"(p));
    return a;
}
__device__ __forceinline__ void cp_async16(uint32_t dst, const void* src) {
    asm volatile("cp.async.ca.shared.global [%0], [%1], 16;" :: "r"(dst), "l"(src));
}
#define CP_COMMIT() asm volatile("cp.async.commit_group;" ::: "memory")
#define CP_WAIT(n)  asm volatile("cp.async.wait_group %0;" :: "n"(n) : "memory")

__device__ __forceinline__ void ldm_x4(uint32_t* r, uint32_t addr) {
    asm volatile("ldmatrix.sync.aligned.m8n8.x4.shared.b16 {%0,%1,%2,%3}, [%4];"
                 : "=r"(r[0]), "=r"(r[1]), "=r"(r[2]), "=r"(r[3]) : "r"(addr));
}
__device__ __forceinline__ void ldm_x2(uint32_t* r, uint32_t addr) {
    asm volatile("ldmatrix.sync.aligned.m8n8.x2.shared.b16 {%0,%1}, [%2];"
                 : "=r"(r[0]), "=r"(r[1]) : "r"(addr));
}
__device__ __forceinline__ void ldm_x2t(uint32_t* r, uint32_t addr) {
    asm volatile("ldmatrix.sync.aligned.m8n8.x2.trans.shared.b16 {%0,%1}, [%2];"
                 : "=r"(r[0]), "=r"(r[1]) : "r"(addr));
}
__device__ __forceinline__ void mma_bf16(float* c, const uint32_t* a, const uint32_t* b) {
    asm volatile(
        "mma.sync.aligned.m16n8k16.row.col.f32.bf16.bf16.f32 "
        "{%0,%1,%2,%3}, {%4,%5,%6,%7}, {%8,%9}, {%0,%1,%2,%3};"
        : "+f"(c[0]), "+f"(c[1]), "+f"(c[2]), "+f"(c[3])
        : "r"(a[0]), "r"(a[1]), "r"(a[2]), "r"(a[3]), "r"(b[0]), "r"(b[1]));
}

// ---------------- k_scores smem geometry ----------------
#define PITCHB 80
#define TILE_B (128 * PITCHB)
#define STAGE_B (4 * TILE_B)
#define RS_OFF (2 * STAGE_B)
#define SC_SMEM (RS_OFF + 128 * 4 * 4)

// ---------------- AV / fusion smem geometry ----------------
#define AV_A_SZ (128 * 80)
#define AV_V_SZ (32 * 272)
#define AV_VH_OFF (2 * AV_A_SZ)
#define AV_STAGE (2 * AV_A_SZ + 2 * AV_V_SZ)
#define AV_SMEM (2 * AV_STAGE)
#define FU_RED_OFF AV_SMEM
#define FU_SMEM (AV_SMEM + 2048)

// ---------------- length normalization ----------------
__global__ void k_lens(const unsigned int* __restrict__ x1l,
                       const unsigned int* __restrict__ x2l) {
    __shared__ int is64;
    int t = threadIdx.x;
    if (t == 0) {
        int all0 = 1;
        for (int i = 1; i < 128; i += 2)
            if (x2l[i] != 0u) { all0 = 0; break; }
        is64 = all0;
    }
    __syncthreads();
    if (t < 32)  g_qlen[t] = (int)(is64 ? x1l[2 * t] : x1l[t]);
    if (t < 128) g_klen[t] = (int)(is64 ? x2l[2 * t] : x2l[t]);
}

// ---------------- fp32 -> bf16 hi/lo split ----------------
__global__ void k_cvt(const float* __restrict__ src, __nv_bfloat16* __restrict__ hi,
                      __nv_bfloat16* __restrict__ lo, int n4) {
    int i = blockIdx.x * blockDim.x + threadIdx.x;
    if (i >= n4) return;
    float4 v = ((const float4*)src)[i];
    __nv_bfloat16 h0 = __float2bfloat16(v.x), h1 = __float2bfloat16(v.y);
    __nv_bfloat16 h2 = __float2bfloat16(v.z), h3 = __float2bfloat16(v.w);
    __nv_bfloat16 l0 = __float2bfloat16(v.x - __bfloat162float(h0));
    __nv_bfloat16 l1 = __float2bfloat16(v.y - __bfloat162float(h1));
    __nv_bfloat16 l2 = __float2bfloat16(v.z - __bfloat162float(h2));
    __nv_bfloat16 l3 = __float2bfloat16(v.w - __bfloat162float(h3));
    __nv_bfloat162 a, b;
    a.x = h0; a.y = h1; b.x = h2; b.y = h3;
    ((__nv_bfloat162*)hi)[2 * i] = a;
    ((__nv_bfloat162*)hi)[2 * i + 1] = b;
    a.x = l0; a.y = l1; b.x = l2; b.y = l3;
    ((__nv_bfloat162*)lo)[2 * i] = a;
    ((__nv_bfloat162*)lo)[2 * i + 1] = b;
}

// ---------------- scores: Q@K^T, masked exp -> bf16 hi/lo (UNNORMALIZED) -----------
// Fully-masked rows (r>=qlen || klen==0) emit exp==1 everywhere -> uniform softmax.
__global__ __launch_bounds__(256, 2) void k_scores_mma(void) {
    extern __shared__ char smem[];
    uint32_t sb = smem_u32(smem);
    int t = threadIdx.x, lane = t & 31, wid = t >> 5;
    int wm = wid >> 2, wn = wid & 3;
    int p = blockIdx.y, x1i = p & 31;
    int qt = blockIdx.x, q0 = qt * 128;
    int qlen = g_qlen[x1i], klen = g_klen[p];

    const char* Qh = (const char*)(g_qh + (size_t)x1i * 262144);
    const char* Ql = (const char*)(g_ql + (size_t)x1i * 262144);
    const char* Kh = (const char*)(g_kh + (size_t)p * 262144);
    const char* Kl = (const char*)(g_kl + (size_t)p * 262144);

    float acc[4][4][4];
#pragma unroll
    for (int a = 0; a < 4; a++)
#pragma unroll
        for (int b = 0; b < 4; b++)
#pragma unroll
            for (int c = 0; c < 4; c++) acc[a][b][c] = 0.f;
    float rsum[4][2];
#pragma unroll
    for (int a = 0; a < 4; a++) rsum[a][0] = rsum[a][1] = 0.f;

    auto load_stage = [&](int s) {
        int nt = s >> 4, ec = s & 15;
        uint32_t bb = sb + (s & 1) * STAGE_B;
#pragma unroll
        for (int h = 0; h < 2; h++) {
            int idx = h * 256 + t;
            int row = idx >> 2, q = (idx & 3) * 16;
            uint32_t dst = row * PITCHB + q;
            size_t asrc = (size_t)(q0 + row) * 1024 + ec * 64 + q;
            size_t bsrc = (size_t)(nt * 128 + row) * 1024 + ec * 64 + q;
            cp_async16(bb + dst, Qh + asrc);
            cp_async16(bb + TILE_B + dst, Ql + asrc);
            cp_async16(bb + 2 * TILE_B + dst, Kh + bsrc);
            cp_async16(bb + 3 * TILE_B + dst, Kl + bsrc);
        }
    };

    load_stage(0);
    CP_COMMIT();

    __nv_bfloat162* AH = (__nv_bfloat162*)(g_ah + (size_t)p * 262144);
    __nv_bfloat162* AL = (__nv_bfloat162*)(g_al + (size_t)p * 262144);

    for (int nt = 0; nt < 4; nt++) {
        for (int ec = 0; ec < 16; ec++) {
            int s = nt * 16 + ec;
            if (s + 1 < 64) {
                load_stage(s + 1);
                CP_COMMIT();
                CP_WAIT(1);
            } else {
                CP_WAIT(0);
            }
            __syncthreads();
            uint32_t bb = sb + (s & 1) * STAGE_B;
#pragma unroll
            for (int kk = 0; kk < 2; kk++) {
                uint32_t aBase = bb + (wm * 64 + (lane & 15)) * PITCHB + (lane >> 4) * 16 +
                                 kk * 32;
                uint32_t bBase = bb + 2 * TILE_B + (wn * 32 + (lane & 7)) * PITCHB +
                                 ((lane >> 3) & 1) * 16 + kk * 32;
                uint32_t aHi[4][4], aLo[4][4];
#pragma unroll
                for (int mt = 0; mt < 4; mt++) {
                    uint32_t ad = aBase + mt * 16 * PITCHB;
                    ldm_x4(aHi[mt], ad);
                    ldm_x4(aLo[mt], ad + TILE_B);
                }
#pragma unroll
                for (int ntl = 0; ntl < 4; ntl++) {
                    uint32_t bd = bBase + ntl * 8 * PITCHB;
                    uint32_t bH[2], bL[2];
                    ldm_x2(bH, bd);
                    ldm_x2(bL, bd + TILE_B);
#pragma unroll
                    for (int mt = 0; mt < 4; mt++) {
                        mma_bf16(acc[mt][ntl], aHi[mt], bH);
                        mma_bf16(acc[mt][ntl], aLo[mt], bH);
                        mma_bf16(acc[mt][ntl], aHi[mt], bL);
                    }
                }
            }
            __syncthreads();
        }
        int nb = nt * 128 + wn * 32;
#pragma unroll
        for (int mt = 0; mt < 4; mt++) {
            int r0 = q0 + wm * 64 + mt * 16 + (lane >> 2);
            bool fm0 = (r0 >= qlen) || (klen == 0);
            bool fm1 = ((r0 + 8) >= qlen) || (klen == 0);
#pragma unroll
            for (int ntl = 0; ntl < 4; ntl++) {
                int col = nb + ntl * 8 + (lane & 3) * 2;
                float* cc = acc[mt][ntl];
                float e0 = fm0 ? 1.f : ((col < klen) ? __expf(cc[0] * SCALE_F) : 0.f);
                float e1 = fm0 ? 1.f : ((col + 1 < klen) ? __expf(cc[1] * SCALE_F) : 0.f);
                float e2 = fm1 ? 1.f : ((col < klen) ? __expf(cc[2] * SCALE_F) : 0.f);
                float e3 = fm1 ? 1.f : ((col + 1 < klen) ? __expf(cc[3] * SCALE_F) : 0.f);
                rsum[mt][0] += e0 + e1;
                rsum[mt][1] += e2 + e3;
                size_t o0 = ((size_t)r0 * 512 + col) >> 1;
                size_t o1 = ((size_t)(r0 + 8) * 512 + col) >> 1;
                __nv_bfloat162 w;
                __nv_bfloat16 h0 = __float2bfloat16(e0), h1 = __float2bfloat16(e1);
                w.x = h0; w.y = h1; AH[o0] = w;
                w.x = __float2bfloat16(e0 - __bfloat162float(h0));
                w.y = __float2bfloat16(e1 - __bfloat162float(h1));
                AL[o0] = w;
                h0 = __float2bfloat16(e2); h1 = __float2bfloat16(e3);
                w.x = h0; w.y = h1; AH[o1] = w;
                w.x = __float2bfloat16(e2 - __bfloat162float(h0));
                w.y = __float2bfloat16(e3 - __bfloat162float(h1));
                AL[o1] = w;
                cc[0] = cc[1] = cc[2] = cc[3] = 0.f;
            }
        }
    }
    __syncthreads();
    float* rs = (float*)(smem + RS_OFF);
#pragma unroll
    for (int mt = 0; mt < 4; mt++)
#pragma unroll
        for (int ri = 0; ri < 2; ri++) {
            float v = rsum[mt][ri];
            v += __shfl_xor_sync(0xffffffffu, v, 1);
            v += __shfl_xor_sync(0xffffffffu, v, 2);
            if ((lane & 3) == 0)
                rs[(wm * 64 + mt * 16 + ri * 8 + (lane >> 2)) * 4 + wn] = v;
        }
    __syncthreads();
    if (t < 128) {
        float s = rs[t * 4] + rs[t * 4 + 1] + rs[t * 4 + 2] + rs[t * 4 + 3];
        g_rowsum[p * 512 + q0 + t] = s;
    }
}

// ---------------- normalize: fp32 attn output from bf16 exp + rowsum ----------------
__global__ void k_norm(float* __restrict__ attn) {
    int row = blockIdx.x;
    int t = threadIdx.x;
    float s = g_rowsum[row];
    float inv = s > 0.f ? 1.f / s : 0.f;
    const __nv_bfloat162* hp = (const __nv_bfloat162*)(g_ah + (size_t)row * 512);
    const __nv_bfloat162* lp = (const __nv_bfloat162*)(g_al + (size_t)row * 512);
    __nv_bfloat162 h0 = hp[2 * t], h1 = hp[2 * t + 1];
    __nv_bfloat162 l0 = lp[2 * t], l1 = lp[2 * t + 1];
    float4 v;
    v.x = (__bfloat162float(h0.x) + __bfloat162float(l0.x)) * inv;
    v.y = (__bfloat162float(h0.y) + __bfloat162float(l0.y)) * inv;
    v.z = (__bfloat162float(h1.x) + __bfloat162float(l1.x)) * inv;
    v.w = (__bfloat162float(h1.y) + __bfloat162float(l1.y)) * inv;
    ((float4*)(attn + (size_t)row * 512))[t] = v;
}

// ---------------- x1_att = exp @ V (scaled by 1/rowsum); epilogue emits cat bf16 ----
__global__ __launch_bounds__(256, 2) void k_av_mma(const float* __restrict__ x1) {
    extern __shared__ char smem[];
    uint32_t sb = smem_u32(smem);
    int t = threadIdx.x, lane = t & 31, wid = t >> 5;
    int wm = wid >> 2, wn = wid & 3;
    int p = blockIdx.z, x1i = p & 31;
    int q0 = blockIdx.y * 128, e0 = blockIdx.x * 128;

    const char* Ah = (const char*)(g_ah + (size_t)p * 262144);
    const char* Al = (const char*)(g_al + (size_t)p * 262144);
    const char* Vh = (const char*)(g_kh + (size_t)p * 262144);
    const char* Vl = (const char*)(g_kl + (size_t)p * 262144);

    float acc[4][4][4];
#pragma unroll
    for (int a = 0; a < 4; a++)
#pragma unroll
        for (int b = 0; b < 4; b++)
#pragma unroll
            for (int c = 0; c < 4; c++) acc[a][b][c] = 0.f;

    auto load_stage = [&](int s) {
        uint32_t bb = sb + (s & 1) * AV_STAGE;
#pragma unroll
        for (int h = 0; h < 2; h++) {
            int idx = h * 256 + t;
            int row = idx >> 2, ch = idx & 3;
            uint32_t d = bb + row * 80 + ch * 16;
            size_t off = (size_t)(q0 + row) * 1024 + s * 64 + ch * 16;
            cp_async16(d, Ah + off);
            cp_async16(d + AV_A_SZ, Al + off);
        }
#pragma unroll
        for (int h = 0; h < 2; h++) {
            int idx = h * 256 + t;
            int row = idx >> 4, ch = idx & 15;
            uint32_t d = bb + AV_VH_OFF + row * 272 + ch * 16;
            size_t off = (size_t)(s * 32 + row) * 1024 + e0 * 2 + ch * 16;
            cp_async16(d, Vh + off);
            cp_async16(d + AV_V_SZ, Vl + off);
        }
    };

    load_stage(0);
    CP_COMMIT();

    for (int s = 0; s < 16; s++) {
        if (s + 1 < 16) {
            load_stage(s + 1);
            CP_COMMIT();
            CP_WAIT(1);
        } else {
            CP_WAIT(0);
        }
        __syncthreads();
        uint32_t bb = sb + (s & 1) * AV_STAGE;
#pragma unroll
        for (int kk = 0; kk < 2; kk++) {
            uint32_t aBase = bb + (wm * 64 + (lane & 15)) * 80 + (lane >> 4) * 16 + kk * 32;
            uint32_t bBase = bb + AV_VH_OFF + (kk * 16 + (lane & 15)) * 272 + wn * 64;
            uint32_t aHi[4][4], aLo[4][4];
#pragma unroll
            for (int mt = 0; mt < 4; mt++) {
                uint32_t ad = aBase + mt * 16 * 80;
                ldm_x4(aHi[mt], ad);
                ldm_x4(aLo[mt], ad + AV_A_SZ);
            }
#pragma unroll
            for (int ntl = 0; ntl < 4; ntl++) {
                uint32_t bd = bBase + ntl * 16;
                uint32_t bH[2], bL[2];
                ldm_x2t(bH, bd);
                ldm_x2t(bL, bd + AV_V_SZ);
#pragma unroll
                for (int mt = 0; mt < 4; mt++) {
                    mma_bf16(acc[mt][ntl], aHi[mt], bH);
                    mma_bf16(acc[mt][ntl], aLo[mt], bH);
                    mma_bf16(acc[mt][ntl], aHi[mt], bL);
                }
            }
        }
        __syncthreads();
    }

    // epilogue: xa = acc/rowsum -> (x1 - xa, x1 * xa) bf16 hi/lo
    const float* X1 = x1 + (size_t)x1i * 262144;
    __nv_bfloat162* Sh = (__nv_bfloat162*)(g_sh + (size_t)p * 262144);
    __nv_bfloat162* Sl = (__nv_bfloat162*)(g_sl + (size_t)p * 262144);
    __nv_bfloat162* Mh = (__nv_bfloat162*)(g_mh + (size_t)p * 262144);
    __nv_bfloat162* Ml = (__nv_bfloat162*)(g_ml + (size_t)p * 262144);
#pragma unroll
    for (int mt = 0; mt < 4; mt++) {
#pragma unroll
        for (int hh = 0; hh < 2; hh++) {
            int r = q0 + wm * 64 + mt * 16 + (lane >> 2) + hh * 8;
            float sr = g_rowsum[p * 512 + r];
            float inv = 1.f / sr;
#pragma unroll
            for (int ntl = 0; ntl < 4; ntl++) {
                float* cc = acc[mt][ntl];
                int c = e0 + wn * 32 + ntl * 8 + (lane & 3) * 2;
                float2 u = *(const float2*)(X1 + (size_t)r * 512 + c);
                float xa0 = cc[hh * 2] * inv, xa1 = cc[hh * 2 + 1] * inv;
                float s0 = u.x - xa0, s1 = u.y - xa1;
                float m0 = u.x * xa0, m1 = u.y * xa1;
                size_t o = ((size_t)r * 512 + c) >> 1;
                __nv_bfloat162 w;
                __nv_bfloat16 h0 = __float2bfloat16(s0), h1 = __float2bfloat16(s1);
                w.x = h0; w.y = h1; Sh[o] = w;
                w.x = __float2bfloat16(s0 - __bfloat162float(h0));
                w.y = __float2bfloat16(s1 - __bfloat162float(h1));
                Sl[o] = w;
                h0 = __float2bfloat16(m0); h1 = __float2bfloat16(m1);
                w.x = h0; w.y = h1; Mh[o] = w;
                w.x = __float2bfloat16(m0 - __bfloat162float(h0));
                w.y = __float2bfloat16(m1 - __bfloat162float(h1));
                Ml[o] = w;
            }
        }
    }
}

// ---------------- fusion GEMM via mma.sync + bias/relu + partial pooling ----------
__global__ __launch_bounds__(256, 2) void k_fusion_mma(const float* __restrict__ fb) {
    extern __shared__ char smem[];
    uint32_t sb = smem_u32(smem);
    int t = threadIdx.x, lane = t & 31, wid = t >> 5;
    int wm = wid >> 2, wn = wid & 3;
    int p = blockIdx.z;
    int qt = blockIdx.y, q0 = qt * 128, e0 = blockIdx.x * 128;

    const char* Sh = (const char*)(g_sh + (size_t)p * 262144);
    const char* Sl = (const char*)(g_sl + (size_t)p * 262144);
    const char* Mh = (const char*)(g_mh + (size_t)p * 262144);
    const char* Ml = (const char*)(g_ml + (size_t)p * 262144);
    const char* Wh = (const char*)g_fwh;
    const char* Wl = (const char*)g_fwl;

    float acc[4][4][4];
#pragma unroll
    for (int a = 0; a < 4; a++)
#pragma unroll
        for (int b = 0; b < 4; b++)
#pragma unroll
            for (int c = 0; c < 4; c++) acc[a][b][c] = 0.f;

    auto load_stage = [&](int s) {
        uint32_t bb = sb + (s & 1) * AV_STAGE;
        const char* ah = (s < 16) ? Sh : Mh;
        const char* al = (s < 16) ? Sl : Ml;
        int kc = (s & 15) * 64;
#pragma unroll
        for (int h = 0; h < 2; h++) {
            int idx = h * 256 + t;
            int row = idx >> 2, ch = idx & 3;
            uint32_t d = bb + row * 80 + ch * 16;
            size_t off = (size_t)(q0 + row) * 1024 + kc + ch * 16;
            cp_async16(d, ah + off);
            cp_async16(d + AV_A_SZ, al + off);
        }
#pragma unroll
        for (int h = 0; h < 2; h++) {
            int idx = h * 256 + t;
            int row = idx >> 4, ch = idx & 15;
            uint32_t d = bb + AV_VH_OFF + row * 272 + ch * 16;
            size_t off = (size_t)(s * 32 + row) * 1024 + e0 * 2 + ch * 16;
            cp_async16(d, Wh + off);
            cp_async16(d + AV_V_SZ, Wl + off);
        }
    };

    load_stage(0);
    CP_COMMIT();

    for (int s = 0; s < 32; s++) {
        if (s + 1 < 32) {
            load_stage(s + 1);
            CP_COMMIT();
            CP_WAIT(1);
        } else {
            CP_WAIT(0);
        }
        __syncthreads();
        uint32_t bb = sb + (s & 1) * AV_STAGE;
#pragma unroll
        for (int kk = 0; kk < 2; kk++) {
            uint32_t aBase = bb + (wm * 64 + (lane & 15)) * 80 + (lane >> 4) * 16 + kk * 32;
            uint32_t bBase = bb + AV_VH_OFF + (kk * 16 + (lane & 15)) * 272 + wn * 64;
            uint32_t aHi[4][4], aLo[4][4];
#pragma unroll
            for (int mt = 0; mt < 4; mt++) {
                uint32_t ad = aBase + mt * 16 * 80;
                ldm_x4(aHi[mt], ad);
                ldm_x4(aLo[mt], ad + AV_A_SZ);
            }
#pragma unroll
            for (int ntl = 0; ntl < 4; ntl++) {
                uint32_t bd = bBase + ntl * 16;
                uint32_t bH[2], bL[2];
                ldm_x2t(bH, bd);
                ldm_x2t(bL, bd + AV_V_SZ);
#pragma unroll
                for (int mt = 0; mt < 4; mt++) {
                    mma_bf16(acc[mt][ntl], aHi[mt], bH);
                    mma_bf16(acc[mt][ntl], aLo[mt], bH);
                    mma_bf16(acc[mt][ntl], aHi[mt], bL);
                }
            }
        }
        __syncthreads();
    }

    // bias + relu + pool over this block's 128 rows
    float psum[4][2], pmax[4][2];
#pragma unroll
    for (int ntl = 0; ntl < 4; ntl++) {
        psum[ntl][0] = psum[ntl][1] = 0.f;
        pmax[ntl][0] = pmax[ntl][1] = 0.f;
    }
#pragma unroll
    for (int ntl = 0; ntl < 4; ntl++) {
        int c = e0 + wn * 32 + ntl * 8 + (lane & 3) * 2;
        float b0 = fb[c], b1 = fb[c + 1];
#pragma unroll
        for (int mt = 0; mt < 4; mt++) {
            float* cc = acc[mt][ntl];
            float v0 = fmaxf(cc[0] + b0, 0.f);
            float v1 = fmaxf(cc[1] + b1, 0.f);
            float v2 = fmaxf(cc[2] + b0, 0.f);
            float v3 = fmaxf(cc[3] + b1, 0.f);
            psum[ntl][0] += v0 + v2;
            psum[ntl][1] += v1 + v3;
            pmax[ntl][0] = fmaxf(pmax[ntl][0], fmaxf(v0, v2));
            pmax[ntl][1] = fmaxf(pmax[ntl][1], fmaxf(v1, v3));
        }
    }
    float* redS = (float*)(smem + FU_RED_OFF);
    float* redM = redS + 256;
#pragma unroll
    for (int ntl = 0; ntl < 4; ntl++)
#pragma unroll
        for (int j = 0; j < 2; j++) {
            float s = psum[ntl][j], m = pmax[ntl][j];
            s += __shfl_xor_sync(0xffffffffu, s, 4);
            s += __shfl_xor_sync(0xffffffffu, s, 8);
            s += __shfl_xor_sync(0xffffffffu, s, 16);
            m = fmaxf(m, __shfl_xor_sync(0xffffffffu, m, 4));
            m = fmaxf(m, __shfl_xor_sync(0xffffffffu, m, 8));
            m = fmaxf(m, __shfl_xor_sync(0xffffffffu, m, 16));
            if (lane < 4) {
                int col = wn * 32 + ntl * 8 + lane * 2 + j;
                redS[wm * 128 + col] = s;
                redM[wm * 128 + col] = m;
            }
        }
    __syncthreads();
    if (t < 128) {
        float s = redS[t] + redS[128 + t];
        float m = fmaxf(redM[t], redM[128 + t]);
        int idx = (p * 4 + qt) * 512 + e0 + t;
        g_psum[idx] = s;
        g_pmax[idx] = m;
    }
}

// ---------------- pool finalize ----------------
__global__ void k_pool(void) {
    int p = blockIdx.x, e = threadIdx.x;
    float s = 0.f, m = 0.f;
#pragma unroll
    for (int qt = 0; qt < 4; qt++) {
        int idx = (p * 4 + qt) * 512 + e;
        s += g_psum[idx];
        m = fmaxf(m, g_pmax[idx]);
    }
    int base = (p >> 2) * 4096 + (p & 3) * 512 + e;
    g_pooled[base] = s * (1.0f / 512.0f);
    g_pooled[base + 2048] = m;
}

// ---------------- out = relu(pooled @ out_w + out_b) ----------------
__global__ __launch_bounds__(256) void k_out(const float* __restrict__ ow,
                                             const float* __restrict__ ob,
                                             float* __restrict__ outp) {
    __shared__ float sp[4096];
    int b = blockIdx.x, t = threadIdx.x;
    for (int i = t; i < 4096; i += 256) sp[i] = g_pooled[b * 4096 + i];
    __syncthreads();
    int col = t * 4;
    float4 acc = *(const float4*)(ob + col);
#pragma unroll 8
    for (int c = 0; c < 4096; c++) {
        float pv = sp[c];
        float4 w = *(const float4*)(ow + (size_t)c * 1024 + col);
        acc.x += pv * w.x;
        acc.y += pv * w.y;
        acc.z += pv * w.z;
        acc.w += pv * w.w;
    }
    acc.x = fmaxf(acc.x, 0.f);
    acc.y = fmaxf(acc.y, 0.f);
    acc.z = fmaxf(acc.z, 0.f);
    acc.w = fmaxf(acc.w, 0.f);
    *(float4*)(outp + b * 1024 + col) = acc;
}

extern "C" void kernel_launch(void* const* d_in, const int* in_sizes, int n_in,
                              void* d_out, int out_size) {
    const float* x1 = (const float*)d_in[0];
    const float* x2 = (const float*)d_in[1];
    const unsigned int* x1_len = (const unsigned int*)d_in[2];
    const unsigned int* x2_len = (const unsigned int*)d_in[3];
    const float* fw = (const float*)d_in[4];
    const float* fb = (const float*)d_in[5];
    const float* ow = (const float*)d_in[6];
    const float* ob = (const float*)d_in[7];

    float* outp = (float*)d_out;
    float* attn;
    if (out_size >= OUT_ELEMS + ATTN_ELEMS) {
        attn = outp + OUT_ELEMS;
    } else if (out_size >= ATTN_ELEMS) {
        attn = outp;
        void* dp = nullptr;
        cudaGetSymbolAddress(&dp, g_out_dummy);
        outp = (float*)dp;
    } else {
        void* dp = nullptr;
        cudaGetSymbolAddress(&dp, g_attn_scratch);
        attn = (float*)dp;
    }

    void *qh, *ql, *kh, *kl, *fwh, *fwl;
    cudaGetSymbolAddress(&qh, g_qh);
    cudaGetSymbolAddress(&ql, g_ql);
    cudaGetSymbolAddress(&kh, g_kh);
    cudaGetSymbolAddress(&kl, g_kl);
    cudaGetSymbolAddress(&fwh, g_fwh);
    cudaGetSymbolAddress(&fwl, g_fwl);

    cudaFuncSetAttribute(k_scores_mma, cudaFuncAttributeMaxDynamicSharedMemorySize, SC_SMEM);
    cudaFuncSetAttribute(k_av_mma, cudaFuncAttributeMaxDynamicSharedMemorySize, AV_SMEM);
    cudaFuncSetAttribute(k_fusion_mma, cudaFuncAttributeMaxDynamicSharedMemorySize, FU_SMEM);

    k_lens<<<1, 128>>>(x1_len, x2_len);
    k_cvt<<<8192, 256>>>(x1, (__nv_bfloat16*)qh, (__nv_bfloat16*)ql, 2097152);
    k_cvt<<<32768, 256>>>(x2, (__nv_bfloat16*)kh, (__nv_bfloat16*)kl, 8388608);
    k_cvt<<<512, 256>>>(fw, (__nv_bfloat16*)fwh, (__nv_bfloat16*)fwl, 131072);
    k_scores_mma<<<dim3(4, NPAIR), 256, SC_SMEM>>>();
    k_norm<<<NPAIR * CL, 128>>>(attn);
    k_av_mma<<<dim3(4, 4, NPAIR), 256, AV_SMEM>>>(x1);
    k_fusion_mma<<<dim3(4, 4, NPAIR), 256, FU_SMEM>>>(fb);
    k_pool<<<NPAIR, 512>>>();
    k_out<<<NB, 256>>>(ow, ob, outp);
}

// round 7
// speedup vs baseline: 2.1517x; 1.0187x over previous
#include <cuda_runtime.h>
#include <cuda_bf16.h>
#include <cstdint>

#define CL 512
#define CE 512
#define NPAIR 128
#define NB 32
#define ATTN_ELEMS (NPAIR * CL * CL)
#define OUT_ELEMS (NB * 1024)
#define SCALE_F 0.044194173824159216f

// ---------------- scratch (device globals; alloc-free rule) ----------------
__device__ float g_pooled[NB * 4096];
__device__ float g_attn_scratch[ATTN_ELEMS];
__device__ float g_out_dummy[OUT_ELEMS];
__device__ float g_rowsum[NPAIR * CL];
__device__ float g_psum[4 * NPAIR * CL];
__device__ float g_pmax[4 * NPAIR * CL];
__device__ int g_qlen[32];
__device__ int g_klen[128];
__device__ __nv_bfloat16 g_qh[NB * CL * CE];
__device__ __nv_bfloat16 g_ql[NB * CL * CE];
__device__ __nv_bfloat16 g_kh[NPAIR * CL * CE];
__device__ __nv_bfloat16 g_kl[NPAIR * CL * CE];
__device__ __nv_bfloat16 g_ah[NPAIR * CL * CL];  // UNNORMALIZED exp hi
__device__ __nv_bfloat16 g_al[NPAIR * CL * CL];  // UNNORMALIZED exp lo
__device__ __nv_bfloat16 g_sh[NPAIR * CL * CE];  // x1 - xa hi
__device__ __nv_bfloat16 g_sl[NPAIR * CL * CE];
__device__ __nv_bfloat16 g_mh[NPAIR * CL * CE];  // x1 * xa hi
__device__ __nv_bfloat16 g_ml[NPAIR * CL * CE];
__device__ __nv_bfloat16 g_fwh[1024 * 512];
__device__ __nv_bfloat16 g_fwl[1024 * 512];

// ---------------- PTX helpers ----------------
__device__ __forceinline__ uint32_t smem_u32(const void* p) {
    uint32_t a;
    asm("{ .reg .u64 t; cvta.to.shared.u64 t, %1; cvt.u32.u64 %0, t; }" : "=r"(a) : "l"(p));
    return a;
}
__device__ __forceinline__ void cp_async16(uint32_t dst, const void* src) {
    asm volatile("cp.async.ca.shared.global [%0], [%1], 16;" :: "r"(dst), "l"(src));
}
#define CP_COMMIT() asm volatile("cp.async.commit_group;" ::: "memory")
#define CP_WAIT(n)  asm volatile("cp.async.wait_group %0;" :: "n"(n) : "memory")

__device__ __forceinline__ void ldm_x4(uint32_t* r, uint32_t addr) {
    asm volatile("ldmatrix.sync.aligned.m8n8.x4.shared.b16 {%0,%1,%2,%3}, [%4];"
                 : "=r"(r[0]), "=r"(r[1]), "=r"(r[2]), "=r"(r[3]) : "r"(addr));
}
__device__ __forceinline__ void ldm_x2(uint32_t* r, uint32_t addr) {
    asm volatile("ldmatrix.sync.aligned.m8n8.x2.shared.b16 {%0,%1}, [%2];"
                 : "=r"(r[0]), "=r"(r[1]) : "r"(addr));
}
__device__ __forceinline__ void ldm_x2t(uint32_t* r, uint32_t addr) {
    asm volatile("ldmatrix.sync.aligned.m8n8.x2.trans.shared.b16 {%0,%1}, [%2];"
                 : "=r"(r[0]), "=r"(r[1]) : "r"(addr));
}
__device__ __forceinline__ void mma_bf16(float* c, const uint32_t* a, const uint32_t* b) {
    asm volatile(
        "mma.sync.aligned.m16n8k16.row.col.f32.bf16.bf16.f32 "
        "{%0,%1,%2,%3}, {%4,%5,%6,%7}, {%8,%9}, {%0,%1,%2,%3};"
        : "+f"(c[0]), "+f"(c[1]), "+f"(c[2]), "+f"(c[3])
        : "r"(a[0]), "r"(a[1]), "r"(a[2]), "r"(a[3]), "r"(b[0]), "r"(b[1]));
}

// ---------------- k_scores smem geometry ----------------
#define PITCHB 80
#define TILE_B (128 * PITCHB)
#define STAGE_B (4 * TILE_B)
#define RS_OFF (2 * STAGE_B)
#define SC_SMEM (RS_OFF + 128 * 4 * 4)

// ---------------- AV / fusion smem geometry ----------------
#define AV_A_SZ (128 * 80)
#define AV_V_SZ (32 * 272)
#define AV_VH_OFF (2 * AV_A_SZ)
#define AV_STAGE (2 * AV_A_SZ + 2 * AV_V_SZ)
#define AV_SMEM (2 * AV_STAGE)
#define FU_RED_OFF AV_SMEM
#define FU_SMEM (AV_SMEM + 2048)

// ---------------- length normalization ----------------
__global__ void k_lens(const unsigned int* __restrict__ x1l,
                       const unsigned int* __restrict__ x2l) {
    __shared__ int is64;
    int t = threadIdx.x;
    if (t == 0) {
        int all0 = 1;
        for (int i = 1; i < 128; i += 2)
            if (x2l[i] != 0u) { all0 = 0; break; }
        is64 = all0;
    }
    __syncthreads();
    if (t < 32)  g_qlen[t] = (int)(is64 ? x1l[2 * t] : x1l[t]);
    if (t < 128) g_klen[t] = (int)(is64 ? x2l[2 * t] : x2l[t]);
}

// ---------------- fp32 -> bf16 hi/lo split ----------------
__global__ void k_cvt(const float* __restrict__ src, __nv_bfloat16* __restrict__ hi,
                      __nv_bfloat16* __restrict__ lo, int n4) {
    int i = blockIdx.x * blockDim.x + threadIdx.x;
    if (i >= n4) return;
    float4 v = ((const float4*)src)[i];
    __nv_bfloat16 h0 = __float2bfloat16(v.x), h1 = __float2bfloat16(v.y);
    __nv_bfloat16 h2 = __float2bfloat16(v.z), h3 = __float2bfloat16(v.w);
    __nv_bfloat16 l0 = __float2bfloat16(v.x - __bfloat162float(h0));
    __nv_bfloat16 l1 = __float2bfloat16(v.y - __bfloat162float(h1));
    __nv_bfloat16 l2 = __float2bfloat16(v.z - __bfloat162float(h2));
    __nv_bfloat16 l3 = __float2bfloat16(v.w - __bfloat162float(h3));
    __nv_bfloat162 a, b;
    a.x = h0; a.y = h1; b.x = h2; b.y = h3;
    ((__nv_bfloat162*)hi)[2 * i] = a;
    ((__nv_bfloat162*)hi)[2 * i + 1] = b;
    a.x = l0; a.y = l1; b.x = l2; b.y = l3;
    ((__nv_bfloat162*)lo)[2 * i] = a;
    ((__nv_bfloat162*)lo)[2 * i + 1] = b;
}

// ---------------- scores: Q@K^T, masked exp -> bf16 hi/lo (UNNORMALIZED) -----------
__global__ __launch_bounds__(256, 2) void k_scores_mma(void) {
    extern __shared__ char smem[];
    uint32_t sb = smem_u32(smem);
    int t = threadIdx.x, lane = t & 31, wid = t >> 5;
    int wm = wid >> 2, wn = wid & 3;
    int p = blockIdx.y, x1i = p & 31;
    int qt = blockIdx.x, q0 = qt * 128;
    int qlen = g_qlen[x1i], klen = g_klen[p];

    const char* Qh = (const char*)(g_qh + (size_t)x1i * 262144);
    const char* Ql = (const char*)(g_ql + (size_t)x1i * 262144);
    const char* Kh = (const char*)(g_kh + (size_t)p * 262144);
    const char* Kl = (const char*)(g_kl + (size_t)p * 262144);

    float acc[4][4][4];
#pragma unroll
    for (int a = 0; a < 4; a++)
#pragma unroll
        for (int b = 0; b < 4; b++)
#pragma unroll
            for (int c = 0; c < 4; c++) acc[a][b][c] = 0.f;
    float rsum[4][2];
#pragma unroll
    for (int a = 0; a < 4; a++) rsum[a][0] = rsum[a][1] = 0.f;

    auto load_stage = [&](int s) {
        int nt = s >> 4, ec = s & 15;
        uint32_t bb = sb + (s & 1) * STAGE_B;
#pragma unroll
        for (int h = 0; h < 2; h++) {
            int idx = h * 256 + t;
            int row = idx >> 2, q = (idx & 3) * 16;
            uint32_t dst = row * PITCHB + q;
            size_t asrc = (size_t)(q0 + row) * 1024 + ec * 64 + q;
            size_t bsrc = (size_t)(nt * 128 + row) * 1024 + ec * 64 + q;
            cp_async16(bb + dst, Qh + asrc);
            cp_async16(bb + TILE_B + dst, Ql + asrc);
            cp_async16(bb + 2 * TILE_B + dst, Kh + bsrc);
            cp_async16(bb + 3 * TILE_B + dst, Kl + bsrc);
        }
    };

    load_stage(0);
    CP_COMMIT();

    __nv_bfloat162* AH = (__nv_bfloat162*)(g_ah + (size_t)p * 262144);
    __nv_bfloat162* AL = (__nv_bfloat162*)(g_al + (size_t)p * 262144);

    for (int s = 0; s < 64; s++) {
        CP_WAIT(0);
        __syncthreads();
        if (s + 1 < 64) {
            load_stage(s + 1);
            CP_COMMIT();
        }
        uint32_t bb = sb + (s & 1) * STAGE_B;
#pragma unroll
        for (int kk = 0; kk < 2; kk++) {
            uint32_t aBase = bb + (wm * 64 + (lane & 15)) * PITCHB + (lane >> 4) * 16 +
                             kk * 32;
            uint32_t bBase = bb + 2 * TILE_B + (wn * 32 + (lane & 7)) * PITCHB +
                             ((lane >> 3) & 1) * 16 + kk * 32;
            uint32_t aHi[4][4], aLo[4][4];
#pragma unroll
            for (int mt = 0; mt < 4; mt++) {
                uint32_t ad = aBase + mt * 16 * PITCHB;
                ldm_x4(aHi[mt], ad);
                ldm_x4(aLo[mt], ad + TILE_B);
            }
#pragma unroll
            for (int ntl = 0; ntl < 4; ntl++) {
                uint32_t bd = bBase + ntl * 8 * PITCHB;
                uint32_t bH[2], bL[2];
                ldm_x2(bH, bd);
                ldm_x2(bL, bd + TILE_B);
#pragma unroll
                for (int mt = 0; mt < 4; mt++) {
                    mma_bf16(acc[mt][ntl], aHi[mt], bH);
                    mma_bf16(acc[mt][ntl], aLo[mt], bH);
                    mma_bf16(acc[mt][ntl], aHi[mt], bL);
                }
            }
        }
        if ((s & 15) == 15) {
            int nt = s >> 4;
            int nb = nt * 128 + wn * 32;
#pragma unroll
            for (int mt = 0; mt < 4; mt++) {
                int r0 = q0 + wm * 64 + mt * 16 + (lane >> 2);
                bool fm0 = (r0 >= qlen) || (klen == 0);
                bool fm1 = ((r0 + 8) >= qlen) || (klen == 0);
#pragma unroll
                for (int ntl = 0; ntl < 4; ntl++) {
                    int col = nb + ntl * 8 + (lane & 3) * 2;
                    float* cc = acc[mt][ntl];
                    float e0 = fm0 ? 1.f : ((col < klen) ? __expf(cc[0] * SCALE_F) : 0.f);
                    float e1 = fm0 ? 1.f : ((col + 1 < klen) ? __expf(cc[1] * SCALE_F) : 0.f);
                    float e2 = fm1 ? 1.f : ((col < klen) ? __expf(cc[2] * SCALE_F) : 0.f);
                    float e3 = fm1 ? 1.f : ((col + 1 < klen) ? __expf(cc[3] * SCALE_F) : 0.f);
                    rsum[mt][0] += e0 + e1;
                    rsum[mt][1] += e2 + e3;
                    size_t o0 = ((size_t)r0 * 512 + col) >> 1;
                    size_t o1 = ((size_t)(r0 + 8) * 512 + col) >> 1;
                    __nv_bfloat162 w;
                    __nv_bfloat16 h0 = __float2bfloat16(e0), h1 = __float2bfloat16(e1);
                    w.x = h0; w.y = h1; AH[o0] = w;
                    w.x = __float2bfloat16(e0 - __bfloat162float(h0));
                    w.y = __float2bfloat16(e1 - __bfloat162float(h1));
                    AL[o0] = w;
                    h0 = __float2bfloat16(e2); h1 = __float2bfloat16(e3);
                    w.x = h0; w.y = h1; AH[o1] = w;
                    w.x = __float2bfloat16(e2 - __bfloat162float(h0));
                    w.y = __float2bfloat16(e3 - __bfloat162float(h1));
                    AL[o1] = w;
                    cc[0] = cc[1] = cc[2] = cc[3] = 0.f;
                }
            }
        }
    }
    __syncthreads();
    float* rs = (float*)(smem + RS_OFF);
#pragma unroll
    for (int mt = 0; mt < 4; mt++)
#pragma unroll
        for (int ri = 0; ri < 2; ri++) {
            float v = rsum[mt][ri];
            v += __shfl_xor_sync(0xffffffffu, v, 1);
            v += __shfl_xor_sync(0xffffffffu, v, 2);
            if ((lane & 3) == 0)
                rs[(wm * 64 + mt * 16 + ri * 8 + (lane >> 2)) * 4 + wn] = v;
        }
    __syncthreads();
    if (t < 128) {
        float s = rs[t * 4] + rs[t * 4 + 1] + rs[t * 4 + 2] + rs[t * 4 + 3];
        g_rowsum[p * 512 + q0 + t] = s;
    }
}

// ---------------- normalize: fp32 attn output from bf16 exp + rowsum ----------------
__global__ void k_norm(float* __restrict__ attn) {
    int row = blockIdx.x;
    int t = threadIdx.x;
    float s = g_rowsum[row];
    float inv = s > 0.f ? 1.f / s : 0.f;
    const __nv_bfloat162* hp = (const __nv_bfloat162*)(g_ah + (size_t)row * 512);
    const __nv_bfloat162* lp = (const __nv_bfloat162*)(g_al + (size_t)row * 512);
    __nv_bfloat162 h0 = hp[2 * t], h1 = hp[2 * t + 1];
    __nv_bfloat162 l0 = lp[2 * t], l1 = lp[2 * t + 1];
    float4 v;
    v.x = (__bfloat162float(h0.x) + __bfloat162float(l0.x)) * inv;
    v.y = (__bfloat162float(h0.y) + __bfloat162float(l0.y)) * inv;
    v.z = (__bfloat162float(h1.x) + __bfloat162float(l1.x)) * inv;
    v.w = (__bfloat162float(h1.y) + __bfloat162float(l1.y)) * inv;
    ((float4*)(attn + (size_t)row * 512))[t] = v;
}

// ---------------- x1_att = exp @ V (scaled by 1/rowsum); epilogue emits cat bf16 ----
__global__ __launch_bounds__(256, 2) void k_av_mma(const float* __restrict__ x1) {
    extern __shared__ char smem[];
    uint32_t sb = smem_u32(smem);
    int t = threadIdx.x, lane = t & 31, wid = t >> 5;
    int wm = wid >> 2, wn = wid & 3;
    int p = blockIdx.z, x1i = p & 31;
    int q0 = blockIdx.y * 128, e0 = blockIdx.x * 128;

    const char* Ah = (const char*)(g_ah + (size_t)p * 262144);
    const char* Al = (const char*)(g_al + (size_t)p * 262144);
    const char* Vh = (const char*)(g_kh + (size_t)p * 262144);
    const char* Vl = (const char*)(g_kl + (size_t)p * 262144);

    float acc[4][4][4];
#pragma unroll
    for (int a = 0; a < 4; a++)
#pragma unroll
        for (int b = 0; b < 4; b++)
#pragma unroll
            for (int c = 0; c < 4; c++) acc[a][b][c] = 0.f;

    auto load_stage = [&](int s) {
        uint32_t bb = sb + (s & 1) * AV_STAGE;
#pragma unroll
        for (int h = 0; h < 2; h++) {
            int idx = h * 256 + t;
            int row = idx >> 2, ch = idx & 3;
            uint32_t d = bb + row * 80 + ch * 16;
            size_t off = (size_t)(q0 + row) * 1024 + s * 64 + ch * 16;
            cp_async16(d, Ah + off);
            cp_async16(d + AV_A_SZ, Al + off);
        }
#pragma unroll
        for (int h = 0; h < 2; h++) {
            int idx = h * 256 + t;
            int row = idx >> 4, ch = idx & 15;
            uint32_t d = bb + AV_VH_OFF + row * 272 + ch * 16;
            size_t off = (size_t)(s * 32 + row) * 1024 + e0 * 2 + ch * 16;
            cp_async16(d, Vh + off);
            cp_async16(d + AV_V_SZ, Vl + off);
        }
    };

    load_stage(0);
    CP_COMMIT();

    for (int s = 0; s < 16; s++) {
        CP_WAIT(0);
        __syncthreads();
        if (s + 1 < 16) {
            load_stage(s + 1);
            CP_COMMIT();
        }
        uint32_t bb = sb + (s & 1) * AV_STAGE;
#pragma unroll
        for (int kk = 0; kk < 2; kk++) {
            uint32_t aBase = bb + (wm * 64 + (lane & 15)) * 80 + (lane >> 4) * 16 + kk * 32;
            uint32_t bBase = bb + AV_VH_OFF + (kk * 16 + (lane & 15)) * 272 + wn * 64;
            uint32_t aHi[4][4], aLo[4][4];
#pragma unroll
            for (int mt = 0; mt < 4; mt++) {
                uint32_t ad = aBase + mt * 16 * 80;
                ldm_x4(aHi[mt], ad);
                ldm_x4(aLo[mt], ad + AV_A_SZ);
            }
#pragma unroll
            for (int ntl = 0; ntl < 4; ntl++) {
                uint32_t bd = bBase + ntl * 16;
                uint32_t bH[2], bL[2];
                ldm_x2t(bH, bd);
                ldm_x2t(bL, bd + AV_V_SZ);
#pragma unroll
                for (int mt = 0; mt < 4; mt++) {
                    mma_bf16(acc[mt][ntl], aHi[mt], bH);
                    mma_bf16(acc[mt][ntl], aLo[mt], bH);
                    mma_bf16(acc[mt][ntl], aHi[mt], bL);
                }
            }
        }
        __syncthreads();
    }

    // epilogue: xa = acc/rowsum -> (x1 - xa, x1 * xa) bf16 hi/lo
    const float* X1 = x1 + (size_t)x1i * 262144;
    __nv_bfloat162* Sh = (__nv_bfloat162*)(g_sh + (size_t)p * 262144);
    __nv_bfloat162* Sl = (__nv_bfloat162*)(g_sl + (size_t)p * 262144);
    __nv_bfloat162* Mh = (__nv_bfloat162*)(g_mh + (size_t)p * 262144);
    __nv_bfloat162* Ml = (__nv_bfloat162*)(g_ml + (size_t)p * 262144);
#pragma unroll
    for (int mt = 0; mt < 4; mt++) {
#pragma unroll
        for (int hh = 0; hh < 2; hh++) {
            int r = q0 + wm * 64 + mt * 16 + (lane >> 2) + hh * 8;
            float sr = g_rowsum[p * 512 + r];
            float inv = 1.f / sr;
#pragma unroll
            for (int ntl = 0; ntl < 4; ntl++) {
                float* cc = acc[mt][ntl];
                int c = e0 + wn * 32 + ntl * 8 + (lane & 3) * 2;
                float2 u = *(const float2*)(X1 + (size_t)r * 512 + c);
                float xa0 = cc[hh * 2] * inv, xa1 = cc[hh * 2 + 1] * inv;
                float s0 = u.x - xa0, s1 = u.y - xa1;
                float m0 = u.x * xa0, m1 = u.y * xa1;
                size_t o = ((size_t)r * 512 + c) >> 1;
                __nv_bfloat162 w;
                __nv_bfloat16 h0 = __float2bfloat16(s0), h1 = __float2bfloat16(s1);
                w.x = h0; w.y = h1; Sh[o] = w;
                w.x = __float2bfloat16(s0 - __bfloat162float(h0));
                w.y = __float2bfloat16(s1 - __bfloat162float(h1));
                Sl[o] = w;
                h0 = __float2bfloat16(m0); h1 = __float2bfloat16(m1);
                w.x = h0; w.y = h1; Mh[o] = w;
                w.x = __float2bfloat16(m0 - __bfloat162float(h0));
                w.y = __float2bfloat16(m1 - __bfloat162float(h1));
                Ml[o] = w;
            }
        }
    }
}

// ---------------- fusion GEMM via mma.sync + bias/relu + partial pooling ----------
__global__ __launch_bounds__(256, 2) void k_fusion_mma(const float* __restrict__ fb) {
    extern __shared__ char smem[];
    uint32_t sb = smem_u32(smem);
    int t = threadIdx.x, lane = t & 31, wid = t >> 5;
    int wm = wid >> 2, wn = wid & 3;
    int p = blockIdx.z;
    int qt = blockIdx.y, q0 = qt * 128, e0 = blockIdx.x * 128;

    const char* Sh = (const char*)(g_sh + (size_t)p * 262144);
    const char* Sl = (const char*)(g_sl + (size_t)p * 262144);
    const char* Mh = (const char*)(g_mh + (size_t)p * 262144);
    const char* Ml = (const char*)(g_ml + (size_t)p * 262144);
    const char* Wh = (const char*)g_fwh;
    const char* Wl = (const char*)g_fwl;

    float acc[4][4][4];
#pragma unroll
    for (int a = 0; a < 4; a++)
#pragma unroll
        for (int b = 0; b < 4; b++)
#pragma unroll
            for (int c = 0; c < 4; c++) acc[a][b][c] = 0.f;

    auto load_stage = [&](int s) {
        uint32_t bb = sb + (s & 1) * AV_STAGE;
        const char* ah = (s < 16) ? Sh : Mh;
        const char* al = (s < 16) ? Sl : Ml;
        int kc = (s & 15) * 64;
#pragma unroll
        for (int h = 0; h < 2; h++) {
            int idx = h * 256 + t;
            int row = idx >> 2, ch = idx & 3;
            uint32_t d = bb + row * 80 + ch * 16;
            size_t off = (size_t)(q0 + row) * 1024 + kc + ch * 16;
            cp_async16(d, ah + off);
            cp_async16(d + AV_A_SZ, al + off);
        }
#pragma unroll
        for (int h = 0; h < 2; h++) {
            int idx = h * 256 + t;
            int row = idx >> 4, ch = idx & 15;
            uint32_t d = bb + AV_VH_OFF + row * 272 + ch * 16;
            size_t off = (size_t)(s * 32 + row) * 1024 + e0 * 2 + ch * 16;
            cp_async16(d, Wh + off);
            cp_async16(d + AV_V_SZ, Wl + off);
        }
    };

    load_stage(0);
    CP_COMMIT();

    for (int s = 0; s < 32; s++) {
        CP_WAIT(0);
        __syncthreads();
        if (s + 1 < 32) {
            load_stage(s + 1);
            CP_COMMIT();
        }
        uint32_t bb = sb + (s & 1) * AV_STAGE;
#pragma unroll
        for (int kk = 0; kk < 2; kk++) {
            uint32_t aBase = bb + (wm * 64 + (lane & 15)) * 80 + (lane >> 4) * 16 + kk * 32;
            uint32_t bBase = bb + AV_VH_OFF + (kk * 16 + (lane & 15)) * 272 + wn * 64;
            uint32_t aHi[4][4], aLo[4][4];
#pragma unroll
            for (int mt = 0; mt < 4; mt++) {
                uint32_t ad = aBase + mt * 16 * 80;
                ldm_x4(aHi[mt], ad);
                ldm_x4(aLo[mt], ad + AV_A_SZ);
            }
#pragma unroll
            for (int ntl = 0; ntl < 4; ntl++) {
                uint32_t bd = bBase + ntl * 16;
                uint32_t bH[2], bL[2];
                ldm_x2t(bH, bd);
                ldm_x2t(bL, bd + AV_V_SZ);
#pragma unroll
                for (int mt = 0; mt < 4; mt++) {
                    mma_bf16(acc[mt][ntl], aHi[mt], bH);
                    mma_bf16(acc[mt][ntl], aLo[mt], bH);
                    mma_bf16(acc[mt][ntl], aHi[mt], bL);
                }
            }
        }
    }

    // bias + relu + pool over this block's 128 rows
    float psum[4][2], pmax[4][2];
#pragma unroll
    for (int ntl = 0; ntl < 4; ntl++) {
        psum[ntl][0] = psum[ntl][1] = 0.f;
        pmax[ntl][0] = pmax[ntl][1] = 0.f;
    }
#pragma unroll
    for (int ntl = 0; ntl < 4; ntl++) {
        int c = e0 + wn * 32 + ntl * 8 + (lane & 3) * 2;
        float b0 = fb[c], b1 = fb[c + 1];
#pragma unroll
        for (int mt = 0; mt < 4; mt++) {
            float* cc = acc[mt][ntl];
            float v0 = fmaxf(cc[0] + b0, 0.f);
            float v1 = fmaxf(cc[1] + b1, 0.f);
            float v2 = fmaxf(cc[2] + b0, 0.f);
            float v3 = fmaxf(cc[3] + b1, 0.f);
            psum[ntl][0] += v0 + v2;
            psum[ntl][1] += v1 + v3;
            pmax[ntl][0] = fmaxf(pmax[ntl][0], fmaxf(v0, v2));
            pmax[ntl][1] = fmaxf(pmax[ntl][1], fmaxf(v1, v3));
        }
    }
    __syncthreads();
    float* redS = (float*)(smem + FU_RED_OFF);
    float* redM = redS + 256;
#pragma unroll
    for (int ntl = 0; ntl < 4; ntl++)
#pragma unroll
        for (int j = 0; j < 2; j++) {
            float s = psum[ntl][j], m = pmax[ntl][j];
            s += __shfl_xor_sync(0xffffffffu, s, 4);
            s += __shfl_xor_sync(0xffffffffu, s, 8);
            s += __shfl_xor_sync(0xffffffffu, s, 16);
            m = fmaxf(m, __shfl_xor_sync(0xffffffffu, m, 4));
            m = fmaxf(m, __shfl_xor_sync(0xffffffffu, m, 8));
            m = fmaxf(m, __shfl_xor_sync(0xffffffffu, m, 16));
            if (lane < 4) {
                int col = wn * 32 + ntl * 8 + lane * 2 + j;
                redS[wm * 128 + col] = s;
                redM[wm * 128 + col] = m;
            }
        }
    __syncthreads();
    if (t < 128) {
        float s = redS[t] + redS[128 + t];
        float m = fmaxf(redM[t], redM[128 + t]);
        int idx = (p * 4 + qt) * 512 + e0 + t;
        g_psum[idx] = s;
        g_pmax[idx] = m;
    }
}

// ---------------- pool finalize ----------------
__global__ void k_pool(void) {
    int p = blockIdx.x, e = threadIdx.x;
    float s = 0.f, m = 0.f;
#pragma unroll
    for (int qt = 0; qt < 4; qt++) {
        int idx = (p * 4 + qt) * 512 + e;
        s += g_psum[idx];
        m = fmaxf(m, g_pmax[idx]);
    }
    int base = (p >> 2) * 4096 + (p & 3) * 512 + e;
    g_pooled[base] = s * (1.0f / 512.0f);
    g_pooled[base + 2048] = m;
}

// ---------------- out = relu(pooled @ out_w + out_b) ----------------
__global__ __launch_bounds__(256) void k_out(const float* __restrict__ ow,
                                             const float* __restrict__ ob,
                                             float* __restrict__ outp) {
    __shared__ float sp[4096];
    int b = blockIdx.x, t = threadIdx.x;
    for (int i = t; i < 4096; i += 256) sp[i] = g_pooled[b * 4096 + i];
    __syncthreads();
    int col = t * 4;
    float4 acc = *(const float4*)(ob + col);
#pragma unroll 8
    for (int c = 0; c < 4096; c++) {
        float pv = sp[c];
        float4 w = *(const float4*)(ow + (size_t)c * 1024 + col);
        acc.x += pv * w.x;
        acc.y += pv * w.y;
        acc.z += pv * w.z;
        acc.w += pv * w.w;
    }
    acc.x = fmaxf(acc.x, 0.f);
    acc.y = fmaxf(acc.y, 0.f);
    acc.z = fmaxf(acc.z, 0.f);
    acc.w = fmaxf(acc.w, 0.f);
    *(float4*)(outp + b * 1024 + col) = acc;
}

extern "C" void kernel_launch(void* const* d_in, const int* in_sizes, int n_in,
                              void* d_out, int out_size) {
    const float* x1 = (const float*)d_in[0];
    const float* x2 = (const float*)d_in[1];
    const unsigned int* x1_len = (const unsigned int*)d_in[2];
    const unsigned int* x2_len = (const unsigned int*)d_in[3];
    const float* fw = (const float*)d_in[4];
    const float* fb = (const float*)d_in[5];
    const float* ow = (const float*)d_in[6];
    const float* ob = (const float*)d_in[7];

    float* outp = (float*)d_out;
    float* attn;
    if (out_size >= OUT_ELEMS + ATTN_ELEMS) {
        attn = outp + OUT_ELEMS;
    } else if (out_size >= ATTN_ELEMS) {
        attn = outp;
        void* dp = nullptr;
        cudaGetSymbolAddress(&dp, g_out_dummy);
        outp = (float*)dp;
    } else {
        void* dp = nullptr;
        cudaGetSymbolAddress(&dp, g_attn_scratch);
        attn = (float*)dp;
    }

    void *qh, *ql, *kh, *kl, *fwh, *fwl;
    cudaGetSymbolAddress(&qh, g_qh);
    cudaGetSymbolAddress(&ql, g_ql);
    cudaGetSymbolAddress(&kh, g_kh);
    cudaGetSymbolAddress(&kl, g_kl);
    cudaGetSymbolAddress(&fwh, g_fwh);
    cudaGetSymbolAddress(&fwl, g_fwl);

    cudaFuncSetAttribute(k_scores_mma, cudaFuncAttributeMaxDynamicSharedMemorySize, SC_SMEM);
    cudaFuncSetAttribute(k_av_mma, cudaFuncAttributeMaxDynamicSharedMemorySize, AV_SMEM);
    cudaFuncSetAttribute(k_fusion_mma, cudaFuncAttributeMaxDynamicSharedMemorySize, FU_SMEM);

    k_lens<<<1, 128>>>(x1_len, x2_len);
    k_cvt<<<8192, 256>>>(x1, (__nv_bfloat16*)qh, (__nv_bfloat16*)ql, 2097152);
    k_cvt<<<32768, 256>>>(x2, (__nv_bfloat16*)kh, (__nv_bfloat16*)kl, 8388608);
    k_cvt<<<512, 256>>>(fw, (__nv_bfloat16*)fwh, (__nv_bfloat16*)fwl, 131072);
    k_scores_mma<<<dim3(4, NPAIR), 256, SC_SMEM>>>();
    k_norm<<<NPAIR * CL, 128>>>(attn);
    k_av_mma<<<dim3(4, 4, NPAIR), 256, AV_SMEM>>>(x1);
    k_fusion_mma<<<dim3(4, 4, NPAIR), 256, FU_SMEM>>>(fb);
    k_pool<<<NPAIR, 512>>>();
    k_out<<<NB, 256>>>(ow, ob, outp);
}

// round 8
// speedup vs baseline: 2.2236x; 1.0334x over previous
#include <cuda_runtime.h>
#include <cuda_bf16.h>
#include <cstdint>

#define CL 512
#define CE 512
#define NPAIR 128
#define NB 32
#define ATTN_ELEMS (NPAIR * CL * CL)
#define OUT_ELEMS (NB * 1024)
#define SCALE_F 0.044194173824159216f

// ---------------- scratch (device globals; alloc-free rule) ----------------
__device__ float g_pooled[NB * 4096];
__device__ float g_attn_scratch[ATTN_ELEMS];
__device__ float g_out_dummy[OUT_ELEMS];
__device__ float g_rowsum[NPAIR * CL];
__device__ float g_psum[4 * NPAIR * CL];
__device__ float g_pmax[4 * NPAIR * CL];
__device__ int g_qlen[32];
__device__ int g_klen[128];
__device__ __nv_bfloat16 g_qh[NB * CL * CE];
__device__ __nv_bfloat16 g_ql[NB * CL * CE];
__device__ __nv_bfloat16 g_kh[NPAIR * CL * CE];
__device__ __nv_bfloat16 g_kl[NPAIR * CL * CE];
__device__ __nv_bfloat16 g_ah[NPAIR * CL * CL];  // UNNORMALIZED exp hi
__device__ __nv_bfloat16 g_al[NPAIR * CL * CL];  // UNNORMALIZED exp lo
__device__ __nv_bfloat16 g_sh[NPAIR * CL * CE];  // x1 - xa hi
__device__ __nv_bfloat16 g_sl[NPAIR * CL * CE];
__device__ __nv_bfloat16 g_mh[NPAIR * CL * CE];  // x1 * xa hi
__device__ __nv_bfloat16 g_ml[NPAIR * CL * CE];
__device__ __nv_bfloat16 g_fwh[1024 * 512];
__device__ __nv_bfloat16 g_fwl[1024 * 512];

// ---------------- PTX helpers ----------------
__device__ __forceinline__ uint32_t smem_u32(const void* p) {
    uint32_t a;
    asm("{ .reg .u64 t; cvta.to.shared.u64 t, %1; cvt.u32.u64 %0, t; }" : "=r"(a) : "l"(p));
    return a;
}
__device__ __forceinline__ void cp_async16(uint32_t dst, const void* src) {
    asm volatile("cp.async.ca.shared.global [%0], [%1], 16;" :: "r"(dst), "l"(src));
}
#define CP_COMMIT() asm volatile("cp.async.commit_group;" ::: "memory")
#define CP_WAIT(n)  asm volatile("cp.async.wait_group %0;" :: "n"(n) : "memory")

__device__ __forceinline__ void ldm_x4(uint32_t* r, uint32_t addr) {
    asm volatile("ldmatrix.sync.aligned.m8n8.x4.shared.b16 {%0,%1,%2,%3}, [%4];"
                 : "=r"(r[0]), "=r"(r[1]), "=r"(r[2]), "=r"(r[3]) : "r"(addr));
}
__device__ __forceinline__ void ldm_x4t(uint32_t* r, uint32_t addr) {
    asm volatile("ldmatrix.sync.aligned.m8n8.x4.trans.shared.b16 {%0,%1,%2,%3}, [%4];"
                 : "=r"(r[0]), "=r"(r[1]), "=r"(r[2]), "=r"(r[3]) : "r"(addr));
}
__device__ __forceinline__ void mma_bf16(float* c, const uint32_t* a, const uint32_t* b) {
    asm volatile(
        "mma.sync.aligned.m16n8k16.row.col.f32.bf16.bf16.f32 "
        "{%0,%1,%2,%3}, {%4,%5,%6,%7}, {%8,%9}, {%0,%1,%2,%3};"
        : "+f"(c[0]), "+f"(c[1]), "+f"(c[2]), "+f"(c[3])
        : "r"(a[0]), "r"(a[1]), "r"(a[2]), "r"(a[3]), "r"(b[0]), "r"(b[1]));
}

// ---------------- k_scores smem geometry ----------------
#define PITCHB 80
#define TILE_B (128 * PITCHB)
#define STAGE_B (4 * TILE_B)
#define RS_OFF (2 * STAGE_B)
#define SC_SMEM (RS_OFF + 128 * 4 * 4)

// ---------------- AV / fusion smem geometry ----------------
#define AV_A_SZ (128 * 80)
#define AV_V_SZ (32 * 272)
#define AV_VH_OFF (2 * AV_A_SZ)
#define AV_STAGE (2 * AV_A_SZ + 2 * AV_V_SZ)
#define AV_SMEM (2 * AV_STAGE)
#define FU_RED_OFF AV_SMEM
#define FU_SMEM (AV_SMEM + 2048)

// ---------------- length normalization ----------------
__global__ void k_lens(const unsigned int* __restrict__ x1l,
                       const unsigned int* __restrict__ x2l) {
    __shared__ int is64;
    int t = threadIdx.x;
    if (t == 0) {
        int all0 = 1;
        for (int i = 1; i < 128; i += 2)
            if (x2l[i] != 0u) { all0 = 0; break; }
        is64 = all0;
    }
    __syncthreads();
    if (t < 32)  g_qlen[t] = (int)(is64 ? x1l[2 * t] : x1l[t]);
    if (t < 128) g_klen[t] = (int)(is64 ? x2l[2 * t] : x2l[t]);
}

// ---------------- fp32 -> bf16 hi/lo split ----------------
__global__ void k_cvt(const float* __restrict__ src, __nv_bfloat16* __restrict__ hi,
                      __nv_bfloat16* __restrict__ lo, int n4) {
    int i = blockIdx.x * blockDim.x + threadIdx.x;
    if (i >= n4) return;
    float4 v = ((const float4*)src)[i];
    __nv_bfloat16 h0 = __float2bfloat16(v.x), h1 = __float2bfloat16(v.y);
    __nv_bfloat16 h2 = __float2bfloat16(v.z), h3 = __float2bfloat16(v.w);
    __nv_bfloat16 l0 = __float2bfloat16(v.x - __bfloat162float(h0));
    __nv_bfloat16 l1 = __float2bfloat16(v.y - __bfloat162float(h1));
    __nv_bfloat16 l2 = __float2bfloat16(v.z - __bfloat162float(h2));
    __nv_bfloat16 l3 = __float2bfloat16(v.w - __bfloat162float(h3));
    __nv_bfloat162 a, b;
    a.x = h0; a.y = h1; b.x = h2; b.y = h3;
    ((__nv_bfloat162*)hi)[2 * i] = a;
    ((__nv_bfloat162*)hi)[2 * i + 1] = b;
    a.x = l0; a.y = l1; b.x = l2; b.y = l3;
    ((__nv_bfloat162*)lo)[2 * i] = a;
    ((__nv_bfloat162*)lo)[2 * i + 1] = b;
}

// ---------------- scores: Q@K^T, masked exp -> bf16 hi/lo (UNNORMALIZED) -----------
__global__ __launch_bounds__(256, 2) void k_scores_mma(void) {
    extern __shared__ char smem[];
    uint32_t sb = smem_u32(smem);
    int t = threadIdx.x, lane = t & 31, wid = t >> 5;
    int wm = wid >> 2, wn = wid & 3;
    int p = blockIdx.y, x1i = p & 31;
    int qt = blockIdx.x, q0 = qt * 128;
    int qlen = g_qlen[x1i], klen = g_klen[p];

    const char* Qh = (const char*)(g_qh + (size_t)x1i * 262144);
    const char* Ql = (const char*)(g_ql + (size_t)x1i * 262144);
    const char* Kh = (const char*)(g_kh + (size_t)p * 262144);
    const char* Kl = (const char*)(g_kl + (size_t)p * 262144);

    float acc[4][4][4];
#pragma unroll
    for (int a = 0; a < 4; a++)
#pragma unroll
        for (int b = 0; b < 4; b++)
#pragma unroll
            for (int c = 0; c < 4; c++) acc[a][b][c] = 0.f;
    float rsum[4][2];
#pragma unroll
    for (int a = 0; a < 4; a++) rsum[a][0] = rsum[a][1] = 0.f;

    auto load_stage = [&](int s) {
        int nt = s >> 4, ec = s & 15;
        uint32_t bb = sb + (s & 1) * STAGE_B;
#pragma unroll
        for (int h = 0; h < 2; h++) {
            int idx = h * 256 + t;
            int row = idx >> 2, q = (idx & 3) * 16;
            uint32_t dst = row * PITCHB + q;
            size_t asrc = (size_t)(q0 + row) * 1024 + ec * 64 + q;
            size_t bsrc = (size_t)(nt * 128 + row) * 1024 + ec * 64 + q;
            cp_async16(bb + dst, Qh + asrc);
            cp_async16(bb + TILE_B + dst, Ql + asrc);
            cp_async16(bb + 2 * TILE_B + dst, Kh + bsrc);
            cp_async16(bb + 3 * TILE_B + dst, Kl + bsrc);
        }
    };

    load_stage(0);
    CP_COMMIT();

    __nv_bfloat162* AH = (__nv_bfloat162*)(g_ah + (size_t)p * 262144);
    __nv_bfloat162* AL = (__nv_bfloat162*)(g_al + (size_t)p * 262144);

    for (int s = 0; s < 64; s++) {
        CP_WAIT(0);
        __syncthreads();
        if (s + 1 < 64) {
            load_stage(s + 1);
            CP_COMMIT();
        }
        uint32_t bb = sb + (s & 1) * STAGE_B;
#pragma unroll
        for (int kk = 0; kk < 2; kk++) {
            uint32_t aBase = bb + (wm * 64 + (lane & 15)) * PITCHB + (lane >> 4) * 16 +
                             kk * 32;
            uint32_t aHi[4][4], aLo[4][4];
#pragma unroll
            for (int mt = 0; mt < 4; mt++) {
                uint32_t ad = aBase + mt * 16 * PITCHB;
                ldm_x4(aHi[mt], ad);
                ldm_x4(aLo[mt], ad + TILE_B);
            }
            // B x4: rows = wn*32 + pair*16 + ((lane>>4)&1)*8 + (lane&7); koff=((lane>>3)&1)*16
            uint32_t bBase = bb + 2 * TILE_B +
                             (wn * 32 + ((lane >> 4) & 1) * 8 + (lane & 7)) * PITCHB +
                             ((lane >> 3) & 1) * 16 + kk * 32;
#pragma unroll
            for (int pr = 0; pr < 2; pr++) {
                uint32_t bH[4], bL[4];
                uint32_t bd = bBase + pr * 16 * PITCHB;
                ldm_x4(bH, bd);
                ldm_x4(bL, bd + TILE_B);
                // term-major: same-acc distance = 8
#pragma unroll
                for (int mt = 0; mt < 4; mt++)
#pragma unroll
                    for (int n2 = 0; n2 < 2; n2++)
                        mma_bf16(acc[mt][pr * 2 + n2], aHi[mt], bH + 2 * n2);
#pragma unroll
                for (int mt = 0; mt < 4; mt++)
#pragma unroll
                    for (int n2 = 0; n2 < 2; n2++)
                        mma_bf16(acc[mt][pr * 2 + n2], aLo[mt], bH + 2 * n2);
#pragma unroll
                for (int mt = 0; mt < 4; mt++)
#pragma unroll
                    for (int n2 = 0; n2 < 2; n2++)
                        mma_bf16(acc[mt][pr * 2 + n2], aHi[mt], bL + 2 * n2);
            }
        }
        if ((s & 15) == 15) {
            int nt = s >> 4;
            int nb = nt * 128 + wn * 32;
#pragma unroll
            for (int mt = 0; mt < 4; mt++) {
                int r0 = q0 + wm * 64 + mt * 16 + (lane >> 2);
                bool fm0 = (r0 >= qlen) || (klen == 0);
                bool fm1 = ((r0 + 8) >= qlen) || (klen == 0);
#pragma unroll
                for (int ntl = 0; ntl < 4; ntl++) {
                    int col = nb + ntl * 8 + (lane & 3) * 2;
                    float* cc = acc[mt][ntl];
                    float e0 = fm0 ? 1.f : ((col < klen) ? __expf(cc[0] * SCALE_F) : 0.f);
                    float e1 = fm0 ? 1.f : ((col + 1 < klen) ? __expf(cc[1] * SCALE_F) : 0.f);
                    float e2 = fm1 ? 1.f : ((col < klen) ? __expf(cc[2] * SCALE_F) : 0.f);
                    float e3 = fm1 ? 1.f : ((col + 1 < klen) ? __expf(cc[3] * SCALE_F) : 0.f);
                    rsum[mt][0] += e0 + e1;
                    rsum[mt][1] += e2 + e3;
                    size_t o0 = ((size_t)r0 * 512 + col) >> 1;
                    size_t o1 = ((size_t)(r0 + 8) * 512 + col) >> 1;
                    __nv_bfloat162 w;
                    __nv_bfloat16 h0 = __float2bfloat16(e0), h1 = __float2bfloat16(e1);
                    w.x = h0; w.y = h1; AH[o0] = w;
                    w.x = __float2bfloat16(e0 - __bfloat162float(h0));
                    w.y = __float2bfloat16(e1 - __bfloat162float(h1));
                    AL[o0] = w;
                    h0 = __float2bfloat16(e2); h1 = __float2bfloat16(e3);
                    w.x = h0; w.y = h1; AH[o1] = w;
                    w.x = __float2bfloat16(e2 - __bfloat162float(h0));
                    w.y = __float2bfloat16(e3 - __bfloat162float(h1));
                    AL[o1] = w;
                    cc[0] = cc[1] = cc[2] = cc[3] = 0.f;
                }
            }
        }
    }
    __syncthreads();
    float* rs = (float*)(smem + RS_OFF);
#pragma unroll
    for (int mt = 0; mt < 4; mt++)
#pragma unroll
        for (int ri = 0; ri < 2; ri++) {
            float v = rsum[mt][ri];
            v += __shfl_xor_sync(0xffffffffu, v, 1);
            v += __shfl_xor_sync(0xffffffffu, v, 2);
            if ((lane & 3) == 0)
                rs[(wm * 64 + mt * 16 + ri * 8 + (lane >> 2)) * 4 + wn] = v;
        }
    __syncthreads();
    if (t < 128) {
        float s = rs[t * 4] + rs[t * 4 + 1] + rs[t * 4 + 2] + rs[t * 4 + 3];
        g_rowsum[p * 512 + q0 + t] = s;
    }
}

// ---------------- normalize: fp32 attn output from bf16 exp + rowsum ----------------
__global__ void k_norm(float* __restrict__ attn) {
    int row = blockIdx.x;
    int t = threadIdx.x;
    float s = g_rowsum[row];
    float inv = s > 0.f ? 1.f / s : 0.f;
    const __nv_bfloat162* hp = (const __nv_bfloat162*)(g_ah + (size_t)row * 512);
    const __nv_bfloat162* lp = (const __nv_bfloat162*)(g_al + (size_t)row * 512);
    __nv_bfloat162 h0 = hp[2 * t], h1 = hp[2 * t + 1];
    __nv_bfloat162 l0 = lp[2 * t], l1 = lp[2 * t + 1];
    float4 v;
    v.x = (__bfloat162float(h0.x) + __bfloat162float(l0.x)) * inv;
    v.y = (__bfloat162float(h0.y) + __bfloat162float(l0.y)) * inv;
    v.z = (__bfloat162float(h1.x) + __bfloat162float(l1.x)) * inv;
    v.w = (__bfloat162float(h1.y) + __bfloat162float(l1.y)) * inv;
    ((float4*)(attn + (size_t)row * 512))[t] = v;
}

// ---------------- x1_att = exp @ V (scaled by 1/rowsum); epilogue emits cat bf16 ----
__global__ __launch_bounds__(256, 2) void k_av_mma(const float* __restrict__ x1) {
    extern __shared__ char smem[];
    uint32_t sb = smem_u32(smem);
    int t = threadIdx.x, lane = t & 31, wid = t >> 5;
    int wm = wid >> 2, wn = wid & 3;
    int p = blockIdx.z, x1i = p & 31;
    int q0 = blockIdx.y * 128, e0 = blockIdx.x * 128;

    const char* Ah = (const char*)(g_ah + (size_t)p * 262144);
    const char* Al = (const char*)(g_al + (size_t)p * 262144);
    const char* Vh = (const char*)(g_kh + (size_t)p * 262144);
    const char* Vl = (const char*)(g_kl + (size_t)p * 262144);

    float acc[4][4][4];
#pragma unroll
    for (int a = 0; a < 4; a++)
#pragma unroll
        for (int b = 0; b < 4; b++)
#pragma unroll
            for (int c = 0; c < 4; c++) acc[a][b][c] = 0.f;

    auto load_stage = [&](int s) {
        uint32_t bb = sb + (s & 1) * AV_STAGE;
#pragma unroll
        for (int h = 0; h < 2; h++) {
            int idx = h * 256 + t;
            int row = idx >> 2, ch = idx & 3;
            uint32_t d = bb + row * 80 + ch * 16;
            size_t off = (size_t)(q0 + row) * 1024 + s * 64 + ch * 16;
            cp_async16(d, Ah + off);
            cp_async16(d + AV_A_SZ, Al + off);
        }
#pragma unroll
        for (int h = 0; h < 2; h++) {
            int idx = h * 256 + t;
            int row = idx >> 4, ch = idx & 15;
            uint32_t d = bb + AV_VH_OFF + row * 272 + ch * 16;
            size_t off = (size_t)(s * 32 + row) * 1024 + e0 * 2 + ch * 16;
            cp_async16(d, Vh + off);
            cp_async16(d + AV_V_SZ, Vl + off);
        }
    };

    load_stage(0);
    CP_COMMIT();

    for (int s = 0; s < 16; s++) {
        CP_WAIT(0);
        __syncthreads();
        if (s + 1 < 16) {
            load_stage(s + 1);
            CP_COMMIT();
        }
        uint32_t bb = sb + (s & 1) * AV_STAGE;
#pragma unroll
        for (int kk = 0; kk < 2; kk++) {
            uint32_t aBase = bb + (wm * 64 + (lane & 15)) * 80 + (lane >> 4) * 16 + kk * 32;
            uint32_t aHi[4][4], aLo[4][4];
#pragma unroll
            for (int mt = 0; mt < 4; mt++) {
                uint32_t ad = aBase + mt * 16 * 80;
                ldm_x4(aHi[mt], ad);
                ldm_x4(aLo[mt], ad + AV_A_SZ);
            }
            // trans B x4: lanes 0-15 -> k rows, lanes 16-31 -> +16B col
            uint32_t bBase = bb + AV_VH_OFF + (kk * 16 + (lane & 15)) * 272 + wn * 64 +
                             ((lane >> 4) & 1) * 16;
#pragma unroll
            for (int pr = 0; pr < 2; pr++) {
                uint32_t bH[4], bL[4];
                uint32_t bd = bBase + pr * 32;
                ldm_x4t(bH, bd);
                ldm_x4t(bL, bd + AV_V_SZ);
#pragma unroll
                for (int mt = 0; mt < 4; mt++)
#pragma unroll
                    for (int n2 = 0; n2 < 2; n2++)
                        mma_bf16(acc[mt][pr * 2 + n2], aHi[mt], bH + 2 * n2);
#pragma unroll
                for (int mt = 0; mt < 4; mt++)
#pragma unroll
                    for (int n2 = 0; n2 < 2; n2++)
                        mma_bf16(acc[mt][pr * 2 + n2], aLo[mt], bH + 2 * n2);
#pragma unroll
                for (int mt = 0; mt < 4; mt++)
#pragma unroll
                    for (int n2 = 0; n2 < 2; n2++)
                        mma_bf16(acc[mt][pr * 2 + n2], aHi[mt], bL + 2 * n2);
            }
        }
    }

    // epilogue: xa = acc/rowsum -> (x1 - xa, x1 * xa) bf16 hi/lo
    const float* X1 = x1 + (size_t)x1i * 262144;
    __nv_bfloat162* Sh = (__nv_bfloat162*)(g_sh + (size_t)p * 262144);
    __nv_bfloat162* Sl = (__nv_bfloat162*)(g_sl + (size_t)p * 262144);
    __nv_bfloat162* Mh = (__nv_bfloat162*)(g_mh + (size_t)p * 262144);
    __nv_bfloat162* Ml = (__nv_bfloat162*)(g_ml + (size_t)p * 262144);
#pragma unroll
    for (int mt = 0; mt < 4; mt++) {
#pragma unroll
        for (int hh = 0; hh < 2; hh++) {
            int r = q0 + wm * 64 + mt * 16 + (lane >> 2) + hh * 8;
            float sr = g_rowsum[p * 512 + r];
            float inv = 1.f / sr;
#pragma unroll
            for (int ntl = 0; ntl < 4; ntl++) {
                float* cc = acc[mt][ntl];
                int c = e0 + wn * 32 + ntl * 8 + (lane & 3) * 2;
                float2 u = *(const float2*)(X1 + (size_t)r * 512 + c);
                float xa0 = cc[hh * 2] * inv, xa1 = cc[hh * 2 + 1] * inv;
                float s0 = u.x - xa0, s1 = u.y - xa1;
                float m0 = u.x * xa0, m1 = u.y * xa1;
                size_t o = ((size_t)r * 512 + c) >> 1;
                __nv_bfloat162 w;
                __nv_bfloat16 h0 = __float2bfloat16(s0), h1 = __float2bfloat16(s1);
                w.x = h0; w.y = h1; Sh[o] = w;
                w.x = __float2bfloat16(s0 - __bfloat162float(h0));
                w.y = __float2bfloat16(s1 - __bfloat162float(h1));
                Sl[o] = w;
                h0 = __float2bfloat16(m0); h1 = __float2bfloat16(m1);
                w.x = h0; w.y = h1; Mh[o] = w;
                w.x = __float2bfloat16(m0 - __bfloat162float(h0));
                w.y = __float2bfloat16(m1 - __bfloat162float(h1));
                Ml[o] = w;
            }
        }
    }
}

// ---------------- fusion GEMM via mma.sync + bias/relu + partial pooling ----------
__global__ __launch_bounds__(256, 2) void k_fusion_mma(const float* __restrict__ fb) {
    extern __shared__ char smem[];
    uint32_t sb = smem_u32(smem);
    int t = threadIdx.x, lane = t & 31, wid = t >> 5;
    int wm = wid >> 2, wn = wid & 3;
    int p = blockIdx.z;
    int qt = blockIdx.y, q0 = qt * 128, e0 = blockIdx.x * 128;

    const char* Sh = (const char*)(g_sh + (size_t)p * 262144);
    const char* Sl = (const char*)(g_sl + (size_t)p * 262144);
    const char* Mh = (const char*)(g_mh + (size_t)p * 262144);
    const char* Ml = (const char*)(g_ml + (size_t)p * 262144);
    const char* Wh = (const char*)g_fwh;
    const char* Wl = (const char*)g_fwl;

    float acc[4][4][4];
#pragma unroll
    for (int a = 0; a < 4; a++)
#pragma unroll
        for (int b = 0; b < 4; b++)
#pragma unroll
            for (int c = 0; c < 4; c++) acc[a][b][c] = 0.f;

    auto load_stage = [&](int s) {
        uint32_t bb = sb + (s & 1) * AV_STAGE;
        const char* ah = (s < 16) ? Sh : Mh;
        const char* al = (s < 16) ? Sl : Ml;
        int kc = (s & 15) * 64;
#pragma unroll
        for (int h = 0; h < 2; h++) {
            int idx = h * 256 + t;
            int row = idx >> 2, ch = idx & 3;
            uint32_t d = bb + row * 80 + ch * 16;
            size_t off = (size_t)(q0 + row) * 1024 + kc + ch * 16;
            cp_async16(d, ah + off);
            cp_async16(d + AV_A_SZ, al + off);
        }
#pragma unroll
        for (int h = 0; h < 2; h++) {
            int idx = h * 256 + t;
            int row = idx >> 4, ch = idx & 15;
            uint32_t d = bb + AV_VH_OFF + row * 272 + ch * 16;
            size_t off = (size_t)(s * 32 + row) * 1024 + e0 * 2 + ch * 16;
            cp_async16(d, Wh + off);
            cp_async16(d + AV_V_SZ, Wl + off);
        }
    };

    load_stage(0);
    CP_COMMIT();

    for (int s = 0; s < 32; s++) {
        CP_WAIT(0);
        __syncthreads();
        if (s + 1 < 32) {
            load_stage(s + 1);
            CP_COMMIT();
        }
        uint32_t bb = sb + (s & 1) * AV_STAGE;
#pragma unroll
        for (int kk = 0; kk < 2; kk++) {
            uint32_t aBase = bb + (wm * 64 + (lane & 15)) * 80 + (lane >> 4) * 16 + kk * 32;
            uint32_t aHi[4][4], aLo[4][4];
#pragma unroll
            for (int mt = 0; mt < 4; mt++) {
                uint32_t ad = aBase + mt * 16 * 80;
                ldm_x4(aHi[mt], ad);
                ldm_x4(aLo[mt], ad + AV_A_SZ);
            }
            uint32_t bBase = bb + AV_VH_OFF + (kk * 16 + (lane & 15)) * 272 + wn * 64 +
                             ((lane >> 4) & 1) * 16;
#pragma unroll
            for (int pr = 0; pr < 2; pr++) {
                uint32_t bH[4], bL[4];
                uint32_t bd = bBase + pr * 32;
                ldm_x4t(bH, bd);
                ldm_x4t(bL, bd + AV_V_SZ);
#pragma unroll
                for (int mt = 0; mt < 4; mt++)
#pragma unroll
                    for (int n2 = 0; n2 < 2; n2++)
                        mma_bf16(acc[mt][pr * 2 + n2], aHi[mt], bH + 2 * n2);
#pragma unroll
                for (int mt = 0; mt < 4; mt++)
#pragma unroll
                    for (int n2 = 0; n2 < 2; n2++)
                        mma_bf16(acc[mt][pr * 2 + n2], aLo[mt], bH + 2 * n2);
#pragma unroll
                for (int mt = 0; mt < 4; mt++)
#pragma unroll
                    for (int n2 = 0; n2 < 2; n2++)
                        mma_bf16(acc[mt][pr * 2 + n2], aHi[mt], bL + 2 * n2);
            }
        }
    }

    // bias + relu + pool over this block's 128 rows
    float psum[4][2], pmax[4][2];
#pragma unroll
    for (int ntl = 0; ntl < 4; ntl++) {
        psum[ntl][0] = psum[ntl][1] = 0.f;
        pmax[ntl][0] = pmax[ntl][1] = 0.f;
    }
#pragma unroll
    for (int ntl = 0; ntl < 4; ntl++) {
        int c = e0 + wn * 32 + ntl * 8 + (lane & 3) * 2;
        float b0 = fb[c], b1 = fb[c + 1];
#pragma unroll
        for (int mt = 0; mt < 4; mt++) {
            float* cc = acc[mt][ntl];
            float v0 = fmaxf(cc[0] + b0, 0.f);
            float v1 = fmaxf(cc[1] + b1, 0.f);
            float v2 = fmaxf(cc[2] + b0, 0.f);
            float v3 = fmaxf(cc[3] + b1, 0.f);
            psum[ntl][0] += v0 + v2;
            psum[ntl][1] += v1 + v3;
            pmax[ntl][0] = fmaxf(pmax[ntl][0], fmaxf(v0, v2));
            pmax[ntl][1] = fmaxf(pmax[ntl][1], fmaxf(v1, v3));
        }
    }
    __syncthreads();
    float* redS = (float*)(smem + FU_RED_OFF);
    float* redM = redS + 256;
#pragma unroll
    for (int ntl = 0; ntl < 4; ntl++)
#pragma unroll
        for (int j = 0; j < 2; j++) {
            float s = psum[ntl][j], m = pmax[ntl][j];
            s += __shfl_xor_sync(0xffffffffu, s, 4);
            s += __shfl_xor_sync(0xffffffffu, s, 8);
            s += __shfl_xor_sync(0xffffffffu, s, 16);
            m = fmaxf(m, __shfl_xor_sync(0xffffffffu, m, 4));
            m = fmaxf(m, __shfl_xor_sync(0xffffffffu, m, 8));
            m = fmaxf(m, __shfl_xor_sync(0xffffffffu, m, 16));
            if (lane < 4) {
                int col = wn * 32 + ntl * 8 + lane * 2 + j;
                redS[wm * 128 + col] = s;
                redM[wm * 128 + col] = m;
            }
        }
    __syncthreads();
    if (t < 128) {
        float s = redS[t] + redS[128 + t];
        float m = fmaxf(redM[t], redM[128 + t]);
        int idx = (p * 4 + qt) * 512 + e0 + t;
        g_psum[idx] = s;
        g_pmax[idx] = m;
    }
}

// ---------------- pool finalize ----------------
__global__ void k_pool(void) {
    int p = blockIdx.x, e = threadIdx.x;
    float s = 0.f, m = 0.f;
#pragma unroll
    for (int qt = 0; qt < 4; qt++) {
        int idx = (p * 4 + qt) * 512 + e;
        s += g_psum[idx];
        m = fmaxf(m, g_pmax[idx]);
    }
    int base = (p >> 2) * 4096 + (p & 3) * 512 + e;
    g_pooled[base] = s * (1.0f / 512.0f);
    g_pooled[base + 2048] = m;
}

// ---------------- out = relu(pooled @ out_w + out_b) ----------------
__global__ __launch_bounds__(256) void k_out(const float* __restrict__ ow,
                                             const float* __restrict__ ob,
                                             float* __restrict__ outp) {
    __shared__ float sp[4096];
    int b = blockIdx.x, t = threadIdx.x;
    for (int i = t; i < 4096; i += 256) sp[i] = g_pooled[b * 4096 + i];
    __syncthreads();
    int col = t * 4;
    float4 acc = *(const float4*)(ob + col);
#pragma unroll 8
    for (int c = 0; c < 4096; c++) {
        float pv = sp[c];
        float4 w = *(const float4*)(ow + (size_t)c * 1024 + col);
        acc.x += pv * w.x;
        acc.y += pv * w.y;
        acc.z += pv * w.z;
        acc.w += pv * w.w;
    }
    acc.x = fmaxf(acc.x, 0.f);
    acc.y = fmaxf(acc.y, 0.f);
    acc.z = fmaxf(acc.z, 0.f);
    acc.w = fmaxf(acc.w, 0.f);
    *(float4*)(outp + b * 1024 + col) = acc;
}

extern "C" void kernel_launch(void* const* d_in, const int* in_sizes, int n_in,
                              void* d_out, int out_size) {
    const float* x1 = (const float*)d_in[0];
    const float* x2 = (const float*)d_in[1];
    const unsigned int* x1_len = (const unsigned int*)d_in[2];
    const unsigned int* x2_len = (const unsigned int*)d_in[3];
    const float* fw = (const float*)d_in[4];
    const float* fb = (const float*)d_in[5];
    const float* ow = (const float*)d_in[6];
    const float* ob = (const float*)d_in[7];

    float* outp = (float*)d_out;
    float* attn;
    if (out_size >= OUT_ELEMS + ATTN_ELEMS) {
        attn = outp + OUT_ELEMS;
    } else if (out_size >= ATTN_ELEMS) {
        attn = outp;
        void* dp = nullptr;
        cudaGetSymbolAddress(&dp, g_out_dummy);
        outp = (float*)dp;
    } else {
        void* dp = nullptr;
        cudaGetSymbolAddress(&dp, g_attn_scratch);
        attn = (float*)dp;
    }

    void *qh, *ql, *kh, *kl, *fwh, *fwl;
    cudaGetSymbolAddress(&qh, g_qh);
    cudaGetSymbolAddress(&ql, g_ql);
    cudaGetSymbolAddress(&kh, g_kh);
    cudaGetSymbolAddress(&kl, g_kl);
    cudaGetSymbolAddress(&fwh, g_fwh);
    cudaGetSymbolAddress(&fwl, g_fwl);

    cudaFuncSetAttribute(k_scores_mma, cudaFuncAttributeMaxDynamicSharedMemorySize, SC_SMEM);
    cudaFuncSetAttribute(k_av_mma, cudaFuncAttributeMaxDynamicSharedMemorySize, AV_SMEM);
    cudaFuncSetAttribute(k_fusion_mma, cudaFuncAttributeMaxDynamicSharedMemorySize, FU_SMEM);

    k_lens<<<1, 128>>>(x1_len, x2_len);
    k_cvt<<<8192, 256>>>(x1, (__nv_bfloat16*)qh, (__nv_bfloat16*)ql, 2097152);
    k_cvt<<<32768, 256>>>(x2, (__nv_bfloat16*)kh, (__nv_bfloat16*)kl, 8388608);
    k_cvt<<<512, 256>>>(fw, (__nv_bfloat16*)fwh, (__nv_bfloat16*)fwl, 131072);
    k_scores_mma<<<dim3(4, NPAIR), 256, SC_SMEM>>>();
    k_norm<<<NPAIR * CL, 128>>>(attn);
    k_av_mma<<<dim3(4, 4, NPAIR), 256, AV_SMEM>>>(x1);
    k_fusion_mma<<<dim3(4, 4, NPAIR), 256, FU_SMEM>>>(fb);
    k_pool<<<NPAIR, 512>>>();
    k_out<<<NB, 256>>>(ow, ob, outp);
}

// round 9
// speedup vs baseline: 2.5886x; 1.1641x over previous
#include <cuda_runtime.h>
#include <cuda_bf16.h>
#include <cstdint>

#define CL 512
#define CE 512
#define NPAIR 128
#define NB 32
#define ATTN_ELEMS (NPAIR * CL * CL)
#define OUT_ELEMS (NB * 1024)
#define SCALE_F 0.044194173824159216f

// ---------------- scratch (device globals; alloc-free rule) ----------------
__device__ float g_pooled[NB * 4096];
__device__ float g_attn_scratch[ATTN_ELEMS];
__device__ float g_out_dummy[OUT_ELEMS];
__device__ float g_rowsum[NPAIR * CL];
__device__ float g_psum[4 * NPAIR * CL];
__device__ float g_pmax[4 * NPAIR * CL];
__device__ float g_vmean[NPAIR * CE];
__device__ int g_qlen[32];
__device__ int g_klen[128];
__device__ __nv_bfloat16 g_qh[NB * CL * CE];
__device__ __nv_bfloat16 g_ql[NB * CL * CE];
__device__ __nv_bfloat16 g_kh[NPAIR * CL * CE];
__device__ __nv_bfloat16 g_kl[NPAIR * CL * CE];
__device__ __nv_bfloat16 g_ah[NPAIR * CL * CL];  // UNNORMALIZED exp hi
__device__ __nv_bfloat16 g_al[NPAIR * CL * CL];  // UNNORMALIZED exp lo
__device__ __nv_bfloat16 g_sh[NPAIR * CL * CE];  // x1 - xa hi
__device__ __nv_bfloat16 g_sl[NPAIR * CL * CE];
__device__ __nv_bfloat16 g_mh[NPAIR * CL * CE];  // x1 * xa hi
__device__ __nv_bfloat16 g_ml[NPAIR * CL * CE];
__device__ __nv_bfloat16 g_fwh[1024 * 512];
__device__ __nv_bfloat16 g_fwl[1024 * 512];

// ---------------- PTX helpers ----------------
__device__ __forceinline__ uint32_t smem_u32(const void* p) {
    uint32_t a;
    asm("{ .reg .u64 t; cvta.to.shared.u64 t, %1; cvt.u32.u64 %0, t; }" : "=r"(a) : "l"(p));
    return a;
}
__device__ __forceinline__ void cp_async16(uint32_t dst, const void* src) {
    asm volatile("cp.async.ca.shared.global [%0], [%1], 16;" :: "r"(dst), "l"(src));
}
#define CP_COMMIT() asm volatile("cp.async.commit_group;" ::: "memory")
#define CP_WAIT(n)  asm volatile("cp.async.wait_group %0;" :: "n"(n) : "memory")

__device__ __forceinline__ void ldm_x4(uint32_t* r, uint32_t addr) {
    asm volatile("ldmatrix.sync.aligned.m8n8.x4.shared.b16 {%0,%1,%2,%3}, [%4];"
                 : "=r"(r[0]), "=r"(r[1]), "=r"(r[2]), "=r"(r[3]) : "r"(addr));
}
__device__ __forceinline__ void ldm_x4t(uint32_t* r, uint32_t addr) {
    asm volatile("ldmatrix.sync.aligned.m8n8.x4.trans.shared.b16 {%0,%1,%2,%3}, [%4];"
                 : "=r"(r[0]), "=r"(r[1]), "=r"(r[2]), "=r"(r[3]) : "r"(addr));
}
__device__ __forceinline__ void mma_bf16(float* c, const uint32_t* a, const uint32_t* b) {
    asm volatile(
        "mma.sync.aligned.m16n8k16.row.col.f32.bf16.bf16.f32 "
        "{%0,%1,%2,%3}, {%4,%5,%6,%7}, {%8,%9}, {%0,%1,%2,%3};"
        : "+f"(c[0]), "+f"(c[1]), "+f"(c[2]), "+f"(c[3])
        : "r"(a[0]), "r"(a[1]), "r"(a[2]), "r"(a[3]), "r"(b[0]), "r"(b[1]));
}

// ---------------- k_scores smem geometry ----------------
#define PITCHB 80
#define TILE_B (128 * PITCHB)
#define STAGE_B (4 * TILE_B)
#define RS_OFF (2 * STAGE_B)
#define SC_SMEM (RS_OFF + 128 * 4 * 4)

// ---------------- AV / fusion smem geometry ----------------
#define AV_A_SZ (128 * 80)
#define AV_V_SZ (32 * 272)
#define AV_VH_OFF (2 * AV_A_SZ)
#define AV_STAGE (2 * AV_A_SZ + 2 * AV_V_SZ)
#define AV_SMEM (2 * AV_STAGE)
#define FU_RED_OFF AV_SMEM
#define FU_SMEM (AV_SMEM + 2048)

// ---------------- length normalization ----------------
__global__ void k_lens(const unsigned int* __restrict__ x1l,
                       const unsigned int* __restrict__ x2l) {
    __shared__ int is64;
    int t = threadIdx.x;
    if (t == 0) {
        int all0 = 1;
        for (int i = 1; i < 128; i += 2)
            if (x2l[i] != 0u) { all0 = 0; break; }
        is64 = all0;
    }
    __syncthreads();
    if (t < 32)  g_qlen[t] = (int)(is64 ? x1l[2 * t] : x1l[t]);
    if (t < 128) g_klen[t] = (int)(is64 ? x2l[2 * t] : x2l[t]);
}

// ---------------- per-pair V column means (for fully-masked rows) ----------------
__global__ void k_vmean(const float* __restrict__ x2) {
    int p = blockIdx.x, e = threadIdx.x;
    const float* base = x2 + (size_t)p * 262144 + e;
    float s0 = 0.f, s1 = 0.f, s2 = 0.f, s3 = 0.f;
    for (int k = 0; k < 512; k += 4) {
        s0 += base[(k + 0) * 512];
        s1 += base[(k + 1) * 512];
        s2 += base[(k + 2) * 512];
        s3 += base[(k + 3) * 512];
    }
    g_vmean[p * 512 + e] = (s0 + s1 + s2 + s3) * (1.f / 512.f);
}

// ---------------- fp32 -> bf16 hi/lo split ----------------
__global__ void k_cvt(const float* __restrict__ src, __nv_bfloat16* __restrict__ hi,
                      __nv_bfloat16* __restrict__ lo, int n4) {
    int i = blockIdx.x * blockDim.x + threadIdx.x;
    if (i >= n4) return;
    float4 v = ((const float4*)src)[i];
    __nv_bfloat16 h0 = __float2bfloat16(v.x), h1 = __float2bfloat16(v.y);
    __nv_bfloat16 h2 = __float2bfloat16(v.z), h3 = __float2bfloat16(v.w);
    __nv_bfloat16 l0 = __float2bfloat16(v.x - __bfloat162float(h0));
    __nv_bfloat16 l1 = __float2bfloat16(v.y - __bfloat162float(h1));
    __nv_bfloat16 l2 = __float2bfloat16(v.z - __bfloat162float(h2));
    __nv_bfloat16 l3 = __float2bfloat16(v.w - __bfloat162float(h3));
    __nv_bfloat162 a, b;
    a.x = h0; a.y = h1; b.x = h2; b.y = h3;
    ((__nv_bfloat162*)hi)[2 * i] = a;
    ((__nv_bfloat162*)hi)[2 * i + 1] = b;
    a.x = l0; a.y = l1; b.x = l2; b.y = l3;
    ((__nv_bfloat162*)lo)[2 * i] = a;
    ((__nv_bfloat162*)lo)[2 * i + 1] = b;
}

// ---------------- scores: Q@K^T, masked exp -> bf16 hi/lo (UNNORMALIZED) -----------
// Masked rows emit exp==1 everywhere (uniform softmax). Skips q-tiles with
// q0>=qlen entirely, and skips 128-col blocks beyond klen (store-only fill).
__global__ __launch_bounds__(256, 2) void k_scores_mma(void) {
    extern __shared__ char smem[];
    uint32_t sb = smem_u32(smem);
    int t = threadIdx.x, lane = t & 31, wid = t >> 5;
    int wm = wid >> 2, wn = wid & 3;
    int p = blockIdx.y, x1i = p & 31;
    int qt = blockIdx.x, q0 = qt * 128;
    int qlen = g_qlen[x1i], klen = g_klen[p];

    bool all_masked = (q0 >= qlen) || (klen == 0);
    int n_nt = all_masked ? 0 : min(4, (klen + 127) >> 7);
    int n_stages = n_nt * 16;

    const char* Qh = (const char*)(g_qh + (size_t)x1i * 262144);
    const char* Ql = (const char*)(g_ql + (size_t)x1i * 262144);
    const char* Kh = (const char*)(g_kh + (size_t)p * 262144);
    const char* Kl = (const char*)(g_kl + (size_t)p * 262144);

    float acc[4][4][4];
#pragma unroll
    for (int a = 0; a < 4; a++)
#pragma unroll
        for (int b = 0; b < 4; b++)
#pragma unroll
            for (int c = 0; c < 4; c++) acc[a][b][c] = 0.f;
    float rsum[4][2];
#pragma unroll
    for (int a = 0; a < 4; a++) rsum[a][0] = rsum[a][1] = 0.f;

    auto load_stage = [&](int s) {
        int nt = s >> 4, ec = s & 15;
        uint32_t bb = sb + (s & 1) * STAGE_B;
#pragma unroll
        for (int h = 0; h < 2; h++) {
            int idx = h * 256 + t;
            int row = idx >> 2, q = (idx & 3) * 16;
            uint32_t dst = row * PITCHB + q;
            size_t asrc = (size_t)(q0 + row) * 1024 + ec * 64 + q;
            size_t bsrc = (size_t)(nt * 128 + row) * 1024 + ec * 64 + q;
            cp_async16(bb + dst, Qh + asrc);
            cp_async16(bb + TILE_B + dst, Ql + asrc);
            cp_async16(bb + 2 * TILE_B + dst, Kh + bsrc);
            cp_async16(bb + 3 * TILE_B + dst, Kl + bsrc);
        }
    };

    if (n_stages > 0) {
        load_stage(0);
        CP_COMMIT();
    }

    __nv_bfloat162* AH = (__nv_bfloat162*)(g_ah + (size_t)p * 262144);
    __nv_bfloat162* AL = (__nv_bfloat162*)(g_al + (size_t)p * 262144);

    for (int s = 0; s < n_stages; s++) {
        CP_WAIT(0);
        __syncthreads();
        if (s + 1 < n_stages) {
            load_stage(s + 1);
            CP_COMMIT();
        }
        uint32_t bb = sb + (s & 1) * STAGE_B;
#pragma unroll
        for (int kk = 0; kk < 2; kk++) {
            uint32_t aBase = bb + (wm * 64 + (lane & 15)) * PITCHB + (lane >> 4) * 16 +
                             kk * 32;
            uint32_t aHi[4][4], aLo[4][4];
#pragma unroll
            for (int mt = 0; mt < 4; mt++) {
                uint32_t ad = aBase + mt * 16 * PITCHB;
                ldm_x4(aHi[mt], ad);
                ldm_x4(aLo[mt], ad + TILE_B);
            }
            uint32_t bBase = bb + 2 * TILE_B +
                             (wn * 32 + ((lane >> 4) & 1) * 8 + (lane & 7)) * PITCHB +
                             ((lane >> 3) & 1) * 16 + kk * 32;
#pragma unroll
            for (int pr = 0; pr < 2; pr++) {
                uint32_t bH[4], bL[4];
                uint32_t bd = bBase + pr * 16 * PITCHB;
                ldm_x4(bH, bd);
                ldm_x4(bL, bd + TILE_B);
#pragma unroll
                for (int mt = 0; mt < 4; mt++)
#pragma unroll
                    for (int n2 = 0; n2 < 2; n2++)
                        mma_bf16(acc[mt][pr * 2 + n2], aHi[mt], bH + 2 * n2);
#pragma unroll
                for (int mt = 0; mt < 4; mt++)
#pragma unroll
                    for (int n2 = 0; n2 < 2; n2++)
                        mma_bf16(acc[mt][pr * 2 + n2], aLo[mt], bH + 2 * n2);
#pragma unroll
                for (int mt = 0; mt < 4; mt++)
#pragma unroll
                    for (int n2 = 0; n2 < 2; n2++)
                        mma_bf16(acc[mt][pr * 2 + n2], aHi[mt], bL + 2 * n2);
            }
        }
        if ((s & 15) == 15) {
            int nt = s >> 4;
            int nb = nt * 128 + wn * 32;
#pragma unroll
            for (int mt = 0; mt < 4; mt++) {
                int r0 = q0 + wm * 64 + mt * 16 + (lane >> 2);
                bool fm0 = (r0 >= qlen);
                bool fm1 = ((r0 + 8) >= qlen);
#pragma unroll
                for (int ntl = 0; ntl < 4; ntl++) {
                    int col = nb + ntl * 8 + (lane & 3) * 2;
                    float* cc = acc[mt][ntl];
                    float e0 = fm0 ? 1.f : ((col < klen) ? __expf(cc[0] * SCALE_F) : 0.f);
                    float e1 = fm0 ? 1.f : ((col + 1 < klen) ? __expf(cc[1] * SCALE_F) : 0.f);
                    float e2 = fm1 ? 1.f : ((col < klen) ? __expf(cc[2] * SCALE_F) : 0.f);
                    float e3 = fm1 ? 1.f : ((col + 1 < klen) ? __expf(cc[3] * SCALE_F) : 0.f);
                    rsum[mt][0] += e0 + e1;
                    rsum[mt][1] += e2 + e3;
                    size_t o0 = ((size_t)r0 * 512 + col) >> 1;
                    size_t o1 = ((size_t)(r0 + 8) * 512 + col) >> 1;
                    __nv_bfloat162 w;
                    __nv_bfloat16 h0 = __float2bfloat16(e0), h1 = __float2bfloat16(e1);
                    w.x = h0; w.y = h1; AH[o0] = w;
                    w.x = __float2bfloat16(e0 - __bfloat162float(h0));
                    w.y = __float2bfloat16(e1 - __bfloat162float(h1));
                    AL[o0] = w;
                    h0 = __float2bfloat16(e2); h1 = __float2bfloat16(e3);
                    w.x = h0; w.y = h1; AH[o1] = w;
                    w.x = __float2bfloat16(e2 - __bfloat162float(h0));
                    w.y = __float2bfloat16(e3 - __bfloat162float(h1));
                    AL[o1] = w;
                    cc[0] = cc[1] = cc[2] = cc[3] = 0.f;
                }
            }
        }
    }

    // fill skipped 128-col blocks: masked rows -> exp 1, live rows -> 0
    {
        __nv_bfloat16* AHB = g_ah + (size_t)p * 262144;
        __nv_bfloat16* ALB = g_al + (size_t)p * 262144;
        const uint32_t ONE2 = 0x3F803F80u;
        uint4 vone = make_uint4(ONE2, ONE2, ONE2, ONE2);
        uint4 vzer = make_uint4(0u, 0u, 0u, 0u);
        for (int nt = n_nt; nt < 4; nt++) {
            for (int i = t; i < 2048; i += 256) {
                int row = i >> 4, c8 = (i & 15) * 8;
                bool mr = all_masked || ((q0 + row) >= qlen);
                size_t o = (size_t)(q0 + row) * 512 + nt * 128 + c8;
                *(uint4*)(AHB + o) = mr ? vone : vzer;
                *(uint4*)(ALB + o) = vzer;
            }
        }
    }

    __syncthreads();
    float* rs = (float*)(smem + RS_OFF);
#pragma unroll
    for (int mt = 0; mt < 4; mt++)
#pragma unroll
        for (int ri = 0; ri < 2; ri++) {
            float v = rsum[mt][ri];
            v += __shfl_xor_sync(0xffffffffu, v, 1);
            v += __shfl_xor_sync(0xffffffffu, v, 2);
            if ((lane & 3) == 0)
                rs[(wm * 64 + mt * 16 + ri * 8 + (lane >> 2)) * 4 + wn] = v;
        }
    __syncthreads();
    if (t < 128) {
        float s = rs[t * 4] + rs[t * 4 + 1] + rs[t * 4 + 2] + rs[t * 4 + 3];
        bool mr = all_masked || ((q0 + t) >= qlen);
        s += (float)(4 - n_nt) * 128.f * (mr ? 1.f : 0.f);
        g_rowsum[p * 512 + q0 + t] = s;
    }
}

// ---------------- normalize: fp32 attn output from bf16 exp + rowsum ----------------
__global__ void k_norm(float* __restrict__ attn) {
    int row = blockIdx.x;
    int t = threadIdx.x;
    float s = g_rowsum[row];
    float inv = s > 0.f ? 1.f / s : 0.f;
    const __nv_bfloat162* hp = (const __nv_bfloat162*)(g_ah + (size_t)row * 512);
    const __nv_bfloat162* lp = (const __nv_bfloat162*)(g_al + (size_t)row * 512);
    __nv_bfloat162 h0 = hp[2 * t], h1 = hp[2 * t + 1];
    __nv_bfloat162 l0 = lp[2 * t], l1 = lp[2 * t + 1];
    float4 v;
    v.x = (__bfloat162float(h0.x) + __bfloat162float(l0.x)) * inv;
    v.y = (__bfloat162float(h0.y) + __bfloat162float(l0.y)) * inv;
    v.z = (__bfloat162float(h1.x) + __bfloat162float(l1.x)) * inv;
    v.w = (__bfloat162float(h1.y) + __bfloat162float(l1.y)) * inv;
    ((float4*)(attn + (size_t)row * 512))[t] = v;
}

// ---------------- x1_att = exp @ V / rowsum; K-loop truncated at klen; ------------
// masked rows use precomputed colmean(V). Epilogue emits cat bf16 hi/lo.
__global__ __launch_bounds__(256, 2) void k_av_mma(const float* __restrict__ x1) {
    extern __shared__ char smem[];
    uint32_t sb = smem_u32(smem);
    int t = threadIdx.x, lane = t & 31, wid = t >> 5;
    int wm = wid >> 2, wn = wid & 3;
    int p = blockIdx.z, x1i = p & 31;
    int q0 = blockIdx.y * 128, e0 = blockIdx.x * 128;
    int qlen = g_qlen[x1i], klen = g_klen[p];

    bool all_masked = (q0 >= qlen) || (klen == 0);
    int n_stage = all_masked ? 0 : min(16, (klen + 31) >> 5);

    const char* Ah = (const char*)(g_ah + (size_t)p * 262144);
    const char* Al = (const char*)(g_al + (size_t)p * 262144);
    const char* Vh = (const char*)(g_kh + (size_t)p * 262144);
    const char* Vl = (const char*)(g_kl + (size_t)p * 262144);

    float acc[4][4][4];
#pragma unroll
    for (int a = 0; a < 4; a++)
#pragma unroll
        for (int b = 0; b < 4; b++)
#pragma unroll
            for (int c = 0; c < 4; c++) acc[a][b][c] = 0.f;

    auto load_stage = [&](int s) {
        uint32_t bb = sb + (s & 1) * AV_STAGE;
#pragma unroll
        for (int h = 0; h < 2; h++) {
            int idx = h * 256 + t;
            int row = idx >> 2, ch = idx & 3;
            uint32_t d = bb + row * 80 + ch * 16;
            size_t off = (size_t)(q0 + row) * 1024 + s * 64 + ch * 16;
            cp_async16(d, Ah + off);
            cp_async16(d + AV_A_SZ, Al + off);
        }
#pragma unroll
        for (int h = 0; h < 2; h++) {
            int idx = h * 256 + t;
            int row = idx >> 4, ch = idx & 15;
            uint32_t d = bb + AV_VH_OFF + row * 272 + ch * 16;
            size_t off = (size_t)(s * 32 + row) * 1024 + e0 * 2 + ch * 16;
            cp_async16(d, Vh + off);
            cp_async16(d + AV_V_SZ, Vl + off);
        }
    };

    if (n_stage > 0) {
        load_stage(0);
        CP_COMMIT();
    }

    for (int s = 0; s < n_stage; s++) {
        CP_WAIT(0);
        __syncthreads();
        if (s + 1 < n_stage) {
            load_stage(s + 1);
            CP_COMMIT();
        }
        uint32_t bb = sb + (s & 1) * AV_STAGE;
#pragma unroll
        for (int kk = 0; kk < 2; kk++) {
            uint32_t aBase = bb + (wm * 64 + (lane & 15)) * 80 + (lane >> 4) * 16 + kk * 32;
            uint32_t aHi[4][4], aLo[4][4];
#pragma unroll
            for (int mt = 0; mt < 4; mt++) {
                uint32_t ad = aBase + mt * 16 * 80;
                ldm_x4(aHi[mt], ad);
                ldm_x4(aLo[mt], ad + AV_A_SZ);
            }
            uint32_t bBase = bb + AV_VH_OFF + (kk * 16 + (lane & 15)) * 272 + wn * 64 +
                             ((lane >> 4) & 1) * 16;
#pragma unroll
            for (int pr = 0; pr < 2; pr++) {
                uint32_t bH[4], bL[4];
                uint32_t bd = bBase + pr * 32;
                ldm_x4t(bH, bd);
                ldm_x4t(bL, bd + AV_V_SZ);
#pragma unroll
                for (int mt = 0; mt < 4; mt++)
#pragma unroll
                    for (int n2 = 0; n2 < 2; n2++)
                        mma_bf16(acc[mt][pr * 2 + n2], aHi[mt], bH + 2 * n2);
#pragma unroll
                for (int mt = 0; mt < 4; mt++)
#pragma unroll
                    for (int n2 = 0; n2 < 2; n2++)
                        mma_bf16(acc[mt][pr * 2 + n2], aLo[mt], bH + 2 * n2);
#pragma unroll
                for (int mt = 0; mt < 4; mt++)
#pragma unroll
                    for (int n2 = 0; n2 < 2; n2++)
                        mma_bf16(acc[mt][pr * 2 + n2], aHi[mt], bL + 2 * n2);
            }
        }
    }

    // epilogue: xa = acc/rowsum (masked rows: colmean V) -> (x1-xa, x1*xa) bf16 hi/lo
    const float* X1 = x1 + (size_t)x1i * 262144;
    const float* VM = g_vmean + p * 512;
    __nv_bfloat162* Sh = (__nv_bfloat162*)(g_sh + (size_t)p * 262144);
    __nv_bfloat162* Sl = (__nv_bfloat162*)(g_sl + (size_t)p * 262144);
    __nv_bfloat162* Mh = (__nv_bfloat162*)(g_mh + (size_t)p * 262144);
    __nv_bfloat162* Ml = (__nv_bfloat162*)(g_ml + (size_t)p * 262144);
#pragma unroll
    for (int mt = 0; mt < 4; mt++) {
#pragma unroll
        for (int hh = 0; hh < 2; hh++) {
            int r = q0 + wm * 64 + mt * 16 + (lane >> 2) + hh * 8;
            bool mr = all_masked || (r >= qlen);
            float inv = 0.f;
            if (!mr) inv = 1.f / g_rowsum[p * 512 + r];
#pragma unroll
            for (int ntl = 0; ntl < 4; ntl++) {
                float* cc = acc[mt][ntl];
                int c = e0 + wn * 32 + ntl * 8 + (lane & 3) * 2;
                float2 u = *(const float2*)(X1 + (size_t)r * 512 + c);
                float xa0, xa1;
                if (mr) {
                    float2 vm = *(const float2*)(VM + c);
                    xa0 = vm.x;
                    xa1 = vm.y;
                } else {
                    xa0 = cc[hh * 2] * inv;
                    xa1 = cc[hh * 2 + 1] * inv;
                }
                float s0 = u.x - xa0, s1 = u.y - xa1;
                float m0 = u.x * xa0, m1 = u.y * xa1;
                size_t o = ((size_t)r * 512 + c) >> 1;
                __nv_bfloat162 w;
                __nv_bfloat16 h0 = __float2bfloat16(s0), h1 = __float2bfloat16(s1);
                w.x = h0; w.y = h1; Sh[o] = w;
                w.x = __float2bfloat16(s0 - __bfloat162float(h0));
                w.y = __float2bfloat16(s1 - __bfloat162float(h1));
                Sl[o] = w;
                h0 = __float2bfloat16(m0); h1 = __float2bfloat16(m1);
                w.x = h0; w.y = h1; Mh[o] = w;
                w.x = __float2bfloat16(m0 - __bfloat162float(h0));
                w.y = __float2bfloat16(m1 - __bfloat162float(h1));
                Ml[o] = w;
            }
        }
    }
}

// ---------------- fusion GEMM via mma.sync + bias/relu + partial pooling ----------
__global__ __launch_bounds__(256, 2) void k_fusion_mma(const float* __restrict__ fb) {
    extern __shared__ char smem[];
    uint32_t sb = smem_u32(smem);
    int t = threadIdx.x, lane = t & 31, wid = t >> 5;
    int wm = wid >> 2, wn = wid & 3;
    int p = blockIdx.z;
    int qt = blockIdx.y, q0 = qt * 128, e0 = blockIdx.x * 128;

    const char* Sh = (const char*)(g_sh + (size_t)p * 262144);
    const char* Sl = (const char*)(g_sl + (size_t)p * 262144);
    const char* Mh = (const char*)(g_mh + (size_t)p * 262144);
    const char* Ml = (const char*)(g_ml + (size_t)p * 262144);
    const char* Wh = (const char*)g_fwh;
    const char* Wl = (const char*)g_fwl;

    float acc[4][4][4];
#pragma unroll
    for (int a = 0; a < 4; a++)
#pragma unroll
        for (int b = 0; b < 4; b++)
#pragma unroll
            for (int c = 0; c < 4; c++) acc[a][b][c] = 0.f;

    auto load_stage = [&](int s) {
        uint32_t bb = sb + (s & 1) * AV_STAGE;
        const char* ah = (s < 16) ? Sh : Mh;
        const char* al = (s < 16) ? Sl : Ml;
        int kc = (s & 15) * 64;
#pragma unroll
        for (int h = 0; h < 2; h++) {
            int idx = h * 256 + t;
            int row = idx >> 2, ch = idx & 3;
            uint32_t d = bb + row * 80 + ch * 16;
            size_t off = (size_t)(q0 + row) * 1024 + kc + ch * 16;
            cp_async16(d, ah + off);
            cp_async16(d + AV_A_SZ, al + off);
        }
#pragma unroll
        for (int h = 0; h < 2; h++) {
            int idx = h * 256 + t;
            int row = idx >> 4, ch = idx & 15;
            uint32_t d = bb + AV_VH_OFF + row * 272 + ch * 16;
            size_t off = (size_t)(s * 32 + row) * 1024 + e0 * 2 + ch * 16;
            cp_async16(d, Wh + off);
            cp_async16(d + AV_V_SZ, Wl + off);
        }
    };

    load_stage(0);
    CP_COMMIT();

    for (int s = 0; s < 32; s++) {
        CP_WAIT(0);
        __syncthreads();
        if (s + 1 < 32) {
            load_stage(s + 1);
            CP_COMMIT();
        }
        uint32_t bb = sb + (s & 1) * AV_STAGE;
#pragma unroll
        for (int kk = 0; kk < 2; kk++) {
            uint32_t aBase = bb + (wm * 64 + (lane & 15)) * 80 + (lane >> 4) * 16 + kk * 32;
            uint32_t aHi[4][4], aLo[4][4];
#pragma unroll
            for (int mt = 0; mt < 4; mt++) {
                uint32_t ad = aBase + mt * 16 * 80;
                ldm_x4(aHi[mt], ad);
                ldm_x4(aLo[mt], ad + AV_A_SZ);
            }
            uint32_t bBase = bb + AV_VH_OFF + (kk * 16 + (lane & 15)) * 272 + wn * 64 +
                             ((lane >> 4) & 1) * 16;
#pragma unroll
            for (int pr = 0; pr < 2; pr++) {
                uint32_t bH[4], bL[4];
                uint32_t bd = bBase + pr * 32;
                ldm_x4t(bH, bd);
                ldm_x4t(bL, bd + AV_V_SZ);
#pragma unroll
                for (int mt = 0; mt < 4; mt++)
#pragma unroll
                    for (int n2 = 0; n2 < 2; n2++)
                        mma_bf16(acc[mt][pr * 2 + n2], aHi[mt], bH + 2 * n2);
#pragma unroll
                for (int mt = 0; mt < 4; mt++)
#pragma unroll
                    for (int n2 = 0; n2 < 2; n2++)
                        mma_bf16(acc[mt][pr * 2 + n2], aLo[mt], bH + 2 * n2);
#pragma unroll
                for (int mt = 0; mt < 4; mt++)
#pragma unroll
                    for (int n2 = 0; n2 < 2; n2++)
                        mma_bf16(acc[mt][pr * 2 + n2], aHi[mt], bL + 2 * n2);
            }
        }
    }

    // bias + relu + pool over this block's 128 rows
    float psum[4][2], pmax[4][2];
#pragma unroll
    for (int ntl = 0; ntl < 4; ntl++) {
        psum[ntl][0] = psum[ntl][1] = 0.f;
        pmax[ntl][0] = pmax[ntl][1] = 0.f;
    }
#pragma unroll
    for (int ntl = 0; ntl < 4; ntl++) {
        int c = e0 + wn * 32 + ntl * 8 + (lane & 3) * 2;
        float b0 = fb[c], b1 = fb[c + 1];
#pragma unroll
        for (int mt = 0; mt < 4; mt++) {
            float* cc = acc[mt][ntl];
            float v0 = fmaxf(cc[0] + b0, 0.f);
            float v1 = fmaxf(cc[1] + b1, 0.f);
            float v2 = fmaxf(cc[2] + b0, 0.f);
            float v3 = fmaxf(cc[3] + b1, 0.f);
            psum[ntl][0] += v0 + v2;
            psum[ntl][1] += v1 + v3;
            pmax[ntl][0] = fmaxf(pmax[ntl][0], fmaxf(v0, v2));
            pmax[ntl][1] = fmaxf(pmax[ntl][1], fmaxf(v1, v3));
        }
    }
    __syncthreads();
    float* redS = (float*)(smem + FU_RED_OFF);
    float* redM = redS + 256;
#pragma unroll
    for (int ntl = 0; ntl < 4; ntl++)
#pragma unroll
        for (int j = 0; j < 2; j++) {
            float s = psum[ntl][j], m = pmax[ntl][j];
            s += __shfl_xor_sync(0xffffffffu, s, 4);
            s += __shfl_xor_sync(0xffffffffu, s, 8);
            s += __shfl_xor_sync(0xffffffffu, s, 16);
            m = fmaxf(m, __shfl_xor_sync(0xffffffffu, m, 4));
            m = fmaxf(m, __shfl_xor_sync(0xffffffffu, m, 8));
            m = fmaxf(m, __shfl_xor_sync(0xffffffffu, m, 16));
            if (lane < 4) {
                int col = wn * 32 + ntl * 8 + lane * 2 + j;
                redS[wm * 128 + col] = s;
                redM[wm * 128 + col] = m;
            }
        }
    __syncthreads();
    if (t < 128) {
        float s = redS[t] + redS[128 + t];
        float m = fmaxf(redM[t], redM[128 + t]);
        int idx = (p * 4 + qt) * 512 + e0 + t;
        g_psum[idx] = s;
        g_pmax[idx] = m;
    }
}

// ---------------- pool finalize ----------------
__global__ void k_pool(void) {
    int p = blockIdx.x, e = threadIdx.x;
    float s = 0.f, m = 0.f;
#pragma unroll
    for (int qt = 0; qt < 4; qt++) {
        int idx = (p * 4 + qt) * 512 + e;
        s += g_psum[idx];
        m = fmaxf(m, g_pmax[idx]);
    }
    int base = (p >> 2) * 4096 + (p & 3) * 512 + e;
    g_pooled[base] = s * (1.0f / 512.0f);
    g_pooled[base + 2048] = m;
}

// ---------------- out = relu(pooled @ out_w + out_b) ----------------
__global__ __launch_bounds__(256) void k_out(const float* __restrict__ ow,
                                             const float* __restrict__ ob,
                                             float* __restrict__ outp) {
    __shared__ float sp[4096];
    int b = blockIdx.x, t = threadIdx.x;
    for (int i = t; i < 4096; i += 256) sp[i] = g_pooled[b * 4096 + i];
    __syncthreads();
    int col = t * 4;
    float4 acc = *(const float4*)(ob + col);
#pragma unroll 8
    for (int c = 0; c < 4096; c++) {
        float pv = sp[c];
        float4 w = *(const float4*)(ow + (size_t)c * 1024 + col);
        acc.x += pv * w.x;
        acc.y += pv * w.y;
        acc.z += pv * w.z;
        acc.w += pv * w.w;
    }
    acc.x = fmaxf(acc.x, 0.f);
    acc.y = fmaxf(acc.y, 0.f);
    acc.z = fmaxf(acc.z, 0.f);
    acc.w = fmaxf(acc.w, 0.f);
    *(float4*)(outp + b * 1024 + col) = acc;
}

extern "C" void kernel_launch(void* const* d_in, const int* in_sizes, int n_in,
                              void* d_out, int out_size) {
    const float* x1 = (const float*)d_in[0];
    const float* x2 = (const float*)d_in[1];
    const unsigned int* x1_len = (const unsigned int*)d_in[2];
    const unsigned int* x2_len = (const unsigned int*)d_in[3];
    const float* fw = (const float*)d_in[4];
    const float* fb = (const float*)d_in[5];
    const float* ow = (const float*)d_in[6];
    const float* ob = (const float*)d_in[7];

    float* outp = (float*)d_out;
    float* attn;
    if (out_size >= OUT_ELEMS + ATTN_ELEMS) {
        attn = outp + OUT_ELEMS;
    } else if (out_size >= ATTN_ELEMS) {
        attn = outp;
        void* dp = nullptr;
        cudaGetSymbolAddress(&dp, g_out_dummy);
        outp = (float*)dp;
    } else {
        void* dp = nullptr;
        cudaGetSymbolAddress(&dp, g_attn_scratch);
        attn = (float*)dp;
    }

    void *qh, *ql, *kh, *kl, *fwh, *fwl;
    cudaGetSymbolAddress(&qh, g_qh);
    cudaGetSymbolAddress(&ql, g_ql);
    cudaGetSymbolAddress(&kh, g_kh);
    cudaGetSymbolAddress(&kl, g_kl);
    cudaGetSymbolAddress(&fwh, g_fwh);
    cudaGetSymbolAddress(&fwl, g_fwl);

    cudaFuncSetAttribute(k_scores_mma, cudaFuncAttributeMaxDynamicSharedMemorySize, SC_SMEM);
    cudaFuncSetAttribute(k_av_mma, cudaFuncAttributeMaxDynamicSharedMemorySize, AV_SMEM);
    cudaFuncSetAttribute(k_fusion_mma, cudaFuncAttributeMaxDynamicSharedMemorySize, FU_SMEM);

    k_lens<<<1, 128>>>(x1_len, x2_len);
    k_vmean<<<NPAIR, 512>>>(x2);
    k_cvt<<<8192, 256>>>(x1, (__nv_bfloat16*)qh, (__nv_bfloat16*)ql, 2097152);
    k_cvt<<<32768, 256>>>(x2, (__nv_bfloat16*)kh, (__nv_bfloat16*)kl, 8388608);
    k_cvt<<<512, 256>>>(fw, (__nv_bfloat16*)fwh, (__nv_bfloat16*)fwl, 131072);
    k_scores_mma<<<dim3(4, NPAIR), 256, SC_SMEM>>>();
    k_norm<<<NPAIR * CL, 128>>>(attn);
    k_av_mma<<<dim3(4, 4, NPAIR), 256, AV_SMEM>>>(x1);
    k_fusion_mma<<<dim3(4, 4, NPAIR), 256, FU_SMEM>>>(fb);
    k_pool<<<NPAIR, 512>>>();
    k_out<<<NB, 256>>>(ow, ob, outp);
}

// round 10
// speedup vs baseline: 3.0372x; 1.1733x over previous
#include <cuda_runtime.h>
#include <cuda_fp16.h>
#include <cstdint>

#define CL 512
#define CE 512
#define NPAIR 128
#define NB 32
#define ATTN_ELEMS (NPAIR * CL * CL)
#define OUT_ELEMS (NB * 1024)
#define SCALE_F 0.044194173824159216f

// ---------------- scratch (device globals; alloc-free rule) ----------------
__device__ float g_pooled[NB * 4096];
__device__ float g_attn_scratch[ATTN_ELEMS];
__device__ float g_out_dummy[OUT_ELEMS];
__device__ float g_rowsum[NPAIR * CL];
__device__ float g_psum[4 * NPAIR * CL];
__device__ float g_pmax[4 * NPAIR * CL];
__device__ float g_vmean[NPAIR * CE];
__device__ int g_qlen[32];
__device__ int g_klen[128];
__device__ __half g_qh[NB * CL * CE];     // x1 fp16 hi
__device__ __half g_ql[NB * CL * CE];     // x1 fp16 lo
__device__ __half g_kh[NPAIR * CL * CE];  // x2 fp16 hi
__device__ __half g_kl[NPAIR * CL * CE];  // x2 fp16 lo (unused by av; kept for cvt reuse)
__device__ __half g_ah[NPAIR * CL * CL];  // UNNORMALIZED exp (fp16 single)
__device__ __half g_sh[NPAIR * CL * CE];  // x1 - xa  fp16 hi
__device__ __half g_sl[NPAIR * CL * CE];  //          fp16 lo
__device__ __half g_mh[NPAIR * CL * CE];  // x1 * xa  fp16 hi
__device__ __half g_ml[NPAIR * CL * CE];  //          fp16 lo
__device__ __half g_fwh[1024 * 512];      // fusion_w fp16 hi
__device__ __half g_fwl[1024 * 512];      // (written, unused)

// ---------------- PTX helpers ----------------
__device__ __forceinline__ uint32_t smem_u32(const void* p) {
    uint32_t a;
    asm("{ .reg .u64 t; cvta.to.shared.u64 t, %1; cvt.u32.u64 %0, t; }" : "=r"(a) : "l"(p));
    return a;
}
__device__ __forceinline__ void cp_async16(uint32_t dst, const void* src) {
    asm volatile("cp.async.ca.shared.global [%0], [%1], 16;" :: "r"(dst), "l"(src));
}
#define CP_COMMIT() asm volatile("cp.async.commit_group;" ::: "memory")
#define CP_WAIT(n)  asm volatile("cp.async.wait_group %0;" :: "n"(n) : "memory")

__device__ __forceinline__ void ldm_x4(uint32_t* r, uint32_t addr) {
    asm volatile("ldmatrix.sync.aligned.m8n8.x4.shared.b16 {%0,%1,%2,%3}, [%4];"
                 : "=r"(r[0]), "=r"(r[1]), "=r"(r[2]), "=r"(r[3]) : "r"(addr));
}
__device__ __forceinline__ void ldm_x4t(uint32_t* r, uint32_t addr) {
    asm volatile("ldmatrix.sync.aligned.m8n8.x4.trans.shared.b16 {%0,%1,%2,%3}, [%4];"
                 : "=r"(r[0]), "=r"(r[1]), "=r"(r[2]), "=r"(r[3]) : "r"(addr));
}
__device__ __forceinline__ void mma_f16(float* c, const uint32_t* a, const uint32_t* b) {
    asm volatile(
        "mma.sync.aligned.m16n8k16.row.col.f32.f16.f16.f32 "
        "{%0,%1,%2,%3}, {%4,%5,%6,%7}, {%8,%9}, {%0,%1,%2,%3};"
        : "+f"(c[0]), "+f"(c[1]), "+f"(c[2]), "+f"(c[3])
        : "r"(a[0]), "r"(a[1]), "r"(a[2]), "r"(a[3]), "r"(b[0]), "r"(b[1]));
}

// ---------------- smem geometry ----------------
#define PITCHB 80
#define TILE_B (128 * PITCHB)           // 10240
// scores: A_hi + A_lo + B_hi per stage
#define SC_STAGE (3 * TILE_B)           // 30720
#define RS_OFF (2 * SC_STAGE)           // 61440
#define SC_SMEM (RS_OFF + 2048)
// av: A(exp) + V per stage
#define AV_A_SZ (128 * 80)              // 10240
#define AV_V_SZ (32 * 272)              // 8704
#define AV_STAGE (AV_A_SZ + AV_V_SZ)    // 18944
#define AV_SMEM (2 * AV_STAGE)
// fusion: A_hi + A_lo + W per stage
#define FU_W_OFF (2 * AV_A_SZ)          // 20480
#define FU_STAGE (FU_W_OFF + AV_V_SZ)   // 29184
#define FU_RED_OFF (2 * FU_STAGE)       // 58368
#define FU_SMEM (FU_RED_OFF + 2048)

// ---------------- length normalization ----------------
__global__ void k_lens(const unsigned int* __restrict__ x1l,
                       const unsigned int* __restrict__ x2l) {
    __shared__ int is64;
    int t = threadIdx.x;
    if (t == 0) {
        int all0 = 1;
        for (int i = 1; i < 128; i += 2)
            if (x2l[i] != 0u) { all0 = 0; break; }
        is64 = all0;
    }
    __syncthreads();
    if (t < 32)  g_qlen[t] = (int)(is64 ? x1l[2 * t] : x1l[t]);
    if (t < 128) g_klen[t] = (int)(is64 ? x2l[2 * t] : x2l[t]);
}

// ---------------- per-pair V column means (for fully-masked rows) ----------------
__global__ void k_vmean(const float* __restrict__ x2) {
    int p = blockIdx.x, e = threadIdx.x;
    const float* base = x2 + (size_t)p * 262144 + e;
    float s0 = 0.f, s1 = 0.f, s2 = 0.f, s3 = 0.f;
    for (int k = 0; k < 512; k += 4) {
        s0 += base[(k + 0) * 512];
        s1 += base[(k + 1) * 512];
        s2 += base[(k + 2) * 512];
        s3 += base[(k + 3) * 512];
    }
    g_vmean[p * 512 + e] = (s0 + s1 + s2 + s3) * (1.f / 512.f);
}

// ---------------- fp32 -> fp16 hi/lo split ----------------
__global__ void k_cvt(const float* __restrict__ src, __half* __restrict__ hi,
                      __half* __restrict__ lo, int n4) {
    int i = blockIdx.x * blockDim.x + threadIdx.x;
    if (i >= n4) return;
    float4 v = ((const float4*)src)[i];
    __half h0 = __float2half(v.x), h1 = __float2half(v.y);
    __half h2 = __float2half(v.z), h3 = __float2half(v.w);
    __half l0 = __float2half(v.x - __half2float(h0));
    __half l1 = __float2half(v.y - __half2float(h1));
    __half l2 = __float2half(v.z - __half2float(h2));
    __half l3 = __float2half(v.w - __half2float(h3));
    ((__half2*)hi)[2 * i] = __halves2half2(h0, h1);
    ((__half2*)hi)[2 * i + 1] = __halves2half2(h2, h3);
    ((__half2*)lo)[2 * i] = __halves2half2(l0, l1);
    ((__half2*)lo)[2 * i + 1] = __halves2half2(l2, l3);
}

// ---------------- scores: Q@K^T (2-term fp16), masked exp -> fp16 (UNNORM) --------
__global__ __launch_bounds__(256, 2) void k_scores_mma(void) {
    extern __shared__ char smem[];
    uint32_t sb = smem_u32(smem);
    int t = threadIdx.x, lane = t & 31, wid = t >> 5;
    int wm = wid >> 2, wn = wid & 3;
    int p = blockIdx.y, x1i = p & 31;
    int qt = blockIdx.x, q0 = qt * 128;
    int qlen = g_qlen[x1i], klen = g_klen[p];

    bool all_masked = (q0 >= qlen) || (klen == 0);
    int n_nt = all_masked ? 0 : min(4, (klen + 127) >> 7);
    int n_stages = n_nt * 16;

    const char* Qh = (const char*)(g_qh + (size_t)x1i * 262144);
    const char* Ql = (const char*)(g_ql + (size_t)x1i * 262144);
    const char* Kh = (const char*)(g_kh + (size_t)p * 262144);

    float acc[4][4][4];
#pragma unroll
    for (int a = 0; a < 4; a++)
#pragma unroll
        for (int b = 0; b < 4; b++)
#pragma unroll
            for (int c = 0; c < 4; c++) acc[a][b][c] = 0.f;
    float rsum[4][2];
#pragma unroll
    for (int a = 0; a < 4; a++) rsum[a][0] = rsum[a][1] = 0.f;

    auto load_stage = [&](int s) {
        int nt = s >> 4, ec = s & 15;
        uint32_t bb = sb + (s & 1) * SC_STAGE;
#pragma unroll
        for (int h = 0; h < 2; h++) {
            int idx = h * 256 + t;
            int row = idx >> 2, q = (idx & 3) * 16;
            uint32_t dst = row * PITCHB + q;
            size_t asrc = (size_t)(q0 + row) * 1024 + ec * 64 + q;
            size_t bsrc = (size_t)(nt * 128 + row) * 1024 + ec * 64 + q;
            cp_async16(bb + dst, Qh + asrc);
            cp_async16(bb + TILE_B + dst, Ql + asrc);
            cp_async16(bb + 2 * TILE_B + dst, Kh + bsrc);
        }
    };

    if (n_stages > 0) {
        load_stage(0);
        CP_COMMIT();
    }

    __half2* AH = (__half2*)(g_ah + (size_t)p * 262144);

    for (int s = 0; s < n_stages; s++) {
        CP_WAIT(0);
        __syncthreads();
        if (s + 1 < n_stages) {
            load_stage(s + 1);
            CP_COMMIT();
        }
        uint32_t bb = sb + (s & 1) * SC_STAGE;
#pragma unroll
        for (int kk = 0; kk < 2; kk++) {
            uint32_t aBase = bb + (wm * 64 + (lane & 15)) * PITCHB + (lane >> 4) * 16 +
                             kk * 32;
            uint32_t aHi[4][4], aLo[4][4];
#pragma unroll
            for (int mt = 0; mt < 4; mt++) {
                uint32_t ad = aBase + mt * 16 * PITCHB;
                ldm_x4(aHi[mt], ad);
                ldm_x4(aLo[mt], ad + TILE_B);
            }
            uint32_t bBase = bb + 2 * TILE_B +
                             (wn * 32 + ((lane >> 4) & 1) * 8 + (lane & 7)) * PITCHB +
                             ((lane >> 3) & 1) * 16 + kk * 32;
#pragma unroll
            for (int pr = 0; pr < 2; pr++) {
                uint32_t bH[4];
                ldm_x4(bH, bBase + pr * 16 * PITCHB);
#pragma unroll
                for (int mt = 0; mt < 4; mt++)
#pragma unroll
                    for (int n2 = 0; n2 < 2; n2++)
                        mma_f16(acc[mt][pr * 2 + n2], aHi[mt], bH + 2 * n2);
#pragma unroll
                for (int mt = 0; mt < 4; mt++)
#pragma unroll
                    for (int n2 = 0; n2 < 2; n2++)
                        mma_f16(acc[mt][pr * 2 + n2], aLo[mt], bH + 2 * n2);
            }
        }
        if ((s & 15) == 15) {
            int nt = s >> 4;
            int nb = nt * 128 + wn * 32;
#pragma unroll
            for (int mt = 0; mt < 4; mt++) {
                int r0 = q0 + wm * 64 + mt * 16 + (lane >> 2);
                bool fm0 = (r0 >= qlen);
                bool fm1 = ((r0 + 8) >= qlen);
#pragma unroll
                for (int ntl = 0; ntl < 4; ntl++) {
                    int col = nb + ntl * 8 + (lane & 3) * 2;
                    float* cc = acc[mt][ntl];
                    float e0 = fm0 ? 1.f : ((col < klen) ? __expf(cc[0] * SCALE_F) : 0.f);
                    float e1 = fm0 ? 1.f : ((col + 1 < klen) ? __expf(cc[1] * SCALE_F) : 0.f);
                    float e2 = fm1 ? 1.f : ((col < klen) ? __expf(cc[2] * SCALE_F) : 0.f);
                    float e3 = fm1 ? 1.f : ((col + 1 < klen) ? __expf(cc[3] * SCALE_F) : 0.f);
                    rsum[mt][0] += e0 + e1;
                    rsum[mt][1] += e2 + e3;
                    AH[((size_t)r0 * 512 + col) >> 1] = __floats2half2_rn(e0, e1);
                    AH[((size_t)(r0 + 8) * 512 + col) >> 1] = __floats2half2_rn(e2, e3);
                    cc[0] = cc[1] = cc[2] = cc[3] = 0.f;
                }
            }
        }
    }

    // fill skipped 128-col blocks: masked rows -> exp 1, live rows -> 0
    {
        __half* AHB = g_ah + (size_t)p * 262144;
        const uint32_t ONE2 = 0x3C003C00u;
        uint4 vone = make_uint4(ONE2, ONE2, ONE2, ONE2);
        uint4 vzer = make_uint4(0u, 0u, 0u, 0u);
        for (int nt = n_nt; nt < 4; nt++) {
            for (int i = t; i < 2048; i += 256) {
                int row = i >> 4, c8 = (i & 15) * 8;
                bool mr = all_masked || ((q0 + row) >= qlen);
                size_t o = (size_t)(q0 + row) * 512 + nt * 128 + c8;
                *(uint4*)(AHB + o) = mr ? vone : vzer;
            }
        }
    }

    __syncthreads();
    float* rs = (float*)(smem + RS_OFF);
#pragma unroll
    for (int mt = 0; mt < 4; mt++)
#pragma unroll
        for (int ri = 0; ri < 2; ri++) {
            float v = rsum[mt][ri];
            v += __shfl_xor_sync(0xffffffffu, v, 1);
            v += __shfl_xor_sync(0xffffffffu, v, 2);
            if ((lane & 3) == 0)
                rs[(wm * 64 + mt * 16 + ri * 8 + (lane >> 2)) * 4 + wn] = v;
        }
    __syncthreads();
    if (t < 128) {
        float s = rs[t * 4] + rs[t * 4 + 1] + rs[t * 4 + 2] + rs[t * 4 + 3];
        bool mr = all_masked || ((q0 + t) >= qlen);
        s += (float)(4 - n_nt) * 128.f * (mr ? 1.f : 0.f);
        g_rowsum[p * 512 + q0 + t] = s;
    }
}

// ---------------- normalize: fp32 attn output from fp16 exp + rowsum --------------
__global__ void k_norm(float* __restrict__ attn) {
    int row = blockIdx.x;
    int t = threadIdx.x;
    float s = g_rowsum[row];
    float inv = s > 0.f ? 1.f / s : 0.f;
    const __half2* hp = (const __half2*)(g_ah + (size_t)row * 512);
    float2 f0 = __half22float2(hp[2 * t]);
    float2 f1 = __half22float2(hp[2 * t + 1]);
    float4 v;
    v.x = f0.x * inv;
    v.y = f0.y * inv;
    v.z = f1.x * inv;
    v.w = f1.y * inv;
    ((float4*)(attn + (size_t)row * 512))[t] = v;
}

// ---------------- x1_att = exp @ V / rowsum (1-term fp16); emits cat fp16 ----------
__global__ __launch_bounds__(256, 2) void k_av_mma(const float* __restrict__ x1) {
    extern __shared__ char smem[];
    uint32_t sb = smem_u32(smem);
    int t = threadIdx.x, lane = t & 31, wid = t >> 5;
    int wm = wid >> 2, wn = wid & 3;
    int p = blockIdx.z, x1i = p & 31;
    int q0 = blockIdx.y * 128, e0 = blockIdx.x * 128;
    int qlen = g_qlen[x1i], klen = g_klen[p];

    bool all_masked = (q0 >= qlen) || (klen == 0);
    int n_stage = all_masked ? 0 : min(16, (klen + 31) >> 5);

    const char* Ah = (const char*)(g_ah + (size_t)p * 262144);
    const char* Vh = (const char*)(g_kh + (size_t)p * 262144);

    float acc[4][4][4];
#pragma unroll
    for (int a = 0; a < 4; a++)
#pragma unroll
        for (int b = 0; b < 4; b++)
#pragma unroll
            for (int c = 0; c < 4; c++) acc[a][b][c] = 0.f;

    auto load_stage = [&](int s) {
        uint32_t bb = sb + (s & 1) * AV_STAGE;
#pragma unroll
        for (int h = 0; h < 2; h++) {
            int idx = h * 256 + t;
            int row = idx >> 2, ch = idx & 3;
            size_t off = (size_t)(q0 + row) * 1024 + s * 64 + ch * 16;
            cp_async16(bb + row * 80 + ch * 16, Ah + off);
        }
#pragma unroll
        for (int h = 0; h < 2; h++) {
            int idx = h * 256 + t;
            int row = idx >> 4, ch = idx & 15;
            size_t off = (size_t)(s * 32 + row) * 1024 + e0 * 2 + ch * 16;
            cp_async16(bb + AV_A_SZ + row * 272 + ch * 16, Vh + off);
        }
    };

    if (n_stage > 0) {
        load_stage(0);
        CP_COMMIT();
    }

    for (int s = 0; s < n_stage; s++) {
        CP_WAIT(0);
        __syncthreads();
        if (s + 1 < n_stage) {
            load_stage(s + 1);
            CP_COMMIT();
        }
        uint32_t bb = sb + (s & 1) * AV_STAGE;
#pragma unroll
        for (int kk = 0; kk < 2; kk++) {
            uint32_t aBase = bb + (wm * 64 + (lane & 15)) * 80 + (lane >> 4) * 16 + kk * 32;
            uint32_t aHi[4][4];
#pragma unroll
            for (int mt = 0; mt < 4; mt++)
                ldm_x4(aHi[mt], aBase + mt * 16 * 80);
            uint32_t bBase = bb + AV_A_SZ + (kk * 16 + (lane & 15)) * 272 + wn * 64 +
                             ((lane >> 4) & 1) * 16;
#pragma unroll
            for (int pr = 0; pr < 2; pr++) {
                uint32_t bH[4];
                ldm_x4t(bH, bBase + pr * 32);
#pragma unroll
                for (int mt = 0; mt < 4; mt++)
#pragma unroll
                    for (int n2 = 0; n2 < 2; n2++)
                        mma_f16(acc[mt][pr * 2 + n2], aHi[mt], bH + 2 * n2);
            }
        }
    }

    // epilogue: xa = acc/rowsum (masked rows: colmean V) -> (x1-xa, x1*xa) fp16 hi/lo
    const float* X1 = x1 + (size_t)x1i * 262144;
    const float* VM = g_vmean + p * 512;
    __half2* Sh = (__half2*)(g_sh + (size_t)p * 262144);
    __half2* Sl = (__half2*)(g_sl + (size_t)p * 262144);
    __half2* Mh = (__half2*)(g_mh + (size_t)p * 262144);
    __half2* Ml = (__half2*)(g_ml + (size_t)p * 262144);
#pragma unroll
    for (int mt = 0; mt < 4; mt++) {
#pragma unroll
        for (int hh = 0; hh < 2; hh++) {
            int r = q0 + wm * 64 + mt * 16 + (lane >> 2) + hh * 8;
            bool mr = all_masked || (r >= qlen);
            float inv = 0.f;
            if (!mr) inv = 1.f / g_rowsum[p * 512 + r];
#pragma unroll
            for (int ntl = 0; ntl < 4; ntl++) {
                float* cc = acc[mt][ntl];
                int c = e0 + wn * 32 + ntl * 8 + (lane & 3) * 2;
                float2 u = *(const float2*)(X1 + (size_t)r * 512 + c);
                float xa0, xa1;
                if (mr) {
                    float2 vm = *(const float2*)(VM + c);
                    xa0 = vm.x;
                    xa1 = vm.y;
                } else {
                    xa0 = cc[hh * 2] * inv;
                    xa1 = cc[hh * 2 + 1] * inv;
                }
                float s0 = u.x - xa0, s1 = u.y - xa1;
                float m0 = u.x * xa0, m1 = u.y * xa1;
                size_t o = ((size_t)r * 512 + c) >> 1;
                __half h0 = __float2half(s0), h1 = __float2half(s1);
                Sh[o] = __halves2half2(h0, h1);
                Sl[o] = __halves2half2(__float2half(s0 - __half2float(h0)),
                                       __float2half(s1 - __half2float(h1)));
                h0 = __float2half(m0); h1 = __float2half(m1);
                Mh[o] = __halves2half2(h0, h1);
                Ml[o] = __halves2half2(__float2half(m0 - __half2float(h0)),
                                       __float2half(m1 - __half2float(h1)));
            }
        }
    }
}

// ---------------- fusion GEMM (2-term fp16) + bias/relu + partial pooling ----------
__global__ __launch_bounds__(256, 2) void k_fusion_mma(const float* __restrict__ fb) {
    extern __shared__ char smem[];
    uint32_t sb = smem_u32(smem);
    int t = threadIdx.x, lane = t & 31, wid = t >> 5;
    int wm = wid >> 2, wn = wid & 3;
    int p = blockIdx.z;
    int qt = blockIdx.y, q0 = qt * 128, e0 = blockIdx.x * 128;

    const char* Sh = (const char*)(g_sh + (size_t)p * 262144);
    const char* Sl = (const char*)(g_sl + (size_t)p * 262144);
    const char* Mh = (const char*)(g_mh + (size_t)p * 262144);
    const char* Ml = (const char*)(g_ml + (size_t)p * 262144);
    const char* Wh = (const char*)g_fwh;

    float acc[4][4][4];
#pragma unroll
    for (int a = 0; a < 4; a++)
#pragma unroll
        for (int b = 0; b < 4; b++)
#pragma unroll
            for (int c = 0; c < 4; c++) acc[a][b][c] = 0.f;

    auto load_stage = [&](int s) {
        uint32_t bb = sb + (s & 1) * FU_STAGE;
        const char* ah = (s < 16) ? Sh : Mh;
        const char* al = (s < 16) ? Sl : Ml;
        int kc = (s & 15) * 64;
#pragma unroll
        for (int h = 0; h < 2; h++) {
            int idx = h * 256 + t;
            int row = idx >> 2, ch = idx & 3;
            uint32_t d = bb + row * 80 + ch * 16;
            size_t off = (size_t)(q0 + row) * 1024 + kc + ch * 16;
            cp_async16(d, ah + off);
            cp_async16(d + AV_A_SZ, al + off);
        }
#pragma unroll
        for (int h = 0; h < 2; h++) {
            int idx = h * 256 + t;
            int row = idx >> 4, ch = idx & 15;
            size_t off = (size_t)(s * 32 + row) * 1024 + e0 * 2 + ch * 16;
            cp_async16(bb + FU_W_OFF + row * 272 + ch * 16, Wh + off);
        }
    };

    load_stage(0);
    CP_COMMIT();

    for (int s = 0; s < 32; s++) {
        CP_WAIT(0);
        __syncthreads();
        if (s + 1 < 32) {
            load_stage(s + 1);
            CP_COMMIT();
        }
        uint32_t bb = sb + (s & 1) * FU_STAGE;
#pragma unroll
        for (int kk = 0; kk < 2; kk++) {
            uint32_t aBase = bb + (wm * 64 + (lane & 15)) * 80 + (lane >> 4) * 16 + kk * 32;
            uint32_t aHi[4][4], aLo[4][4];
#pragma unroll
            for (int mt = 0; mt < 4; mt++) {
                uint32_t ad = aBase + mt * 16 * 80;
                ldm_x4(aHi[mt], ad);
                ldm_x4(aLo[mt], ad + AV_A_SZ);
            }
            uint32_t bBase = bb + FU_W_OFF + (kk * 16 + (lane & 15)) * 272 + wn * 64 +
                             ((lane >> 4) & 1) * 16;
#pragma unroll
            for (int pr = 0; pr < 2; pr++) {
                uint32_t bH[4];
                ldm_x4t(bH, bBase + pr * 32);
#pragma unroll
                for (int mt = 0; mt < 4; mt++)
#pragma unroll
                    for (int n2 = 0; n2 < 2; n2++)
                        mma_f16(acc[mt][pr * 2 + n2], aHi[mt], bH + 2 * n2);
#pragma unroll
                for (int mt = 0; mt < 4; mt++)
#pragma unroll
                    for (int n2 = 0; n2 < 2; n2++)
                        mma_f16(acc[mt][pr * 2 + n2], aLo[mt], bH + 2 * n2);
            }
        }
    }

    // bias + relu + pool over this block's 128 rows
    float psum[4][2], pmax[4][2];
#pragma unroll
    for (int ntl = 0; ntl < 4; ntl++) {
        psum[ntl][0] = psum[ntl][1] = 0.f;
        pmax[ntl][0] = pmax[ntl][1] = 0.f;
    }
#pragma unroll
    for (int ntl = 0; ntl < 4; ntl++) {
        int c = e0 + wn * 32 + ntl * 8 + (lane & 3) * 2;
        float b0 = fb[c], b1 = fb[c + 1];
#pragma unroll
        for (int mt = 0; mt < 4; mt++) {
            float* cc = acc[mt][ntl];
            float v0 = fmaxf(cc[0] + b0, 0.f);
            float v1 = fmaxf(cc[1] + b1, 0.f);
            float v2 = fmaxf(cc[2] + b0, 0.f);
            float v3 = fmaxf(cc[3] + b1, 0.f);
            psum[ntl][0] += v0 + v2;
            psum[ntl][1] += v1 + v3;
            pmax[ntl][0] = fmaxf(pmax[ntl][0], fmaxf(v0, v2));
            pmax[ntl][1] = fmaxf(pmax[ntl][1], fmaxf(v1, v3));
        }
    }
    __syncthreads();
    float* redS = (float*)(smem + FU_RED_OFF);
    float* redM = redS + 256;
#pragma unroll
    for (int ntl = 0; ntl < 4; ntl++)
#pragma unroll
        for (int j = 0; j < 2; j++) {
            float s = psum[ntl][j], m = pmax[ntl][j];
            s += __shfl_xor_sync(0xffffffffu, s, 4);
            s += __shfl_xor_sync(0xffffffffu, s, 8);
            s += __shfl_xor_sync(0xffffffffu, s, 16);
            m = fmaxf(m, __shfl_xor_sync(0xffffffffu, m, 4));
            m = fmaxf(m, __shfl_xor_sync(0xffffffffu, m, 8));
            m = fmaxf(m, __shfl_xor_sync(0xffffffffu, m, 16));
            if (lane < 4) {
                int col = wn * 32 + ntl * 8 + lane * 2 + j;
                redS[wm * 128 + col] = s;
                redM[wm * 128 + col] = m;
            }
        }
    __syncthreads();
    if (t < 128) {
        float s = redS[t] + redS[128 + t];
        float m = fmaxf(redM[t], redM[128 + t]);
        int idx = (p * 4 + qt) * 512 + e0 + t;
        g_psum[idx] = s;
        g_pmax[idx] = m;
    }
}

// ---------------- pool finalize ----------------
__global__ void k_pool(void) {
    int p = blockIdx.x, e = threadIdx.x;
    float s = 0.f, m = 0.f;
#pragma unroll
    for (int qt = 0; qt < 4; qt++) {
        int idx = (p * 4 + qt) * 512 + e;
        s += g_psum[idx];
        m = fmaxf(m, g_pmax[idx]);
    }
    int base = (p >> 2) * 4096 + (p & 3) * 512 + e;
    g_pooled[base] = s * (1.0f / 512.0f);
    g_pooled[base + 2048] = m;
}

// ---------------- out = relu(pooled @ out_w + out_b) ----------------
__global__ __launch_bounds__(256) void k_out(const float* __restrict__ ow,
                                             const float* __restrict__ ob,
                                             float* __restrict__ outp) {
    __shared__ float sp[4096];
    int b = blockIdx.x, t = threadIdx.x;
    for (int i = t; i < 4096; i += 256) sp[i] = g_pooled[b * 4096 + i];
    __syncthreads();
    int col = t * 4;
    float4 acc = *(const float4*)(ob + col);
#pragma unroll 8
    for (int c = 0; c < 4096; c++) {
        float pv = sp[c];
        float4 w = *(const float4*)(ow + (size_t)c * 1024 + col);
        acc.x += pv * w.x;
        acc.y += pv * w.y;
        acc.z += pv * w.z;
        acc.w += pv * w.w;
    }
    acc.x = fmaxf(acc.x, 0.f);
    acc.y = fmaxf(acc.y, 0.f);
    acc.z = fmaxf(acc.z, 0.f);
    acc.w = fmaxf(acc.w, 0.f);
    *(float4*)(outp + b * 1024 + col) = acc;
}

extern "C" void kernel_launch(void* const* d_in, const int* in_sizes, int n_in,
                              void* d_out, int out_size) {
    const float* x1 = (const float*)d_in[0];
    const float* x2 = (const float*)d_in[1];
    const unsigned int* x1_len = (const unsigned int*)d_in[2];
    const unsigned int* x2_len = (const unsigned int*)d_in[3];
    const float* fw = (const float*)d_in[4];
    const float* fb = (const float*)d_in[5];
    const float* ow = (const float*)d_in[6];
    const float* ob = (const float*)d_in[7];

    float* outp = (float*)d_out;
    float* attn;
    if (out_size >= OUT_ELEMS + ATTN_ELEMS) {
        attn = outp + OUT_ELEMS;
    } else if (out_size >= ATTN_ELEMS) {
        attn = outp;
        void* dp = nullptr;
        cudaGetSymbolAddress(&dp, g_out_dummy);
        outp = (float*)dp;
    } else {
        void* dp = nullptr;
        cudaGetSymbolAddress(&dp, g_attn_scratch);
        attn = (float*)dp;
    }

    void *qh, *ql, *kh, *kl, *fwh, *fwl;
    cudaGetSymbolAddress(&qh, g_qh);
    cudaGetSymbolAddress(&ql, g_ql);
    cudaGetSymbolAddress(&kh, g_kh);
    cudaGetSymbolAddress(&kl, g_kl);
    cudaGetSymbolAddress(&fwh, g_fwh);
    cudaGetSymbolAddress(&fwl, g_fwl);

    cudaFuncSetAttribute(k_scores_mma, cudaFuncAttributeMaxDynamicSharedMemorySize, SC_SMEM);
    cudaFuncSetAttribute(k_av_mma, cudaFuncAttributeMaxDynamicSharedMemorySize, AV_SMEM);
    cudaFuncSetAttribute(k_fusion_mma, cudaFuncAttributeMaxDynamicSharedMemorySize, FU_SMEM);

    k_lens<<<1, 128>>>(x1_len, x2_len);
    k_vmean<<<NPAIR, 512>>>(x2);
    k_cvt<<<8192, 256>>>(x1, (__half*)qh, (__half*)ql, 2097152);
    k_cvt<<<32768, 256>>>(x2, (__half*)kh, (__half*)kl, 8388608);
    k_cvt<<<512, 256>>>(fw, (__half*)fwh, (__half*)fwl, 131072);
    k_scores_mma<<<dim3(4, NPAIR), 256, SC_SMEM>>>();
    k_norm<<<NPAIR * CL, 128>>>(attn);
    k_av_mma<<<dim3(4, 4, NPAIR), 256, AV_SMEM>>>(x1);
    k_fusion_mma<<<dim3(4, 4, NPAIR), 256, FU_SMEM>>>(fb);
    k_pool<<<NPAIR, 512>>>();
    k_out<<<NB, 256>>>(ow, ob, outp);
}

// round 11
// speedup vs baseline: 3.5376x; 1.1647x over previous
#include <cuda_runtime.h>
#include <cuda_fp16.h>
#include <cstdint>

#define CL 512
#define CE 512
#define NPAIR 128
#define NB 32
#define ATTN_ELEMS (NPAIR * CL * CL)
#define OUT_ELEMS (NB * 1024)
#define SCALE_F 0.044194173824159216f

// ---------------- scratch (device globals; alloc-free rule) ----------------
__device__ float g_pooled[NB * 4096];
__device__ float g_attn_scratch[ATTN_ELEMS];
__device__ float g_out_dummy[OUT_ELEMS];
__device__ float g_rowsum[NPAIR * CL];
__device__ float g_psum[4 * NPAIR * CL];
__device__ float g_pmax[4 * NPAIR * CL];
__device__ float g_vmean[NPAIR * CE];
__device__ int g_qlen[32];
__device__ int g_klen[128];
__device__ __half g_qh[NB * CL * CE];     // x1 fp16 hi
__device__ __half g_ql[NB * CL * CE];     // x1 fp16 lo
__device__ __half g_kh[NPAIR * CL * CE];  // x2 fp16 (single)
__device__ __half g_ah[NPAIR * CL * CL];  // UNNORMALIZED exp (fp16 single)
__device__ __half g_sh[NPAIR * CL * CE];  // x1 - xa (fp16 single)
__device__ __half g_mh[NPAIR * CL * CE];  // x1 * xa (fp16 single)
__device__ __half g_fwh[1024 * 512];      // fusion_w fp16 (single)

// ---------------- PTX helpers ----------------
__device__ __forceinline__ uint32_t smem_u32(const void* p) {
    uint32_t a;
    asm("{ .reg .u64 t; cvta.to.shared.u64 t, %1; cvt.u32.u64 %0, t; }" : "=r"(a) : "l"(p));
    return a;
}
__device__ __forceinline__ void cp_async16(uint32_t dst, const void* src) {
    asm volatile("cp.async.ca.shared.global [%0], [%1], 16;" :: "r"(dst), "l"(src));
}
#define CP_COMMIT() asm volatile("cp.async.commit_group;" ::: "memory")
#define CP_WAIT(n)  asm volatile("cp.async.wait_group %0;" :: "n"(n) : "memory")

__device__ __forceinline__ void ldm_x4(uint32_t* r, uint32_t addr) {
    asm volatile("ldmatrix.sync.aligned.m8n8.x4.shared.b16 {%0,%1,%2,%3}, [%4];"
                 : "=r"(r[0]), "=r"(r[1]), "=r"(r[2]), "=r"(r[3]) : "r"(addr));
}
__device__ __forceinline__ void ldm_x4t(uint32_t* r, uint32_t addr) {
    asm volatile("ldmatrix.sync.aligned.m8n8.x4.trans.shared.b16 {%0,%1,%2,%3}, [%4];"
                 : "=r"(r[0]), "=r"(r[1]), "=r"(r[2]), "=r"(r[3]) : "r"(addr));
}
__device__ __forceinline__ void mma_f16(float* c, const uint32_t* a, const uint32_t* b) {
    asm volatile(
        "mma.sync.aligned.m16n8k16.row.col.f32.f16.f16.f32 "
        "{%0,%1,%2,%3}, {%4,%5,%6,%7}, {%8,%9}, {%0,%1,%2,%3};"
        : "+f"(c[0]), "+f"(c[1]), "+f"(c[2]), "+f"(c[3])
        : "r"(a[0]), "r"(a[1]), "r"(a[2]), "r"(a[3]), "r"(b[0]), "r"(b[1]));
}

// ---------------- smem geometry ----------------
#define PITCHB 80
#define TILE_B (128 * PITCHB)           // 10240
// scores: A_hi + A_lo + B per stage
#define SC_STAGE (3 * TILE_B)           // 30720
#define RS_OFF (2 * SC_STAGE)           // 61440
#define SC_SMEM (RS_OFF + 2048)
// av / fusion: A + B per stage
#define AV_A_SZ (128 * 80)              // 10240
#define AV_V_SZ (32 * 272)              // 8704
#define AV_STAGE (AV_A_SZ + AV_V_SZ)    // 18944
#define AV_SMEM (2 * AV_STAGE)
#define FU_RED_OFF AV_SMEM              // 37888
#define FU_SMEM (FU_RED_OFF + 2048)

// ---------------- length normalization ----------------
__global__ void k_lens(const unsigned int* __restrict__ x1l,
                       const unsigned int* __restrict__ x2l) {
    __shared__ int is64;
    int t = threadIdx.x;
    if (t == 0) {
        int all0 = 1;
        for (int i = 1; i < 128; i += 2)
            if (x2l[i] != 0u) { all0 = 0; break; }
        is64 = all0;
    }
    __syncthreads();
    if (t < 32)  g_qlen[t] = (int)(is64 ? x1l[2 * t] : x1l[t]);
    if (t < 128) g_klen[t] = (int)(is64 ? x2l[2 * t] : x2l[t]);
}

// ---------------- per-pair V column means (for fully-masked rows) ----------------
__global__ void k_vmean(const float* __restrict__ x2) {
    int p = blockIdx.x, e = threadIdx.x;
    const float* base = x2 + (size_t)p * 262144 + e;
    float s0 = 0.f, s1 = 0.f, s2 = 0.f, s3 = 0.f;
    for (int k = 0; k < 512; k += 4) {
        s0 += base[(k + 0) * 512];
        s1 += base[(k + 1) * 512];
        s2 += base[(k + 2) * 512];
        s3 += base[(k + 3) * 512];
    }
    g_vmean[p * 512 + e] = (s0 + s1 + s2 + s3) * (1.f / 512.f);
}

// ---------------- fp32 -> fp16 hi/lo split ----------------
__global__ void k_cvt(const float* __restrict__ src, __half* __restrict__ hi,
                      __half* __restrict__ lo, int n4) {
    int i = blockIdx.x * blockDim.x + threadIdx.x;
    if (i >= n4) return;
    float4 v = ((const float4*)src)[i];
    __half h0 = __float2half(v.x), h1 = __float2half(v.y);
    __half h2 = __float2half(v.z), h3 = __float2half(v.w);
    __half l0 = __float2half(v.x - __half2float(h0));
    __half l1 = __float2half(v.y - __half2float(h1));
    __half l2 = __float2half(v.z - __half2float(h2));
    __half l3 = __float2half(v.w - __half2float(h3));
    ((__half2*)hi)[2 * i] = __halves2half2(h0, h1);
    ((__half2*)hi)[2 * i + 1] = __halves2half2(h2, h3);
    ((__half2*)lo)[2 * i] = __halves2half2(l0, l1);
    ((__half2*)lo)[2 * i + 1] = __halves2half2(l2, l3);
}

// ---------------- fp32 -> fp16 (single) ----------------
__global__ void k_cvt1(const float* __restrict__ src, __half* __restrict__ hi, int n4) {
    int i = blockIdx.x * blockDim.x + threadIdx.x;
    if (i >= n4) return;
    float4 v = ((const float4*)src)[i];
    ((__half2*)hi)[2 * i] = __floats2half2_rn(v.x, v.y);
    ((__half2*)hi)[2 * i + 1] = __floats2half2_rn(v.z, v.w);
}

// ---------------- scores: Q@K^T (2-term fp16), masked exp -> fp16 (UNNORM) --------
__global__ __launch_bounds__(256, 2) void k_scores_mma(void) {
    extern __shared__ char smem[];
    uint32_t sb = smem_u32(smem);
    int t = threadIdx.x, lane = t & 31, wid = t >> 5;
    int wm = wid >> 2, wn = wid & 3;
    int p = blockIdx.y, x1i = p & 31;
    int qt = blockIdx.x, q0 = qt * 128;
    int qlen = g_qlen[x1i], klen = g_klen[p];

    bool all_masked = (q0 >= qlen) || (klen == 0);
    int n_nt = all_masked ? 0 : min(4, (klen + 127) >> 7);
    int n_stages = n_nt * 16;

    const char* Qh = (const char*)(g_qh + (size_t)x1i * 262144);
    const char* Ql = (const char*)(g_ql + (size_t)x1i * 262144);
    const char* Kh = (const char*)(g_kh + (size_t)p * 262144);

    float acc[4][4][4];
#pragma unroll
    for (int a = 0; a < 4; a++)
#pragma unroll
        for (int b = 0; b < 4; b++)
#pragma unroll
            for (int c = 0; c < 4; c++) acc[a][b][c] = 0.f;
    float rsum[4][2];
#pragma unroll
    for (int a = 0; a < 4; a++) rsum[a][0] = rsum[a][1] = 0.f;

    auto load_stage = [&](int s) {
        int nt = s >> 4, ec = s & 15;
        uint32_t bb = sb + (s & 1) * SC_STAGE;
#pragma unroll
        for (int h = 0; h < 2; h++) {
            int idx = h * 256 + t;
            int row = idx >> 2, q = (idx & 3) * 16;
            uint32_t dst = row * PITCHB + q;
            size_t asrc = (size_t)(q0 + row) * 1024 + ec * 64 + q;
            size_t bsrc = (size_t)(nt * 128 + row) * 1024 + ec * 64 + q;
            cp_async16(bb + dst, Qh + asrc);
            cp_async16(bb + TILE_B + dst, Ql + asrc);
            cp_async16(bb + 2 * TILE_B + dst, Kh + bsrc);
        }
    };

    if (n_stages > 0) {
        load_stage(0);
        CP_COMMIT();
    }

    __half2* AH = (__half2*)(g_ah + (size_t)p * 262144);

    for (int s = 0; s < n_stages; s++) {
        CP_WAIT(0);
        __syncthreads();
        if (s + 1 < n_stages) {
            load_stage(s + 1);
            CP_COMMIT();
        }
        uint32_t bb = sb + (s & 1) * SC_STAGE;
#pragma unroll
        for (int kk = 0; kk < 2; kk++) {
            uint32_t aBase = bb + (wm * 64 + (lane & 15)) * PITCHB + (lane >> 4) * 16 +
                             kk * 32;
            uint32_t aHi[4][4], aLo[4][4];
#pragma unroll
            for (int mt = 0; mt < 4; mt++) {
                uint32_t ad = aBase + mt * 16 * PITCHB;
                ldm_x4(aHi[mt], ad);
                ldm_x4(aLo[mt], ad + TILE_B);
            }
            uint32_t bBase = bb + 2 * TILE_B +
                             (wn * 32 + ((lane >> 4) & 1) * 8 + (lane & 7)) * PITCHB +
                             ((lane >> 3) & 1) * 16 + kk * 32;
#pragma unroll
            for (int pr = 0; pr < 2; pr++) {
                uint32_t bH[4];
                ldm_x4(bH, bBase + pr * 16 * PITCHB);
#pragma unroll
                for (int mt = 0; mt < 4; mt++)
#pragma unroll
                    for (int n2 = 0; n2 < 2; n2++)
                        mma_f16(acc[mt][pr * 2 + n2], aHi[mt], bH + 2 * n2);
#pragma unroll
                for (int mt = 0; mt < 4; mt++)
#pragma unroll
                    for (int n2 = 0; n2 < 2; n2++)
                        mma_f16(acc[mt][pr * 2 + n2], aLo[mt], bH + 2 * n2);
            }
        }
        if ((s & 15) == 15) {
            int nt = s >> 4;
            int nb = nt * 128 + wn * 32;
#pragma unroll
            for (int mt = 0; mt < 4; mt++) {
                int r0 = q0 + wm * 64 + mt * 16 + (lane >> 2);
                bool fm0 = (r0 >= qlen);
                bool fm1 = ((r0 + 8) >= qlen);
#pragma unroll
                for (int ntl = 0; ntl < 4; ntl++) {
                    int col = nb + ntl * 8 + (lane & 3) * 2;
                    float* cc = acc[mt][ntl];
                    float e0 = fm0 ? 1.f : ((col < klen) ? __expf(cc[0] * SCALE_F) : 0.f);
                    float e1 = fm0 ? 1.f : ((col + 1 < klen) ? __expf(cc[1] * SCALE_F) : 0.f);
                    float e2 = fm1 ? 1.f : ((col < klen) ? __expf(cc[2] * SCALE_F) : 0.f);
                    float e3 = fm1 ? 1.f : ((col + 1 < klen) ? __expf(cc[3] * SCALE_F) : 0.f);
                    rsum[mt][0] += e0 + e1;
                    rsum[mt][1] += e2 + e3;
                    AH[((size_t)r0 * 512 + col) >> 1] = __floats2half2_rn(e0, e1);
                    AH[((size_t)(r0 + 8) * 512 + col) >> 1] = __floats2half2_rn(e2, e3);
                    cc[0] = cc[1] = cc[2] = cc[3] = 0.f;
                }
            }
        }
    }

    // fill skipped 128-col blocks: masked rows -> exp 1, live rows -> 0
    {
        __half* AHB = g_ah + (size_t)p * 262144;
        const uint32_t ONE2 = 0x3C003C00u;
        uint4 vone = make_uint4(ONE2, ONE2, ONE2, ONE2);
        uint4 vzer = make_uint4(0u, 0u, 0u, 0u);
        for (int nt = n_nt; nt < 4; nt++) {
            for (int i = t; i < 2048; i += 256) {
                int row = i >> 4, c8 = (i & 15) * 8;
                bool mr = all_masked || ((q0 + row) >= qlen);
                size_t o = (size_t)(q0 + row) * 512 + nt * 128 + c8;
                *(uint4*)(AHB + o) = mr ? vone : vzer;
            }
        }
    }

    __syncthreads();
    float* rs = (float*)(smem + RS_OFF);
#pragma unroll
    for (int mt = 0; mt < 4; mt++)
#pragma unroll
        for (int ri = 0; ri < 2; ri++) {
            float v = rsum[mt][ri];
            v += __shfl_xor_sync(0xffffffffu, v, 1);
            v += __shfl_xor_sync(0xffffffffu, v, 2);
            if ((lane & 3) == 0)
                rs[(wm * 64 + mt * 16 + ri * 8 + (lane >> 2)) * 4 + wn] = v;
        }
    __syncthreads();
    if (t < 128) {
        float s = rs[t * 4] + rs[t * 4 + 1] + rs[t * 4 + 2] + rs[t * 4 + 3];
        bool mr = all_masked || ((q0 + t) >= qlen);
        s += (float)(4 - n_nt) * 128.f * (mr ? 1.f : 0.f);
        g_rowsum[p * 512 + q0 + t] = s;
    }
}

// ---------------- normalize: fp32 attn output from fp16 exp + rowsum --------------
__global__ void k_norm(float* __restrict__ attn) {
    int row = blockIdx.x;
    int t = threadIdx.x;
    float s = g_rowsum[row];
    float inv = s > 0.f ? 1.f / s : 0.f;
    const __half2* hp = (const __half2*)(g_ah + (size_t)row * 512);
    float2 f0 = __half22float2(hp[2 * t]);
    float2 f1 = __half22float2(hp[2 * t + 1]);
    float4 v;
    v.x = f0.x * inv;
    v.y = f0.y * inv;
    v.z = f1.x * inv;
    v.w = f1.y * inv;
    ((float4*)(attn + (size_t)row * 512))[t] = v;
}

// ---------------- x1_att = exp @ V / rowsum (1-term fp16); emits cat fp16 ----------
__global__ __launch_bounds__(256, 2) void k_av_mma(const float* __restrict__ x1) {
    extern __shared__ char smem[];
    uint32_t sb = smem_u32(smem);
    int t = threadIdx.x, lane = t & 31, wid = t >> 5;
    int wm = wid >> 2, wn = wid & 3;
    int p = blockIdx.z, x1i = p & 31;
    int q0 = blockIdx.y * 128, e0 = blockIdx.x * 128;
    int qlen = g_qlen[x1i], klen = g_klen[p];

    bool all_masked = (q0 >= qlen) || (klen == 0);
    int n_stage = all_masked ? 0 : min(16, (klen + 31) >> 5);

    const char* Ah = (const char*)(g_ah + (size_t)p * 262144);
    const char* Vh = (const char*)(g_kh + (size_t)p * 262144);

    float acc[4][4][4];
#pragma unroll
    for (int a = 0; a < 4; a++)
#pragma unroll
        for (int b = 0; b < 4; b++)
#pragma unroll
            for (int c = 0; c < 4; c++) acc[a][b][c] = 0.f;

    auto load_stage = [&](int s) {
        uint32_t bb = sb + (s & 1) * AV_STAGE;
#pragma unroll
        for (int h = 0; h < 2; h++) {
            int idx = h * 256 + t;
            int row = idx >> 2, ch = idx & 3;
            size_t off = (size_t)(q0 + row) * 1024 + s * 64 + ch * 16;
            cp_async16(bb + row * 80 + ch * 16, Ah + off);
        }
#pragma unroll
        for (int h = 0; h < 2; h++) {
            int idx = h * 256 + t;
            int row = idx >> 4, ch = idx & 15;
            size_t off = (size_t)(s * 32 + row) * 1024 + e0 * 2 + ch * 16;
            cp_async16(bb + AV_A_SZ + row * 272 + ch * 16, Vh + off);
        }
    };

    if (n_stage > 0) {
        load_stage(0);
        CP_COMMIT();
    }

    for (int s = 0; s < n_stage; s++) {
        CP_WAIT(0);
        __syncthreads();
        if (s + 1 < n_stage) {
            load_stage(s + 1);
            CP_COMMIT();
        }
        uint32_t bb = sb + (s & 1) * AV_STAGE;
#pragma unroll
        for (int kk = 0; kk < 2; kk++) {
            uint32_t aBase = bb + (wm * 64 + (lane & 15)) * 80 + (lane >> 4) * 16 + kk * 32;
            uint32_t aHi[4][4];
#pragma unroll
            for (int mt = 0; mt < 4; mt++)
                ldm_x4(aHi[mt], aBase + mt * 16 * 80);
            uint32_t bBase = bb + AV_A_SZ + (kk * 16 + (lane & 15)) * 272 + wn * 64 +
                             ((lane >> 4) & 1) * 16;
#pragma unroll
            for (int pr = 0; pr < 2; pr++) {
                uint32_t bH[4];
                ldm_x4t(bH, bBase + pr * 32);
#pragma unroll
                for (int mt = 0; mt < 4; mt++)
#pragma unroll
                    for (int n2 = 0; n2 < 2; n2++)
                        mma_f16(acc[mt][pr * 2 + n2], aHi[mt], bH + 2 * n2);
            }
        }
    }

    // epilogue: xa = acc/rowsum (masked rows: colmean V) -> (x1-xa, x1*xa) fp16
    const float* X1 = x1 + (size_t)x1i * 262144;
    const float* VM = g_vmean + p * 512;
    __half2* Sh = (__half2*)(g_sh + (size_t)p * 262144);
    __half2* Mh = (__half2*)(g_mh + (size_t)p * 262144);
#pragma unroll
    for (int mt = 0; mt < 4; mt++) {
#pragma unroll
        for (int hh = 0; hh < 2; hh++) {
            int r = q0 + wm * 64 + mt * 16 + (lane >> 2) + hh * 8;
            bool mr = all_masked || (r >= qlen);
            float inv = 0.f;
            if (!mr) inv = 1.f / g_rowsum[p * 512 + r];
#pragma unroll
            for (int ntl = 0; ntl < 4; ntl++) {
                float* cc = acc[mt][ntl];
                int c = e0 + wn * 32 + ntl * 8 + (lane & 3) * 2;
                float2 u = *(const float2*)(X1 + (size_t)r * 512 + c);
                float xa0, xa1;
                if (mr) {
                    float2 vm = *(const float2*)(VM + c);
                    xa0 = vm.x;
                    xa1 = vm.y;
                } else {
                    xa0 = cc[hh * 2] * inv;
                    xa1 = cc[hh * 2 + 1] * inv;
                }
                size_t o = ((size_t)r * 512 + c) >> 1;
                Sh[o] = __floats2half2_rn(u.x - xa0, u.y - xa1);
                Mh[o] = __floats2half2_rn(u.x * xa0, u.y * xa1);
            }
        }
    }
}

// ---------------- fusion GEMM (1-term fp16) + bias/relu + partial pooling ----------
__global__ __launch_bounds__(256, 2) void k_fusion_mma(const float* __restrict__ fb) {
    extern __shared__ char smem[];
    uint32_t sb = smem_u32(smem);
    int t = threadIdx.x, lane = t & 31, wid = t >> 5;
    int wm = wid >> 2, wn = wid & 3;
    int p = blockIdx.z;
    int qt = blockIdx.y, q0 = qt * 128, e0 = blockIdx.x * 128;

    const char* Sh = (const char*)(g_sh + (size_t)p * 262144);
    const char* Mh = (const char*)(g_mh + (size_t)p * 262144);
    const char* Wh = (const char*)g_fwh;

    float acc[4][4][4];
#pragma unroll
    for (int a = 0; a < 4; a++)
#pragma unroll
        for (int b = 0; b < 4; b++)
#pragma unroll
            for (int c = 0; c < 4; c++) acc[a][b][c] = 0.f;

    auto load_stage = [&](int s) {
        uint32_t bb = sb + (s & 1) * AV_STAGE;
        const char* ah = (s < 16) ? Sh : Mh;
        int kc = (s & 15) * 64;
#pragma unroll
        for (int h = 0; h < 2; h++) {
            int idx = h * 256 + t;
            int row = idx >> 2, ch = idx & 3;
            size_t off = (size_t)(q0 + row) * 1024 + kc + ch * 16;
            cp_async16(bb + row * 80 + ch * 16, ah + off);
        }
#pragma unroll
        for (int h = 0; h < 2; h++) {
            int idx = h * 256 + t;
            int row = idx >> 4, ch = idx & 15;
            size_t off = (size_t)(s * 32 + row) * 1024 + e0 * 2 + ch * 16;
            cp_async16(bb + AV_A_SZ + row * 272 + ch * 16, Wh + off);
        }
    };

    load_stage(0);
    CP_COMMIT();

    for (int s = 0; s < 32; s++) {
        CP_WAIT(0);
        __syncthreads();
        if (s + 1 < 32) {
            load_stage(s + 1);
            CP_COMMIT();
        }
        uint32_t bb = sb + (s & 1) * AV_STAGE;
#pragma unroll
        for (int kk = 0; kk < 2; kk++) {
            uint32_t aBase = bb + (wm * 64 + (lane & 15)) * 80 + (lane >> 4) * 16 + kk * 32;
            uint32_t aHi[4][4];
#pragma unroll
            for (int mt = 0; mt < 4; mt++)
                ldm_x4(aHi[mt], aBase + mt * 16 * 80);
            uint32_t bBase = bb + AV_A_SZ + (kk * 16 + (lane & 15)) * 272 + wn * 64 +
                             ((lane >> 4) & 1) * 16;
#pragma unroll
            for (int pr = 0; pr < 2; pr++) {
                uint32_t bH[4];
                ldm_x4t(bH, bBase + pr * 32);
#pragma unroll
                for (int mt = 0; mt < 4; mt++)
#pragma unroll
                    for (int n2 = 0; n2 < 2; n2++)
                        mma_f16(acc[mt][pr * 2 + n2], aHi[mt], bH + 2 * n2);
            }
        }
    }

    // bias + relu + pool over this block's 128 rows
    float psum[4][2], pmax[4][2];
#pragma unroll
    for (int ntl = 0; ntl < 4; ntl++) {
        psum[ntl][0] = psum[ntl][1] = 0.f;
        pmax[ntl][0] = pmax[ntl][1] = 0.f;
    }
#pragma unroll
    for (int ntl = 0; ntl < 4; ntl++) {
        int c = e0 + wn * 32 + ntl * 8 + (lane & 3) * 2;
        float b0 = fb[c], b1 = fb[c + 1];
#pragma unroll
        for (int mt = 0; mt < 4; mt++) {
            float* cc = acc[mt][ntl];
            float v0 = fmaxf(cc[0] + b0, 0.f);
            float v1 = fmaxf(cc[1] + b1, 0.f);
            float v2 = fmaxf(cc[2] + b0, 0.f);
            float v3 = fmaxf(cc[3] + b1, 0.f);
            psum[ntl][0] += v0 + v2;
            psum[ntl][1] += v1 + v3;
            pmax[ntl][0] = fmaxf(pmax[ntl][0], fmaxf(v0, v2));
            pmax[ntl][1] = fmaxf(pmax[ntl][1], fmaxf(v1, v3));
        }
    }
    __syncthreads();
    float* redS = (float*)(smem + FU_RED_OFF);
    float* redM = redS + 256;
#pragma unroll
    for (int ntl = 0; ntl < 4; ntl++)
#pragma unroll
        for (int j = 0; j < 2; j++) {
            float s = psum[ntl][j], m = pmax[ntl][j];
            s += __shfl_xor_sync(0xffffffffu, s, 4);
            s += __shfl_xor_sync(0xffffffffu, s, 8);
            s += __shfl_xor_sync(0xffffffffu, s, 16);
            m = fmaxf(m, __shfl_xor_sync(0xffffffffu, m, 4));
            m = fmaxf(m, __shfl_xor_sync(0xffffffffu, m, 8));
            m = fmaxf(m, __shfl_xor_sync(0xffffffffu, m, 16));
            if (lane < 4) {
                int col = wn * 32 + ntl * 8 + lane * 2 + j;
                redS[wm * 128 + col] = s;
                redM[wm * 128 + col] = m;
            }
        }
    __syncthreads();
    if (t < 128) {
        float s = redS[t] + redS[128 + t];
        float m = fmaxf(redM[t], redM[128 + t]);
        int idx = (p * 4 + qt) * 512 + e0 + t;
        g_psum[idx] = s;
        g_pmax[idx] = m;
    }
}

// ---------------- pool finalize ----------------
__global__ void k_pool(void) {
    int p = blockIdx.x, e = threadIdx.x;
    float s = 0.f, m = 0.f;
#pragma unroll
    for (int qt = 0; qt < 4; qt++) {
        int idx = (p * 4 + qt) * 512 + e;
        s += g_psum[idx];
        m = fmaxf(m, g_pmax[idx]);
    }
    int base = (p >> 2) * 4096 + (p & 3) * 512 + e;
    g_pooled[base] = s * (1.0f / 512.0f);
    g_pooled[base + 2048] = m;
}

// ---------------- out = relu(pooled @ out_w + out_b) ----------------
__global__ __launch_bounds__(256) void k_out(const float* __restrict__ ow,
                                             const float* __restrict__ ob,
                                             float* __restrict__ outp) {
    __shared__ float sp[4096];
    int b = blockIdx.x, t = threadIdx.x;
    for (int i = t; i < 4096; i += 256) sp[i] = g_pooled[b * 4096 + i];
    __syncthreads();
    int col = t * 4;
    float4 acc = *(const float4*)(ob + col);
#pragma unroll 8
    for (int c = 0; c < 4096; c++) {
        float pv = sp[c];
        float4 w = *(const float4*)(ow + (size_t)c * 1024 + col);
        acc.x += pv * w.x;
        acc.y += pv * w.y;
        acc.z += pv * w.z;
        acc.w += pv * w.w;
    }
    acc.x = fmaxf(acc.x, 0.f);
    acc.y = fmaxf(acc.y, 0.f);
    acc.z = fmaxf(acc.z, 0.f);
    acc.w = fmaxf(acc.w, 0.f);
    *(float4*)(outp + b * 1024 + col) = acc;
}

extern "C" void kernel_launch(void* const* d_in, const int* in_sizes, int n_in,
                              void* d_out, int out_size) {
    const float* x1 = (const float*)d_in[0];
    const float* x2 = (const float*)d_in[1];
    const unsigned int* x1_len = (const unsigned int*)d_in[2];
    const unsigned int* x2_len = (const unsigned int*)d_in[3];
    const float* fw = (const float*)d_in[4];
    const float* fb = (const float*)d_in[5];
    const float* ow = (const float*)d_in[6];
    const float* ob = (const float*)d_in[7];

    float* outp = (float*)d_out;
    float* attn;
    if (out_size >= OUT_ELEMS + ATTN_ELEMS) {
        attn = outp + OUT_ELEMS;
    } else if (out_size >= ATTN_ELEMS) {
        attn = outp;
        void* dp = nullptr;
        cudaGetSymbolAddress(&dp, g_out_dummy);
        outp = (float*)dp;
    } else {
        void* dp = nullptr;
        cudaGetSymbolAddress(&dp, g_attn_scratch);
        attn = (float*)dp;
    }

    void *qh, *ql, *kh, *fwh;
    cudaGetSymbolAddress(&qh, g_qh);
    cudaGetSymbolAddress(&ql, g_ql);
    cudaGetSymbolAddress(&kh, g_kh);
    cudaGetSymbolAddress(&fwh, g_fwh);

    cudaFuncSetAttribute(k_scores_mma, cudaFuncAttributeMaxDynamicSharedMemorySize, SC_SMEM);
    cudaFuncSetAttribute(k_av_mma, cudaFuncAttributeMaxDynamicSharedMemorySize, AV_SMEM);
    cudaFuncSetAttribute(k_fusion_mma, cudaFuncAttributeMaxDynamicSharedMemorySize, FU_SMEM);

    k_lens<<<1, 128>>>(x1_len, x2_len);
    k_vmean<<<NPAIR, 512>>>(x2);
    k_cvt<<<8192, 256>>>(x1, (__half*)qh, (__half*)ql, 2097152);
    k_cvt1<<<32768, 256>>>(x2, (__half*)kh, 8388608);
    k_cvt1<<<512, 256>>>(fw, (__half*)fwh, 131072);
    k_scores_mma<<<dim3(4, NPAIR), 256, SC_SMEM>>>();
    k_norm<<<NPAIR * CL, 128>>>(attn);
    k_av_mma<<<dim3(4, 4, NPAIR), 256, AV_SMEM>>>(x1);
    k_fusion_mma<<<dim3(4, 4, NPAIR), 256, FU_SMEM>>>(fb);
    k_pool<<<NPAIR, 512>>>();
    k_out<<<NB, 256>>>(ow, ob, outp);
}

// round 12
// speedup vs baseline: 3.7267x; 1.0535x over previous
#include <cuda_runtime.h>
#include <cuda_fp16.h>
#include <cstdint>

#define CL 512
#define CE 512
#define NPAIR 128
#define NB 32
#define ATTN_ELEMS (NPAIR * CL * CL)
#define OUT_ELEMS (NB * 1024)
#define SCALE_F 0.044194173824159216f

// ---------------- scratch (device globals; alloc-free rule) ----------------
__device__ float g_pooled[NB * 4096];
__device__ float g_attn_scratch[ATTN_ELEMS];
__device__ float g_out_dummy[OUT_ELEMS];
__device__ float g_rowsum[NPAIR * CL];
__device__ float g_psum[4 * NPAIR * CL];
__device__ float g_pmax[4 * NPAIR * CL];
__device__ float g_vmean[NPAIR * CE];
__device__ int g_qlen[32];
__device__ int g_klen[128];
__device__ __half g_qh[NB * CL * CE];     // x1 fp16 (single)
__device__ __half g_kh[NPAIR * CL * CE];  // x2 fp16 (single)
__device__ __half g_ah[NPAIR * CL * CL];  // UNNORMALIZED exp (fp16 single)
__device__ __half g_sh[NPAIR * CL * CE];  // x1 - xa (fp16 single)
__device__ __half g_mh[NPAIR * CL * CE];  // x1 * xa (fp16 single)
__device__ __half g_fwh[1024 * 512];      // fusion_w fp16 (single)

// ---------------- PTX helpers ----------------
__device__ __forceinline__ uint32_t smem_u32(const void* p) {
    uint32_t a;
    asm("{ .reg .u64 t; cvta.to.shared.u64 t, %1; cvt.u32.u64 %0, t; }" : "=r"(a) : "l"(p));
    return a;
}
__device__ __forceinline__ void cp_async16(uint32_t dst, const void* src) {
    asm volatile("cp.async.ca.shared.global [%0], [%1], 16;" :: "r"(dst), "l"(src));
}
#define CP_COMMIT() asm volatile("cp.async.commit_group;" ::: "memory")
#define CP_WAIT(n)  asm volatile("cp.async.wait_group %0;" :: "n"(n) : "memory")

__device__ __forceinline__ void ldm_x4(uint32_t* r, uint32_t addr) {
    asm volatile("ldmatrix.sync.aligned.m8n8.x4.shared.b16 {%0,%1,%2,%3}, [%4];"
                 : "=r"(r[0]), "=r"(r[1]), "=r"(r[2]), "=r"(r[3]) : "r"(addr));
}
__device__ __forceinline__ void ldm_x4t(uint32_t* r, uint32_t addr) {
    asm volatile("ldmatrix.sync.aligned.m8n8.x4.trans.shared.b16 {%0,%1,%2,%3}, [%4];"
                 : "=r"(r[0]), "=r"(r[1]), "=r"(r[2]), "=r"(r[3]) : "r"(addr));
}
__device__ __forceinline__ void mma_f16(float* c, const uint32_t* a, const uint32_t* b) {
    asm volatile(
        "mma.sync.aligned.m16n8k16.row.col.f32.f16.f16.f32 "
        "{%0,%1,%2,%3}, {%4,%5,%6,%7}, {%8,%9}, {%0,%1,%2,%3};"
        : "+f"(c[0]), "+f"(c[1]), "+f"(c[2]), "+f"(c[3])
        : "r"(a[0]), "r"(a[1]), "r"(a[2]), "r"(a[3]), "r"(b[0]), "r"(b[1]));
}

// ---------------- smem geometry ----------------
#define PITCHB 80
#define TILE_B (128 * PITCHB)           // 10240
// scores: A + B per stage (1-term)
#define SC_STAGE (2 * TILE_B)           // 20480
#define RS_OFF (2 * SC_STAGE)           // 40960
#define RINV_OFF (RS_OFF + 2048)
#define SC_SMEM (RINV_OFF + 512)
// av / fusion: A + B per stage
#define AV_A_SZ (128 * 80)              // 10240
#define AV_V_SZ (32 * 272)              // 8704
#define AV_STAGE (AV_A_SZ + AV_V_SZ)    // 18944
#define AV_SMEM (2 * AV_STAGE)
#define FU_RED_OFF AV_SMEM              // 37888
#define FU_SMEM (FU_RED_OFF + 2048)

// ---------------- length normalization ----------------
__global__ void k_lens(const unsigned int* __restrict__ x1l,
                       const unsigned int* __restrict__ x2l) {
    __shared__ int is64;
    int t = threadIdx.x;
    if (t == 0) {
        int all0 = 1;
        for (int i = 1; i < 128; i += 2)
            if (x2l[i] != 0u) { all0 = 0; break; }
        is64 = all0;
    }
    __syncthreads();
    if (t < 32)  g_qlen[t] = (int)(is64 ? x1l[2 * t] : x1l[t]);
    if (t < 128) g_klen[t] = (int)(is64 ? x2l[2 * t] : x2l[t]);
}

// ---------------- per-pair V column means (for fully-masked rows) ----------------
__global__ void k_vmean(const float* __restrict__ x2) {
    int p = blockIdx.x, e = threadIdx.x;
    const float* base = x2 + (size_t)p * 262144 + e;
    float s0 = 0.f, s1 = 0.f, s2 = 0.f, s3 = 0.f;
    for (int k = 0; k < 512; k += 4) {
        s0 += base[(k + 0) * 512];
        s1 += base[(k + 1) * 512];
        s2 += base[(k + 2) * 512];
        s3 += base[(k + 3) * 512];
    }
    g_vmean[p * 512 + e] = (s0 + s1 + s2 + s3) * (1.f / 512.f);
}

// ---------------- fp32 -> fp16 (single) ----------------
__global__ void k_cvt1(const float* __restrict__ src, __half* __restrict__ hi, int n4) {
    int i = blockIdx.x * blockDim.x + threadIdx.x;
    if (i >= n4) return;
    float4 v = ((const float4*)src)[i];
    ((__half2*)hi)[2 * i] = __floats2half2_rn(v.x, v.y);
    ((__half2*)hi)[2 * i + 1] = __floats2half2_rn(v.z, v.w);
}

// ---------------- scores: Q@K^T (1-term fp16), masked exp -> fp16 + fp32 attn -----
__global__ __launch_bounds__(256, 2) void k_scores_mma(float* __restrict__ attn) {
    extern __shared__ char smem[];
    uint32_t sb = smem_u32(smem);
    int t = threadIdx.x, lane = t & 31, wid = t >> 5;
    int wm = wid >> 2, wn = wid & 3;
    int p = blockIdx.y, x1i = p & 31;
    int qt = blockIdx.x, q0 = qt * 128;
    int qlen = g_qlen[x1i], klen = g_klen[p];

    bool all_masked = (q0 >= qlen) || (klen == 0);
    int n_nt = all_masked ? 0 : min(4, (klen + 127) >> 7);
    int n_stages = n_nt * 16;

    const char* Qh = (const char*)(g_qh + (size_t)x1i * 262144);
    const char* Kh = (const char*)(g_kh + (size_t)p * 262144);

    float acc[4][4][4];
#pragma unroll
    for (int a = 0; a < 4; a++)
#pragma unroll
        for (int b = 0; b < 4; b++)
#pragma unroll
            for (int c = 0; c < 4; c++) acc[a][b][c] = 0.f;
    float rsum[4][2];
#pragma unroll
    for (int a = 0; a < 4; a++) rsum[a][0] = rsum[a][1] = 0.f;

    auto load_stage = [&](int s) {
        int nt = s >> 4, ec = s & 15;
        uint32_t bb = sb + (s & 1) * SC_STAGE;
#pragma unroll
        for (int h = 0; h < 2; h++) {
            int idx = h * 256 + t;
            int row = idx >> 2, q = (idx & 3) * 16;
            uint32_t dst = row * PITCHB + q;
            size_t asrc = (size_t)(q0 + row) * 1024 + ec * 64 + q;
            size_t bsrc = (size_t)(nt * 128 + row) * 1024 + ec * 64 + q;
            cp_async16(bb + dst, Qh + asrc);
            cp_async16(bb + TILE_B + dst, Kh + bsrc);
        }
    };

    if (n_stages > 0) {
        load_stage(0);
        CP_COMMIT();
    }

    __half2* AH = (__half2*)(g_ah + (size_t)p * 262144);

    for (int s = 0; s < n_stages; s++) {
        CP_WAIT(0);
        __syncthreads();
        if (s + 1 < n_stages) {
            load_stage(s + 1);
            CP_COMMIT();
        }
        uint32_t bb = sb + (s & 1) * SC_STAGE;
#pragma unroll
        for (int kk = 0; kk < 2; kk++) {
            uint32_t aBase = bb + (wm * 64 + (lane & 15)) * PITCHB + (lane >> 4) * 16 +
                             kk * 32;
            uint32_t aHi[4][4];
#pragma unroll
            for (int mt = 0; mt < 4; mt++)
                ldm_x4(aHi[mt], aBase + mt * 16 * PITCHB);
            uint32_t bBase = bb + TILE_B +
                             (wn * 32 + ((lane >> 4) & 1) * 8 + (lane & 7)) * PITCHB +
                             ((lane >> 3) & 1) * 16 + kk * 32;
#pragma unroll
            for (int pr = 0; pr < 2; pr++) {
                uint32_t bH[4];
                ldm_x4(bH, bBase + pr * 16 * PITCHB);
#pragma unroll
                for (int mt = 0; mt < 4; mt++)
#pragma unroll
                    for (int n2 = 0; n2 < 2; n2++)
                        mma_f16(acc[mt][pr * 2 + n2], aHi[mt], bH + 2 * n2);
            }
        }
        if ((s & 15) == 15) {
            int nt = s >> 4;
            int nb = nt * 128 + wn * 32;
#pragma unroll
            for (int mt = 0; mt < 4; mt++) {
                int r0 = q0 + wm * 64 + mt * 16 + (lane >> 2);
                bool fm0 = (r0 >= qlen);
                bool fm1 = ((r0 + 8) >= qlen);
#pragma unroll
                for (int ntl = 0; ntl < 4; ntl++) {
                    int col = nb + ntl * 8 + (lane & 3) * 2;
                    float* cc = acc[mt][ntl];
                    float e0 = fm0 ? 1.f : ((col < klen) ? __expf(cc[0] * SCALE_F) : 0.f);
                    float e1 = fm0 ? 1.f : ((col + 1 < klen) ? __expf(cc[1] * SCALE_F) : 0.f);
                    float e2 = fm1 ? 1.f : ((col < klen) ? __expf(cc[2] * SCALE_F) : 0.f);
                    float e3 = fm1 ? 1.f : ((col + 1 < klen) ? __expf(cc[3] * SCALE_F) : 0.f);
                    rsum[mt][0] += e0 + e1;
                    rsum[mt][1] += e2 + e3;
                    AH[((size_t)r0 * 512 + col) >> 1] = __floats2half2_rn(e0, e1);
                    AH[((size_t)(r0 + 8) * 512 + col) >> 1] = __floats2half2_rn(e2, e3);
                    cc[0] = cc[1] = cc[2] = cc[3] = 0.f;
                }
            }
        }
    }

    // fill skipped 128-col blocks: masked rows -> exp 1, live rows -> 0
    {
        __half* AHB = g_ah + (size_t)p * 262144;
        const uint32_t ONE2 = 0x3C003C00u;
        uint4 vone = make_uint4(ONE2, ONE2, ONE2, ONE2);
        uint4 vzer = make_uint4(0u, 0u, 0u, 0u);
        for (int nt = n_nt; nt < 4; nt++) {
            for (int i = t; i < 2048; i += 256) {
                int row = i >> 4, c8 = (i & 15) * 8;
                bool mr = all_masked || ((q0 + row) >= qlen);
                size_t o = (size_t)(q0 + row) * 512 + nt * 128 + c8;
                *(uint4*)(AHB + o) = mr ? vone : vzer;
            }
        }
    }

    __syncthreads();
    float* rs = (float*)(smem + RS_OFF);
    float* rinv = (float*)(smem + RINV_OFF);
#pragma unroll
    for (int mt = 0; mt < 4; mt++)
#pragma unroll
        for (int ri = 0; ri < 2; ri++) {
            float v = rsum[mt][ri];
            v += __shfl_xor_sync(0xffffffffu, v, 1);
            v += __shfl_xor_sync(0xffffffffu, v, 2);
            if ((lane & 3) == 0)
                rs[(wm * 64 + mt * 16 + ri * 8 + (lane >> 2)) * 4 + wn] = v;
        }
    __syncthreads();
    if (t < 128) {
        float s = rs[t * 4] + rs[t * 4 + 1] + rs[t * 4 + 2] + rs[t * 4 + 3];
        bool mr = all_masked || ((q0 + t) >= qlen);
        s += (float)(4 - n_nt) * 128.f * (mr ? 1.f : 0.f);
        g_rowsum[p * 512 + q0 + t] = s;
        rinv[t] = s > 0.f ? 1.f / s : 0.f;
    }
    __syncthreads();

    // normalize tail: fp32 attn from just-written exp (L2-hot) + rowsum
    {
        const __half2* AHB = (const __half2*)(g_ah + (size_t)p * 262144);
        float* AT = attn + (size_t)p * 262144;
        for (int i = t; i < 128 * 128; i += 256) {
            int row = i >> 7, c4 = (i & 127) * 4;
            float inv = rinv[row];
            size_t o = (size_t)(q0 + row) * 512 + c4;
            float2 f0 = __half22float2(AHB[o >> 1]);
            float2 f1 = __half22float2(AHB[(o >> 1) + 1]);
            float4 v;
            v.x = f0.x * inv;
            v.y = f0.y * inv;
            v.z = f1.x * inv;
            v.w = f1.y * inv;
            *(float4*)(AT + o) = v;
        }
    }
}

// ---------------- x1_att = exp @ V / rowsum (1-term fp16); emits cat fp16 ----------
__global__ __launch_bounds__(256, 2) void k_av_mma(const float* __restrict__ x1) {
    extern __shared__ char smem[];
    uint32_t sb = smem_u32(smem);
    int t = threadIdx.x, lane = t & 31, wid = t >> 5;
    int wm = wid >> 2, wn = wid & 3;
    int p = blockIdx.z, x1i = p & 31;
    int q0 = blockIdx.y * 128, e0 = blockIdx.x * 128;
    int qlen = g_qlen[x1i], klen = g_klen[p];

    bool all_masked = (q0 >= qlen) || (klen == 0);
    int n_stage = all_masked ? 0 : min(16, (klen + 31) >> 5);

    const char* Ah = (const char*)(g_ah + (size_t)p * 262144);
    const char* Vh = (const char*)(g_kh + (size_t)p * 262144);

    float acc[4][4][4];
#pragma unroll
    for (int a = 0; a < 4; a++)
#pragma unroll
        for (int b = 0; b < 4; b++)
#pragma unroll
            for (int c = 0; c < 4; c++) acc[a][b][c] = 0.f;

    auto load_stage = [&](int s) {
        uint32_t bb = sb + (s & 1) * AV_STAGE;
#pragma unroll
        for (int h = 0; h < 2; h++) {
            int idx = h * 256 + t;
            int row = idx >> 2, ch = idx & 3;
            size_t off = (size_t)(q0 + row) * 1024 + s * 64 + ch * 16;
            cp_async16(bb + row * 80 + ch * 16, Ah + off);
        }
#pragma unroll
        for (int h = 0; h < 2; h++) {
            int idx = h * 256 + t;
            int row = idx >> 4, ch = idx & 15;
            size_t off = (size_t)(s * 32 + row) * 1024 + e0 * 2 + ch * 16;
            cp_async16(bb + AV_A_SZ + row * 272 + ch * 16, Vh + off);
        }
    };

    if (n_stage > 0) {
        load_stage(0);
        CP_COMMIT();
    }

    for (int s = 0; s < n_stage; s++) {
        CP_WAIT(0);
        __syncthreads();
        if (s + 1 < n_stage) {
            load_stage(s + 1);
            CP_COMMIT();
        }
        uint32_t bb = sb + (s & 1) * AV_STAGE;
#pragma unroll
        for (int kk = 0; kk < 2; kk++) {
            uint32_t aBase = bb + (wm * 64 + (lane & 15)) * 80 + (lane >> 4) * 16 + kk * 32;
            uint32_t aHi[4][4];
#pragma unroll
            for (int mt = 0; mt < 4; mt++)
                ldm_x4(aHi[mt], aBase + mt * 16 * 80);
            uint32_t bBase = bb + AV_A_SZ + (kk * 16 + (lane & 15)) * 272 + wn * 64 +
                             ((lane >> 4) & 1) * 16;
#pragma unroll
            for (int pr = 0; pr < 2; pr++) {
                uint32_t bH[4];
                ldm_x4t(bH, bBase + pr * 32);
#pragma unroll
                for (int mt = 0; mt < 4; mt++)
#pragma unroll
                    for (int n2 = 0; n2 < 2; n2++)
                        mma_f16(acc[mt][pr * 2 + n2], aHi[mt], bH + 2 * n2);
            }
        }
    }

    // epilogue: xa = acc/rowsum (masked rows: colmean V) -> (x1-xa, x1*xa) fp16
    const float* X1 = x1 + (size_t)x1i * 262144;
    const float* VM = g_vmean + p * 512;
    __half2* Sh = (__half2*)(g_sh + (size_t)p * 262144);
    __half2* Mh = (__half2*)(g_mh + (size_t)p * 262144);
#pragma unroll
    for (int mt = 0; mt < 4; mt++) {
#pragma unroll
        for (int hh = 0; hh < 2; hh++) {
            int r = q0 + wm * 64 + mt * 16 + (lane >> 2) + hh * 8;
            bool mr = all_masked || (r >= qlen);
            float inv = 0.f;
            if (!mr) inv = 1.f / g_rowsum[p * 512 + r];
#pragma unroll
            for (int ntl = 0; ntl < 4; ntl++) {
                float* cc = acc[mt][ntl];
                int c = e0 + wn * 32 + ntl * 8 + (lane & 3) * 2;
                float2 u = *(const float2*)(X1 + (size_t)r * 512 + c);
                float xa0, xa1;
                if (mr) {
                    float2 vm = *(const float2*)(VM + c);
                    xa0 = vm.x;
                    xa1 = vm.y;
                } else {
                    xa0 = cc[hh * 2] * inv;
                    xa1 = cc[hh * 2 + 1] * inv;
                }
                size_t o = ((size_t)r * 512 + c) >> 1;
                Sh[o] = __floats2half2_rn(u.x - xa0, u.y - xa1);
                Mh[o] = __floats2half2_rn(u.x * xa0, u.y * xa1);
            }
        }
    }
}

// ---------------- fusion GEMM (1-term fp16) + bias/relu + partial pooling ----------
__global__ __launch_bounds__(256, 2) void k_fusion_mma(const float* __restrict__ fb) {
    extern __shared__ char smem[];
    uint32_t sb = smem_u32(smem);
    int t = threadIdx.x, lane = t & 31, wid = t >> 5;
    int wm = wid >> 2, wn = wid & 3;
    int p = blockIdx.z;
    int qt = blockIdx.y, q0 = qt * 128, e0 = blockIdx.x * 128;

    const char* Sh = (const char*)(g_sh + (size_t)p * 262144);
    const char* Mh = (const char*)(g_mh + (size_t)p * 262144);
    const char* Wh = (const char*)g_fwh;

    float acc[4][4][4];
#pragma unroll
    for (int a = 0; a < 4; a++)
#pragma unroll
        for (int b = 0; b < 4; b++)
#pragma unroll
            for (int c = 0; c < 4; c++) acc[a][b][c] = 0.f;

    auto load_stage = [&](int s) {
        uint32_t bb = sb + (s & 1) * AV_STAGE;
        const char* ah = (s < 16) ? Sh : Mh;
        int kc = (s & 15) * 64;
#pragma unroll
        for (int h = 0; h < 2; h++) {
            int idx = h * 256 + t;
            int row = idx >> 2, ch = idx & 3;
            size_t off = (size_t)(q0 + row) * 1024 + kc + ch * 16;
            cp_async16(bb + row * 80 + ch * 16, ah + off);
        }
#pragma unroll
        for (int h = 0; h < 2; h++) {
            int idx = h * 256 + t;
            int row = idx >> 4, ch = idx & 15;
            size_t off = (size_t)(s * 32 + row) * 1024 + e0 * 2 + ch * 16;
            cp_async16(bb + AV_A_SZ + row * 272 + ch * 16, Wh + off);
        }
    };

    load_stage(0);
    CP_COMMIT();

    for (int s = 0; s < 32; s++) {
        CP_WAIT(0);
        __syncthreads();
        if (s + 1 < 32) {
            load_stage(s + 1);
            CP_COMMIT();
        }
        uint32_t bb = sb + (s & 1) * AV_STAGE;
#pragma unroll
        for (int kk = 0; kk < 2; kk++) {
            uint32_t aBase = bb + (wm * 64 + (lane & 15)) * 80 + (lane >> 4) * 16 + kk * 32;
            uint32_t aHi[4][4];
#pragma unroll
            for (int mt = 0; mt < 4; mt++)
                ldm_x4(aHi[mt], aBase + mt * 16 * 80);
            uint32_t bBase = bb + AV_A_SZ + (kk * 16 + (lane & 15)) * 272 + wn * 64 +
                             ((lane >> 4) & 1) * 16;
#pragma unroll
            for (int pr = 0; pr < 2; pr++) {
                uint32_t bH[4];
                ldm_x4t(bH, bBase + pr * 32);
#pragma unroll
                for (int mt = 0; mt < 4; mt++)
#pragma unroll
                    for (int n2 = 0; n2 < 2; n2++)
                        mma_f16(acc[mt][pr * 2 + n2], aHi[mt], bH + 2 * n2);
            }
        }
    }

    // bias + relu + pool over this block's 128 rows
    float psum[4][2], pmax[4][2];
#pragma unroll
    for (int ntl = 0; ntl < 4; ntl++) {
        psum[ntl][0] = psum[ntl][1] = 0.f;
        pmax[ntl][0] = pmax[ntl][1] = 0.f;
    }
#pragma unroll
    for (int ntl = 0; ntl < 4; ntl++) {
        int c = e0 + wn * 32 + ntl * 8 + (lane & 3) * 2;
        float b0 = fb[c], b1 = fb[c + 1];
#pragma unroll
        for (int mt = 0; mt < 4; mt++) {
            float* cc = acc[mt][ntl];
            float v0 = fmaxf(cc[0] + b0, 0.f);
            float v1 = fmaxf(cc[1] + b1, 0.f);
            float v2 = fmaxf(cc[2] + b0, 0.f);
            float v3 = fmaxf(cc[3] + b1, 0.f);
            psum[ntl][0] += v0 + v2;
            psum[ntl][1] += v1 + v3;
            pmax[ntl][0] = fmaxf(pmax[ntl][0], fmaxf(v0, v2));
            pmax[ntl][1] = fmaxf(pmax[ntl][1], fmaxf(v1, v3));
        }
    }
    __syncthreads();
    float* redS = (float*)(smem + FU_RED_OFF);
    float* redM = redS + 256;
#pragma unroll
    for (int ntl = 0; ntl < 4; ntl++)
#pragma unroll
        for (int j = 0; j < 2; j++) {
            float s = psum[ntl][j], m = pmax[ntl][j];
            s += __shfl_xor_sync(0xffffffffu, s, 4);
            s += __shfl_xor_sync(0xffffffffu, s, 8);
            s += __shfl_xor_sync(0xffffffffu, s, 16);
            m = fmaxf(m, __shfl_xor_sync(0xffffffffu, m, 4));
            m = fmaxf(m, __shfl_xor_sync(0xffffffffu, m, 8));
            m = fmaxf(m, __shfl_xor_sync(0xffffffffu, m, 16));
            if (lane < 4) {
                int col = wn * 32 + ntl * 8 + lane * 2 + j;
                redS[wm * 128 + col] = s;
                redM[wm * 128 + col] = m;
            }
        }
    __syncthreads();
    if (t < 128) {
        float s = redS[t] + redS[128 + t];
        float m = fmaxf(redM[t], redM[128 + t]);
        int idx = (p * 4 + qt) * 512 + e0 + t;
        g_psum[idx] = s;
        g_pmax[idx] = m;
    }
}

// ---------------- pool finalize ----------------
__global__ void k_pool(void) {
    int p = blockIdx.x, e = threadIdx.x;
    float s = 0.f, m = 0.f;
#pragma unroll
    for (int qt = 0; qt < 4; qt++) {
        int idx = (p * 4 + qt) * 512 + e;
        s += g_psum[idx];
        m = fmaxf(m, g_pmax[idx]);
    }
    int base = (p >> 2) * 4096 + (p & 3) * 512 + e;
    g_pooled[base] = s * (1.0f / 512.0f);
    g_pooled[base + 2048] = m;
}

// ---------------- out = relu(pooled @ out_w + out_b) ----------------
__global__ __launch_bounds__(256) void k_out(const float* __restrict__ ow,
                                             const float* __restrict__ ob,
                                             float* __restrict__ outp) {
    __shared__ float sp[4096];
    int b = blockIdx.x, t = threadIdx.x;
    for (int i = t; i < 4096; i += 256) sp[i] = g_pooled[b * 4096 + i];
    __syncthreads();
    int col = t * 4;
    float4 acc = *(const float4*)(ob + col);
#pragma unroll 8
    for (int c = 0; c < 4096; c++) {
        float pv = sp[c];
        float4 w = *(const float4*)(ow + (size_t)c * 1024 + col);
        acc.x += pv * w.x;
        acc.y += pv * w.y;
        acc.z += pv * w.z;
        acc.w += pv * w.w;
    }
    acc.x = fmaxf(acc.x, 0.f);
    acc.y = fmaxf(acc.y, 0.f);
    acc.z = fmaxf(acc.z, 0.f);
    acc.w = fmaxf(acc.w, 0.f);
    *(float4*)(outp + b * 1024 + col) = acc;
}

extern "C" void kernel_launch(void* const* d_in, const int* in_sizes, int n_in,
                              void* d_out, int out_size) {
    const float* x1 = (const float*)d_in[0];
    const float* x2 = (const float*)d_in[1];
    const unsigned int* x1_len = (const unsigned int*)d_in[2];
    const unsigned int* x2_len = (const unsigned int*)d_in[3];
    const float* fw = (const float*)d_in[4];
    const float* fb = (const float*)d_in[5];
    const float* ow = (const float*)d_in[6];
    const float* ob = (const float*)d_in[7];

    float* outp = (float*)d_out;
    float* attn;
    if (out_size >= OUT_ELEMS + ATTN_ELEMS) {
        attn = outp + OUT_ELEMS;
    } else if (out_size >= ATTN_ELEMS) {
        attn = outp;
        void* dp = nullptr;
        cudaGetSymbolAddress(&dp, g_out_dummy);
        outp = (float*)dp;
    } else {
        void* dp = nullptr;
        cudaGetSymbolAddress(&dp, g_attn_scratch);
        attn = (float*)dp;
    }

    void *qh, *kh, *fwh;
    cudaGetSymbolAddress(&qh, g_qh);
    cudaGetSymbolAddress(&kh, g_kh);
    cudaGetSymbolAddress(&fwh, g_fwh);

    cudaFuncSetAttribute(k_scores_mma, cudaFuncAttributeMaxDynamicSharedMemorySize, SC_SMEM);
    cudaFuncSetAttribute(k_av_mma, cudaFuncAttributeMaxDynamicSharedMemorySize, AV_SMEM);
    cudaFuncSetAttribute(k_fusion_mma, cudaFuncAttributeMaxDynamicSharedMemorySize, FU_SMEM);

    k_lens<<<1, 128>>>(x1_len, x2_len);
    k_vmean<<<NPAIR, 512>>>(x2);
    k_cvt1<<<8192, 256>>>(x1, (__half*)qh, 2097152);
    k_cvt1<<<32768, 256>>>(x2, (__half*)kh, 8388608);
    k_cvt1<<<512, 256>>>(fw, (__half*)fwh, 131072);
    k_scores_mma<<<dim3(4, NPAIR), 256, SC_SMEM>>>(attn);
    k_av_mma<<<dim3(4, 4, NPAIR), 256, AV_SMEM>>>(x1);
    k_fusion_mma<<<dim3(4, 4, NPAIR), 256, FU_SMEM>>>(fb);
    k_pool<<<NPAIR, 512>>>();
    k_out<<<NB, 256>>>(ow, ob, outp);
}

// round 13
// speedup vs baseline: 6.5474x; 1.7569x over previous
#include <cuda_runtime.h>
#include <cuda_fp16.h>
#include <cstdint>

#define CL 512
#define CE 512
#define NPAIR 128
#define NB 32
#define ATTN_ELEMS (NPAIR * CL * CL)
#define OUT_ELEMS (NB * 1024)
#define SCALE_F 0.044194173824159216f

// ---------------- scratch (device globals; alloc-free rule) ----------------
__device__ float g_pooled[NB * 4096];
__device__ float g_attn_scratch[ATTN_ELEMS];
__device__ float g_out_dummy[OUT_ELEMS];
__device__ float g_rowsum[NPAIR * CL];
__device__ float g_psum[4 * NPAIR * CL];
__device__ float g_pmax[4 * NPAIR * CL];
__device__ float g_vmean[NPAIR * CE];
__device__ float g_opart[8 * NB * 1024];
__device__ int g_qlen[32];
__device__ int g_klen[128];
__device__ __half g_qh[NB * CL * CE];     // x1 fp16 (single)
__device__ __half g_kh[NPAIR * CL * CE];  // x2 fp16 (single)
__device__ __half g_ah[NPAIR * CL * CL];  // UNNORMALIZED exp (fp16 single)
__device__ __half g_sh[NPAIR * CL * CE];  // x1 - xa (fp16 single)
__device__ __half g_mh[NPAIR * CL * CE];  // x1 * xa (fp16 single)
__device__ __half g_fwh[1024 * 512];      // fusion_w fp16 (single)

// ---------------- PTX helpers ----------------
__device__ __forceinline__ uint32_t smem_u32(const void* p) {
    uint32_t a;
    asm("{ .reg .u64 t; cvta.to.shared.u64 t, %1; cvt.u32.u64 %0, t; }" : "=r"(a) : "l"(p));
    return a;
}
__device__ __forceinline__ void cp_async16(uint32_t dst, const void* src) {
    asm volatile("cp.async.ca.shared.global [%0], [%1], 16;" :: "r"(dst), "l"(src));
}
#define CP_COMMIT() asm volatile("cp.async.commit_group;" ::: "memory")
#define CP_WAIT(n)  asm volatile("cp.async.wait_group %0;" :: "n"(n) : "memory")

__device__ __forceinline__ void ldm_x4(uint32_t* r, uint32_t addr) {
    asm volatile("ldmatrix.sync.aligned.m8n8.x4.shared.b16 {%0,%1,%2,%3}, [%4];"
                 : "=r"(r[0]), "=r"(r[1]), "=r"(r[2]), "=r"(r[3]) : "r"(addr));
}
__device__ __forceinline__ void ldm_x4t(uint32_t* r, uint32_t addr) {
    asm volatile("ldmatrix.sync.aligned.m8n8.x4.trans.shared.b16 {%0,%1,%2,%3}, [%4];"
                 : "=r"(r[0]), "=r"(r[1]), "=r"(r[2]), "=r"(r[3]) : "r"(addr));
}
__device__ __forceinline__ void mma_f16(float* c, const uint32_t* a, const uint32_t* b) {
    asm volatile(
        "mma.sync.aligned.m16n8k16.row.col.f32.f16.f16.f32 "
        "{%0,%1,%2,%3}, {%4,%5,%6,%7}, {%8,%9}, {%0,%1,%2,%3};"
        : "+f"(c[0]), "+f"(c[1]), "+f"(c[2]), "+f"(c[3])
        : "r"(a[0]), "r"(a[1]), "r"(a[2]), "r"(a[3]), "r"(b[0]), "r"(b[1]));
}

// ---------------- smem geometry (3-stage rings) ----------------
#define PITCHB 80
#define TILE_B (128 * PITCHB)           // 10240
#define SC_STAGE (2 * TILE_B)           // 20480
#define SC_RS_OFF (3 * SC_STAGE)        // 61440
#define SC_RINV_OFF (SC_RS_OFF + 2048)
#define SC_SMEM (SC_RINV_OFF + 512)     // 64000
#define AV_A_SZ (128 * 80)              // 10240
#define AV_V_SZ (32 * 272)              // 8704
#define AV_STAGE (AV_A_SZ + AV_V_SZ)    // 18944
#define AV_SMEM (3 * AV_STAGE)          // 56832
#define FU_RED_OFF (3 * AV_STAGE)       // 56832
#define FU_SMEM (FU_RED_OFF + 2048)     // 58880

// ---------------- length normalization ----------------
__global__ void k_lens(const unsigned int* __restrict__ x1l,
                       const unsigned int* __restrict__ x2l) {
    __shared__ int is64;
    int t = threadIdx.x;
    if (t == 0) {
        int all0 = 1;
        for (int i = 1; i < 128; i += 2)
            if (x2l[i] != 0u) { all0 = 0; break; }
        is64 = all0;
    }
    __syncthreads();
    if (t < 32)  g_qlen[t] = (int)(is64 ? x1l[2 * t] : x1l[t]);
    if (t < 128) g_klen[t] = (int)(is64 ? x2l[2 * t] : x2l[t]);
}

// ---------------- per-pair V colmeans + fused x2 -> fp16 conversion ----------------
__global__ void k_vmean(const float* __restrict__ x2) {
    int p = blockIdx.x, e = threadIdx.x;
    const float* base = x2 + (size_t)p * 262144 + e;
    __half* kh = g_kh + (size_t)p * 262144 + e;
    float s0 = 0.f, s1 = 0.f, s2 = 0.f, s3 = 0.f;
    for (int k = 0; k < 512; k += 4) {
        float v0 = base[(k + 0) * 512];
        float v1 = base[(k + 1) * 512];
        float v2 = base[(k + 2) * 512];
        float v3 = base[(k + 3) * 512];
        s0 += v0; s1 += v1; s2 += v2; s3 += v3;
        kh[(k + 0) * 512] = __float2half(v0);
        kh[(k + 1) * 512] = __float2half(v1);
        kh[(k + 2) * 512] = __float2half(v2);
        kh[(k + 3) * 512] = __float2half(v3);
    }
    g_vmean[p * 512 + e] = (s0 + s1 + s2 + s3) * (1.f / 512.f);
}

// ---------------- fp32 -> fp16 (single) ----------------
__global__ void k_cvt1(const float* __restrict__ src, __half* __restrict__ hi, int n4) {
    int i = blockIdx.x * blockDim.x + threadIdx.x;
    if (i >= n4) return;
    float4 v = ((const float4*)src)[i];
    ((__half2*)hi)[2 * i] = __floats2half2_rn(v.x, v.y);
    ((__half2*)hi)[2 * i + 1] = __floats2half2_rn(v.z, v.w);
}

// ---------------- scores: Q@K^T (1-term fp16), masked exp -> fp16 + fp32 attn -----
__global__ __launch_bounds__(256, 2) void k_scores_mma(float* __restrict__ attn) {
    extern __shared__ char smem[];
    uint32_t sb = smem_u32(smem);
    int t = threadIdx.x, lane = t & 31, wid = t >> 5;
    int wm = wid >> 2, wn = wid & 3;
    int p = blockIdx.y, x1i = p & 31;
    int qt = blockIdx.x, q0 = qt * 128;
    int qlen = g_qlen[x1i], klen = g_klen[p];

    bool all_masked = (q0 >= qlen) || (klen == 0);
    int n_nt = all_masked ? 0 : min(4, (klen + 127) >> 7);
    int n_stages = n_nt * 16;

    const char* Qh = (const char*)(g_qh + (size_t)x1i * 262144);
    const char* Kh = (const char*)(g_kh + (size_t)p * 262144);

    float acc[4][4][4];
#pragma unroll
    for (int a = 0; a < 4; a++)
#pragma unroll
        for (int b = 0; b < 4; b++)
#pragma unroll
            for (int c = 0; c < 4; c++) acc[a][b][c] = 0.f;
    float rsum[4][2];
#pragma unroll
    for (int a = 0; a < 4; a++) rsum[a][0] = rsum[a][1] = 0.f;

    auto load_stage = [&](int s) {
        int nt = s >> 4, ec = s & 15;
        uint32_t bb = sb + (s % 3) * SC_STAGE;
#pragma unroll
        for (int h = 0; h < 2; h++) {
            int idx = h * 256 + t;
            int row = idx >> 2, q = (idx & 3) * 16;
            uint32_t dst = row * PITCHB + q;
            size_t asrc = (size_t)(q0 + row) * 1024 + ec * 64 + q;
            size_t bsrc = (size_t)(nt * 128 + row) * 1024 + ec * 64 + q;
            cp_async16(bb + dst, Qh + asrc);
            cp_async16(bb + TILE_B + dst, Kh + bsrc);
        }
    };

    if (n_stages > 0) {
        load_stage(0);
        CP_COMMIT();
        if (n_stages > 1) load_stage(1);
        CP_COMMIT();
    }

    __half2* AH = (__half2*)(g_ah + (size_t)p * 262144);

    for (int s = 0; s < n_stages; s++) {
        CP_WAIT(1);
        __syncthreads();
        if (s + 2 < n_stages) load_stage(s + 2);
        CP_COMMIT();
        uint32_t bb = sb + (s % 3) * SC_STAGE;
#pragma unroll
        for (int kk = 0; kk < 2; kk++) {
            uint32_t aBase = bb + (wm * 64 + (lane & 15)) * PITCHB + (lane >> 4) * 16 +
                             kk * 32;
            uint32_t aHi[4][4];
#pragma unroll
            for (int mt = 0; mt < 4; mt++)
                ldm_x4(aHi[mt], aBase + mt * 16 * PITCHB);
            uint32_t bBase = bb + TILE_B +
                             (wn * 32 + ((lane >> 4) & 1) * 8 + (lane & 7)) * PITCHB +
                             ((lane >> 3) & 1) * 16 + kk * 32;
#pragma unroll
            for (int pr = 0; pr < 2; pr++) {
                uint32_t bH[4];
                ldm_x4(bH, bBase + pr * 16 * PITCHB);
#pragma unroll
                for (int mt = 0; mt < 4; mt++)
#pragma unroll
                    for (int n2 = 0; n2 < 2; n2++)
                        mma_f16(acc[mt][pr * 2 + n2], aHi[mt], bH + 2 * n2);
            }
        }
        if ((s & 15) == 15) {
            int nt = s >> 4;
            int nb = nt * 128 + wn * 32;
#pragma unroll
            for (int mt = 0; mt < 4; mt++) {
                int r0 = q0 + wm * 64 + mt * 16 + (lane >> 2);
                bool fm0 = (r0 >= qlen);
                bool fm1 = ((r0 + 8) >= qlen);
#pragma unroll
                for (int ntl = 0; ntl < 4; ntl++) {
                    int col = nb + ntl * 8 + (lane & 3) * 2;
                    float* cc = acc[mt][ntl];
                    float e0 = fm0 ? 1.f : ((col < klen) ? __expf(cc[0] * SCALE_F) : 0.f);
                    float e1 = fm0 ? 1.f : ((col + 1 < klen) ? __expf(cc[1] * SCALE_F) : 0.f);
                    float e2 = fm1 ? 1.f : ((col < klen) ? __expf(cc[2] * SCALE_F) : 0.f);
                    float e3 = fm1 ? 1.f : ((col + 1 < klen) ? __expf(cc[3] * SCALE_F) : 0.f);
                    rsum[mt][0] += e0 + e1;
                    rsum[mt][1] += e2 + e3;
                    AH[((size_t)r0 * 512 + col) >> 1] = __floats2half2_rn(e0, e1);
                    AH[((size_t)(r0 + 8) * 512 + col) >> 1] = __floats2half2_rn(e2, e3);
                    cc[0] = cc[1] = cc[2] = cc[3] = 0.f;
                }
            }
        }
    }

    // fill skipped 128-col blocks: masked rows -> exp 1, live rows -> 0
    {
        __half* AHB = g_ah + (size_t)p * 262144;
        const uint32_t ONE2 = 0x3C003C00u;
        uint4 vone = make_uint4(ONE2, ONE2, ONE2, ONE2);
        uint4 vzer = make_uint4(0u, 0u, 0u, 0u);
        for (int nt = n_nt; nt < 4; nt++) {
            for (int i = t; i < 2048; i += 256) {
                int row = i >> 4, c8 = (i & 15) * 8;
                bool mr = all_masked || ((q0 + row) >= qlen);
                size_t o = (size_t)(q0 + row) * 512 + nt * 128 + c8;
                *(uint4*)(AHB + o) = mr ? vone : vzer;
            }
        }
    }

    __syncthreads();
    float* rs = (float*)(smem + SC_RS_OFF);
    float* rinv = (float*)(smem + SC_RINV_OFF);
#pragma unroll
    for (int mt = 0; mt < 4; mt++)
#pragma unroll
        for (int ri = 0; ri < 2; ri++) {
            float v = rsum[mt][ri];
            v += __shfl_xor_sync(0xffffffffu, v, 1);
            v += __shfl_xor_sync(0xffffffffu, v, 2);
            if ((lane & 3) == 0)
                rs[(wm * 64 + mt * 16 + ri * 8 + (lane >> 2)) * 4 + wn] = v;
        }
    __syncthreads();
    if (t < 128) {
        float s = rs[t * 4] + rs[t * 4 + 1] + rs[t * 4 + 2] + rs[t * 4 + 3];
        bool mr = all_masked || ((q0 + t) >= qlen);
        s += (float)(4 - n_nt) * 128.f * (mr ? 1.f : 0.f);
        g_rowsum[p * 512 + q0 + t] = s;
        rinv[t] = s > 0.f ? 1.f / s : 0.f;
    }
    __syncthreads();

    // normalize tail: fp32 attn from just-written exp (L2-hot) + rowsum
    {
        const __half2* AHB = (const __half2*)(g_ah + (size_t)p * 262144);
        float* AT = attn + (size_t)p * 262144;
        for (int i = t; i < 128 * 128; i += 256) {
            int row = i >> 7, c4 = (i & 127) * 4;
            float inv = rinv[row];
            size_t o = (size_t)(q0 + row) * 512 + c4;
            float2 f0 = __half22float2(AHB[o >> 1]);
            float2 f1 = __half22float2(AHB[(o >> 1) + 1]);
            float4 v;
            v.x = f0.x * inv;
            v.y = f0.y * inv;
            v.z = f1.x * inv;
            v.w = f1.y * inv;
            *(float4*)(AT + o) = v;
        }
    }
}

// ---------------- x1_att = exp @ V / rowsum (1-term fp16); emits cat fp16 ----------
__global__ __launch_bounds__(256, 2) void k_av_mma(const float* __restrict__ x1) {
    extern __shared__ char smem[];
    uint32_t sb = smem_u32(smem);
    int t = threadIdx.x, lane = t & 31, wid = t >> 5;
    int wm = wid >> 2, wn = wid & 3;
    int p = blockIdx.z, x1i = p & 31;
    int q0 = blockIdx.y * 128, e0 = blockIdx.x * 128;
    int qlen = g_qlen[x1i], klen = g_klen[p];

    bool all_masked = (q0 >= qlen) || (klen == 0);
    int n_stage = all_masked ? 0 : min(16, (klen + 31) >> 5);

    const char* Ah = (const char*)(g_ah + (size_t)p * 262144);
    const char* Vh = (const char*)(g_kh + (size_t)p * 262144);

    float acc[4][4][4];
#pragma unroll
    for (int a = 0; a < 4; a++)
#pragma unroll
        for (int b = 0; b < 4; b++)
#pragma unroll
            for (int c = 0; c < 4; c++) acc[a][b][c] = 0.f;

    auto load_stage = [&](int s) {
        uint32_t bb = sb + (s % 3) * AV_STAGE;
#pragma unroll
        for (int h = 0; h < 2; h++) {
            int idx = h * 256 + t;
            int row = idx >> 2, ch = idx & 3;
            size_t off = (size_t)(q0 + row) * 1024 + s * 64 + ch * 16;
            cp_async16(bb + row * 80 + ch * 16, Ah + off);
        }
#pragma unroll
        for (int h = 0; h < 2; h++) {
            int idx = h * 256 + t;
            int row = idx >> 4, ch = idx & 15;
            size_t off = (size_t)(s * 32 + row) * 1024 + e0 * 2 + ch * 16;
            cp_async16(bb + AV_A_SZ + row * 272 + ch * 16, Vh + off);
        }
    };

    if (n_stage > 0) {
        load_stage(0);
        CP_COMMIT();
        if (n_stage > 1) load_stage(1);
        CP_COMMIT();
    }

    for (int s = 0; s < n_stage; s++) {
        CP_WAIT(1);
        __syncthreads();
        if (s + 2 < n_stage) load_stage(s + 2);
        CP_COMMIT();
        uint32_t bb = sb + (s % 3) * AV_STAGE;
#pragma unroll
        for (int kk = 0; kk < 2; kk++) {
            uint32_t aBase = bb + (wm * 64 + (lane & 15)) * 80 + (lane >> 4) * 16 + kk * 32;
            uint32_t aHi[4][4];
#pragma unroll
            for (int mt = 0; mt < 4; mt++)
                ldm_x4(aHi[mt], aBase + mt * 16 * 80);
            uint32_t bBase = bb + AV_A_SZ + (kk * 16 + (lane & 15)) * 272 + wn * 64 +
                             ((lane >> 4) & 1) * 16;
#pragma unroll
            for (int pr = 0; pr < 2; pr++) {
                uint32_t bH[4];
                ldm_x4t(bH, bBase + pr * 32);
#pragma unroll
                for (int mt = 0; mt < 4; mt++)
#pragma unroll
                    for (int n2 = 0; n2 < 2; n2++)
                        mma_f16(acc[mt][pr * 2 + n2], aHi[mt], bH + 2 * n2);
            }
        }
    }

    // epilogue: xa = acc/rowsum (masked rows: colmean V) -> (x1-xa, x1*xa) fp16
    const float* X1 = x1 + (size_t)x1i * 262144;
    const float* VM = g_vmean + p * 512;
    __half2* Sh = (__half2*)(g_sh + (size_t)p * 262144);
    __half2* Mh = (__half2*)(g_mh + (size_t)p * 262144);
#pragma unroll
    for (int mt = 0; mt < 4; mt++) {
#pragma unroll
        for (int hh = 0; hh < 2; hh++) {
            int r = q0 + wm * 64 + mt * 16 + (lane >> 2) + hh * 8;
            bool mr = all_masked || (r >= qlen);
            float inv = 0.f;
            if (!mr) inv = 1.f / g_rowsum[p * 512 + r];
#pragma unroll
            for (int ntl = 0; ntl < 4; ntl++) {
                float* cc = acc[mt][ntl];
                int c = e0 + wn * 32 + ntl * 8 + (lane & 3) * 2;
                float2 u = *(const float2*)(X1 + (size_t)r * 512 + c);
                float xa0, xa1;
                if (mr) {
                    float2 vm = *(const float2*)(VM + c);
                    xa0 = vm.x;
                    xa1 = vm.y;
                } else {
                    xa0 = cc[hh * 2] * inv;
                    xa1 = cc[hh * 2 + 1] * inv;
                }
                size_t o = ((size_t)r * 512 + c) >> 1;
                Sh[o] = __floats2half2_rn(u.x - xa0, u.y - xa1);
                Mh[o] = __floats2half2_rn(u.x * xa0, u.y * xa1);
            }
        }
    }
}

// ---------------- fusion GEMM (1-term fp16) + bias/relu + partial pooling ----------
__global__ __launch_bounds__(256, 2) void k_fusion_mma(const float* __restrict__ fb) {
    extern __shared__ char smem[];
    uint32_t sb = smem_u32(smem);
    int t = threadIdx.x, lane = t & 31, wid = t >> 5;
    int wm = wid >> 2, wn = wid & 3;
    int p = blockIdx.z;
    int qt = blockIdx.y, q0 = qt * 128, e0 = blockIdx.x * 128;

    const char* Sh = (const char*)(g_sh + (size_t)p * 262144);
    const char* Mh = (const char*)(g_mh + (size_t)p * 262144);
    const char* Wh = (const char*)g_fwh;

    float acc[4][4][4];
#pragma unroll
    for (int a = 0; a < 4; a++)
#pragma unroll
        for (int b = 0; b < 4; b++)
#pragma unroll
            for (int c = 0; c < 4; c++) acc[a][b][c] = 0.f;

    auto load_stage = [&](int s) {
        uint32_t bb = sb + (s % 3) * AV_STAGE;
        const char* ah = (s < 16) ? Sh : Mh;
        int kc = (s & 15) * 64;
#pragma unroll
        for (int h = 0; h < 2; h++) {
            int idx = h * 256 + t;
            int row = idx >> 2, ch = idx & 3;
            size_t off = (size_t)(q0 + row) * 1024 + kc + ch * 16;
            cp_async16(bb + row * 80 + ch * 16, ah + off);
        }
#pragma unroll
        for (int h = 0; h < 2; h++) {
            int idx = h * 256 + t;
            int row = idx >> 4, ch = idx & 15;
            size_t off = (size_t)(s * 32 + row) * 1024 + e0 * 2 + ch * 16;
            cp_async16(bb + AV_A_SZ + row * 272 + ch * 16, Wh + off);
        }
    };

    load_stage(0);
    CP_COMMIT();
    load_stage(1);
    CP_COMMIT();

    for (int s = 0; s < 32; s++) {
        CP_WAIT(1);
        __syncthreads();
        if (s + 2 < 32) load_stage(s + 2);
        CP_COMMIT();
        uint32_t bb = sb + (s % 3) * AV_STAGE;
#pragma unroll
        for (int kk = 0; kk < 2; kk++) {
            uint32_t aBase = bb + (wm * 64 + (lane & 15)) * 80 + (lane >> 4) * 16 + kk * 32;
            uint32_t aHi[4][4];
#pragma unroll
            for (int mt = 0; mt < 4; mt++)
                ldm_x4(aHi[mt], aBase + mt * 16 * 80);
            uint32_t bBase = bb + AV_A_SZ + (kk * 16 + (lane & 15)) * 272 + wn * 64 +
                             ((lane >> 4) & 1) * 16;
#pragma unroll
            for (int pr = 0; pr < 2; pr++) {
                uint32_t bH[4];
                ldm_x4t(bH, bBase + pr * 32);
#pragma unroll
                for (int mt = 0; mt < 4; mt++)
#pragma unroll
                    for (int n2 = 0; n2 < 2; n2++)
                        mma_f16(acc[mt][pr * 2 + n2], aHi[mt], bH + 2 * n2);
            }
        }
    }

    // bias + relu + pool over this block's 128 rows
    float psum[4][2], pmax[4][2];
#pragma unroll
    for (int ntl = 0; ntl < 4; ntl++) {
        psum[ntl][0] = psum[ntl][1] = 0.f;
        pmax[ntl][0] = pmax[ntl][1] = 0.f;
    }
#pragma unroll
    for (int ntl = 0; ntl < 4; ntl++) {
        int c = e0 + wn * 32 + ntl * 8 + (lane & 3) * 2;
        float b0 = fb[c], b1 = fb[c + 1];
#pragma unroll
        for (int mt = 0; mt < 4; mt++) {
            float* cc = acc[mt][ntl];
            float v0 = fmaxf(cc[0] + b0, 0.f);
            float v1 = fmaxf(cc[1] + b1, 0.f);
            float v2 = fmaxf(cc[2] + b0, 0.f);
            float v3 = fmaxf(cc[3] + b1, 0.f);
            psum[ntl][0] += v0 + v2;
            psum[ntl][1] += v1 + v3;
            pmax[ntl][0] = fmaxf(pmax[ntl][0], fmaxf(v0, v2));
            pmax[ntl][1] = fmaxf(pmax[ntl][1], fmaxf(v1, v3));
        }
    }
    __syncthreads();
    float* redS = (float*)(smem + FU_RED_OFF);
    float* redM = redS + 256;
#pragma unroll
    for (int ntl = 0; ntl < 4; ntl++)
#pragma unroll
        for (int j = 0; j < 2; j++) {
            float s = psum[ntl][j], m = pmax[ntl][j];
            s += __shfl_xor_sync(0xffffffffu, s, 4);
            s += __shfl_xor_sync(0xffffffffu, s, 8);
            s += __shfl_xor_sync(0xffffffffu, s, 16);
            m = fmaxf(m, __shfl_xor_sync(0xffffffffu, m, 4));
            m = fmaxf(m, __shfl_xor_sync(0xffffffffu, m, 8));
            m = fmaxf(m, __shfl_xor_sync(0xffffffffu, m, 16));
            if (lane < 4) {
                int col = wn * 32 + ntl * 8 + lane * 2 + j;
                redS[wm * 128 + col] = s;
                redM[wm * 128 + col] = m;
            }
        }
    __syncthreads();
    if (t < 128) {
        float s = redS[t] + redS[128 + t];
        float m = fmaxf(redM[t], redM[128 + t]);
        int idx = (p * 4 + qt) * 512 + e0 + t;
        g_psum[idx] = s;
        g_pmax[idx] = m;
    }
}

// ---------------- pool finalize ----------------
__global__ void k_pool(void) {
    int p = blockIdx.x, e = threadIdx.x;
    float s = 0.f, m = 0.f;
#pragma unroll
    for (int qt = 0; qt < 4; qt++) {
        int idx = (p * 4 + qt) * 512 + e;
        s += g_psum[idx];
        m = fmaxf(m, g_pmax[idx]);
    }
    int base = (p >> 2) * 4096 + (p & 3) * 512 + e;
    g_pooled[base] = s * (1.0f / 512.0f);
    g_pooled[base + 2048] = m;
}

// ---------------- out GEMM: k-split partials ----------------
__global__ __launch_bounds__(256) void k_out_part(const float* __restrict__ ow) {
    __shared__ float sp[512];
    int b = blockIdx.x, ks = blockIdx.y, t = threadIdx.x;
    for (int i = t; i < 512; i += 256) sp[i] = g_pooled[b * 4096 + ks * 512 + i];
    __syncthreads();
    int col = t * 4;
    float4 acc = make_float4(0.f, 0.f, 0.f, 0.f);
#pragma unroll 8
    for (int c = 0; c < 512; c++) {
        float pv = sp[c];
        float4 w = *(const float4*)(ow + (size_t)(ks * 512 + c) * 1024 + col);
        acc.x += pv * w.x;
        acc.y += pv * w.y;
        acc.z += pv * w.z;
        acc.w += pv * w.w;
    }
    *(float4*)(g_opart + ((size_t)ks * 32 + b) * 1024 + col) = acc;
}

// ---------------- out finalize: fixed-order sum + bias + relu ----------------
__global__ __launch_bounds__(256) void k_out_fin(const float* __restrict__ ob,
                                                 float* __restrict__ outp) {
    int b = blockIdx.x, col = threadIdx.x * 4;
    float4 acc = *(const float4*)(ob + col);
#pragma unroll
    for (int ks = 0; ks < 8; ks++) {
        float4 v = *(const float4*)(g_opart + ((size_t)ks * 32 + b) * 1024 + col);
        acc.x += v.x;
        acc.y += v.y;
        acc.z += v.z;
        acc.w += v.w;
    }
    acc.x = fmaxf(acc.x, 0.f);
    acc.y = fmaxf(acc.y, 0.f);
    acc.z = fmaxf(acc.z, 0.f);
    acc.w = fmaxf(acc.w, 0.f);
    *(float4*)(outp + b * 1024 + col) = acc;
}

extern "C" void kernel_launch(void* const* d_in, const int* in_sizes, int n_in,
                              void* d_out, int out_size) {
    const float* x1 = (const float*)d_in[0];
    const float* x2 = (const float*)d_in[1];
    const unsigned int* x1_len = (const unsigned int*)d_in[2];
    const unsigned int* x2_len = (const unsigned int*)d_in[3];
    const float* fw = (const float*)d_in[4];
    const float* fb = (const float*)d_in[5];
    const float* ow = (const float*)d_in[6];
    const float* ob = (const float*)d_in[7];

    float* outp = (float*)d_out;
    float* attn;
    if (out_size >= OUT_ELEMS + ATTN_ELEMS) {
        attn = outp + OUT_ELEMS;
    } else if (out_size >= ATTN_ELEMS) {
        attn = outp;
        void* dp = nullptr;
        cudaGetSymbolAddress(&dp, g_out_dummy);
        outp = (float*)dp;
    } else {
        void* dp = nullptr;
        cudaGetSymbolAddress(&dp, g_attn_scratch);
        attn = (float*)dp;
    }

    void *qh, *fwh;
    cudaGetSymbolAddress(&qh, g_qh);
    cudaGetSymbolAddress(&fwh, g_fwh);

    cudaFuncSetAttribute(k_scores_mma, cudaFuncAttributeMaxDynamicSharedMemorySize, SC_SMEM);
    cudaFuncSetAttribute(k_av_mma, cudaFuncAttributeMaxDynamicSharedMemorySize, AV_SMEM);
    cudaFuncSetAttribute(k_fusion_mma, cudaFuncAttributeMaxDynamicSharedMemorySize, FU_SMEM);

    k_lens<<<1, 128>>>(x1_len, x2_len);
    k_vmean<<<NPAIR, 512>>>(x2);
    k_cvt1<<<8192, 256>>>(x1, (__half*)qh, 2097152);
    k_cvt1<<<512, 256>>>(fw, (__half*)fwh, 131072);
    k_scores_mma<<<dim3(4, NPAIR), 256, SC_SMEM>>>(attn);
    k_av_mma<<<dim3(4, 4, NPAIR), 256, AV_SMEM>>>(x1);
    k_fusion_mma<<<dim3(4, 4, NPAIR), 256, FU_SMEM>>>(fb);
    k_pool<<<NPAIR, 512>>>();
    k_out_part<<<dim3(NB, 8), 256>>>(ow);
    k_out_fin<<<NB, 256>>>(ob, outp);
}